// round 10
// baseline (speedup 1.0000x reference)
#include <cuda_runtime.h>
#include <cuda_bf16.h>
#include <math.h>
#include <stdint.h>

#define T 2048
#define D 1024
#define H 16
#define DH 64
#define DFF 4096
#define D3 3072

// ======================= scratch (device globals) =======================
__device__ float g_wheads[(size_t)T * D3];
__device__ float g_scores[(size_t)H * T * T];
__device__ float g_x[(size_t)T * D];

__device__ __nv_bfloat16 g_qin_h[(size_t)T * D],  g_qin_l[(size_t)T * D];
__device__ __nv_bfloat16 g_y_h[(size_t)T * D],    g_y_l[(size_t)T * D];
__device__ __nv_bfloat16 g_pos_h[(size_t)T * D],  g_pos_l[(size_t)T * D];
__device__ __nv_bfloat16 g_av_h[(size_t)T * D],   g_av_l[(size_t)T * D];
__device__ __nv_bfloat16 g_ff_h[(size_t)T * DFF], g_ff_l[(size_t)T * DFF];

__device__ __nv_bfloat16 g_qkvwT_h[(size_t)D3 * D],  g_qkvwT_l[(size_t)D3 * D];
__device__ __nv_bfloat16 g_rwT_h[(size_t)D * D],     g_rwT_l[(size_t)D * D];
__device__ __nv_bfloat16 g_owT_h[(size_t)D * D],     g_owT_l[(size_t)D * D];
__device__ __nv_bfloat16 g_w1T_h[(size_t)DFF * D],   g_w1T_l[(size_t)DFF * D];
__device__ __nv_bfloat16 g_w2T_h[(size_t)D * DFF],   g_w2T_l[(size_t)D * DFF];

__device__ __nv_bfloat16 g_ph[(size_t)H * T * T];   // probs hi
__device__ __nv_bfloat16 g_pl[(size_t)H * T * T];   // probs lo
__device__ __nv_bfloat16 g_vt_h[(size_t)D * T];     // V^T hi: [h*64+d][t]
__device__ __nv_bfloat16 g_vt_l[(size_t)D * T];

// pre-split attention inputs
__device__ __nv_bfloat16 g_qw_h[(size_t)T * D], g_qw_l[(size_t)T * D];   // Q + r_w_bias
__device__ __nv_bfloat16 g_qr_h[(size_t)T * D], g_qr_l[(size_t)T * D];   // Q + r_r_bias
__device__ __nv_bfloat16 g_k_h[(size_t)T * D],  g_k_l[(size_t)T * D];    // K
__device__ __nv_bfloat16 g_rk_h[(size_t)T * D], g_rk_l[(size_t)T * D];   // r_k

// ======================= small utils =======================
__device__ __forceinline__ float warpSum(float v) {
#pragma unroll
    for (int o = 16; o > 0; o >>= 1) v += __shfl_xor_sync(0xffffffffu, v, o);
    return v;
}
__device__ __forceinline__ float warpMax(float v) {
#pragma unroll
    for (int o = 16; o > 0; o >>= 1) v = fmaxf(v, __shfl_xor_sync(0xffffffffu, v, o));
    return v;
}
__device__ __forceinline__ uint32_t bf2pack(float a, float b) {
    __nv_bfloat162 t = __floats2bfloat162_rn(a, b);
    return *reinterpret_cast<uint32_t*>(&t);
}
__device__ __forceinline__ void split2p(float v0, float v1, __nv_bfloat16* h, __nv_bfloat16* l, size_t idx) {
    float h0 = __bfloat162float(__float2bfloat16(v0));
    float h1 = __bfloat162float(__float2bfloat16(v1));
    *(uint32_t*)&h[idx] = bf2pack(v0, v1);
    *(uint32_t*)&l[idx] = bf2pack(v0 - h0, v1 - h1);
}
__device__ __forceinline__ void split4(float4 v, __nv_bfloat16* h, __nv_bfloat16* l, size_t idx) {
    float h0 = __bfloat162float(__float2bfloat16(v.x));
    float h1 = __bfloat162float(__float2bfloat16(v.y));
    float h2 = __bfloat162float(__float2bfloat16(v.z));
    float h3 = __bfloat162float(__float2bfloat16(v.w));
    uint2 hu, lu;
    hu.x = bf2pack(v.x, v.y);     hu.y = bf2pack(v.z, v.w);
    lu.x = bf2pack(v.x - h0, v.y - h1);
    lu.y = bf2pack(v.z - h2, v.w - h3);
    *(uint2*)&h[idx] = hu;
    *(uint2*)&l[idx] = lu;
}
__device__ __forceinline__ uint32_t smem_u32(const void* p) {
    uint32_t a;
    asm("{ .reg .u64 tmp; cvta.to.shared.u64 tmp, %1; cvt.u32.u64 %0, tmp; }" : "=r"(a) : "l"(p));
    return a;
}

// ======================= HMMA helpers =======================
__device__ __forceinline__ void ldsm_x4(uint32_t* r, uint32_t addr) {
    asm volatile("ldmatrix.sync.aligned.m8n8.x4.shared.b16 {%0,%1,%2,%3}, [%4];"
                 : "=r"(r[0]), "=r"(r[1]), "=r"(r[2]), "=r"(r[3]) : "r"(addr));
}
__device__ __forceinline__ void mma16816(float* c, const uint32_t* a, uint32_t b0, uint32_t b1) {
    asm volatile(
        "mma.sync.aligned.m16n8k16.row.col.f32.bf16.bf16.f32 "
        "{%0,%1,%2,%3}, {%4,%5,%6,%7}, {%8,%9}, {%0,%1,%2,%3};"
        : "+f"(c[0]), "+f"(c[1]), "+f"(c[2]), "+f"(c[3])
        : "r"(a[0]), "r"(a[1]), "r"(a[2]), "r"(a[3]), "r"(b0), "r"(b1));
}
#define MMSTRIDE 72
__device__ __forceinline__ uint32_t faddr(uint32_t base, int row0, int kk, int lane) {
    return base + (uint32_t)(((row0 + (lane & 15)) * MMSTRIDE + kk * 16 + ((lane >> 4) << 3)) * 2);
}
__device__ __forceinline__ void cpa16(uint32_t dst, const void* src) {
    asm volatile("cp.async.cg.shared.global [%0], [%1], 16;"
                 :: "r"(dst), "l"(__cvta_generic_to_global(src)) : "memory");
}
__device__ __forceinline__ void cpa16z(uint32_t dst, const void* src, int bytes) {
    asm volatile("cp.async.cg.shared.global [%0], [%1], 16, %2;"
                 :: "r"(dst), "l"(__cvta_generic_to_global(src)), "r"(bytes) : "memory");
}

// ======================= convert kernels =======================
__global__ void splitcvt_kernel(const float* __restrict__ x, __nv_bfloat16* __restrict__ h,
                                __nv_bfloat16* __restrict__ l, int n) {
    int i = (blockIdx.x * 256 + threadIdx.x) * 4;
    if (i >= n) return;
    split4(*(const float4*)(x + i), h, l, i);
}

// transpose + split: W [K,N] f32 -> WT hi/lo [N,K] bf16 (paired uint32 stores)
__global__ void wconvT_kernel(const float* __restrict__ W, __nv_bfloat16* __restrict__ th,
                              __nv_bfloat16* __restrict__ tl, int K, int N) {
    __shared__ float sm[32][33];
    const int k0 = blockIdx.y * 32, n0 = blockIdx.x * 32;
    const int tx = threadIdx.x, ty = threadIdx.y;   // 32 x 8
    const int t = ty * 32 + tx;
#pragma unroll
    for (int i = 0; i < 4; i++)
        sm[ty + 8 * i][tx] = W[(size_t)(k0 + ty + 8 * i) * N + n0 + tx];
    __syncthreads();
#pragma unroll
    for (int e = 0; e < 2; e++) {
        int pid = e * 256 + t;          // 512 pairs
        int n = pid >> 4, kp = pid & 15;
        float v0 = sm[2 * kp][n], v1 = sm[2 * kp + 1][n];
        split2p(v0, v1, th, tl, (size_t)(n0 + n) * K + k0 + 2 * kp);
    }
}

// V^T conversion: wheads V section [t][2D + c] f32 -> VT hi/lo [c][t]
__global__ void vconvT_kernel(const float* __restrict__ wh, __nv_bfloat16* __restrict__ th,
                              __nv_bfloat16* __restrict__ tl) {
    __shared__ float sm[32][33];
    const int t0 = blockIdx.x * 32, c0 = blockIdx.y * 32;
    const int tx = threadIdx.x, ty = threadIdx.y;   // 32 x 8
    const int t = ty * 32 + tx;
#pragma unroll
    for (int i = 0; i < 4; i++)
        sm[ty + 8 * i][tx] = wh[(size_t)(t0 + ty + 8 * i) * D3 + 2 * D + c0 + tx];
    __syncthreads();
#pragma unroll
    for (int e = 0; e < 2; e++) {
        int pid = e * 256 + t;
        int c = pid >> 4, tp = pid & 15;
        float v0 = sm[2 * tp][c], v1 = sm[2 * tp + 1][c];
        split2p(v0, v1, th, tl, (size_t)(c0 + c) * T + t0 + 2 * tp);
    }
}

// ======================= layernorm (writes bf16 hi/lo, vectorized) =======
__global__ void ln_kernel(const float* __restrict__ x, const float* __restrict__ g,
                          const float* __restrict__ b, __nv_bfloat16* __restrict__ oh,
                          __nv_bfloat16* __restrict__ ol) {
    const int row = blockIdx.x;
    const int t = threadIdx.x;
    const float* xr = x + (size_t)row * D;
    float4 v = *(const float4*)&xr[t * 4];
    float s = v.x + v.y + v.z + v.w;
    __shared__ float red1[8], red2[8];
    s = warpSum(s);
    if ((t & 31) == 0) red1[t >> 5] = s;
    __syncthreads();
    float tot = red1[0] + red1[1] + red1[2] + red1[3] + red1[4] + red1[5] + red1[6] + red1[7];
    const float mean = tot * (1.0f / D);
    float dx = v.x - mean, dy = v.y - mean, dz = v.z - mean, dw = v.w - mean;
    float s2 = dx * dx + dy * dy + dz * dz + dw * dw;
    s2 = warpSum(s2);
    if ((t & 31) == 0) red2[t >> 5] = s2;
    __syncthreads();
    float var = (red2[0] + red2[1] + red2[2] + red2[3] + red2[4] + red2[5] + red2[6] + red2[7]) * (1.0f / D);
    const float inv = rsqrtf(var + 1e-5f);
    float4 gg = *(const float4*)&g[t * 4];
    float4 bb = *(const float4*)&b[t * 4];
    float4 o;
    o.x = dx * inv * gg.x + bb.x;
    o.y = dy * inv * gg.y + bb.y;
    o.z = dz * inv * gg.z + bb.z;
    o.w = dw * inv * gg.w + bb.w;
    split4(o, oh, ol, (size_t)row * D + t * 4);
}

// ======================= HMMA GEMM (dense projections) =======================
// EPI bits: 1=bias, 2=relu, 4=residual, 8=split-output, 16=QKV attn-prep epilogue
#define BM 128
#define BN 128
#define BK 64
#define ARR_BYTES (128 * MMSTRIDE * 2)    // 18432
#define STAGE_BYTES (4 * ARR_BYTES)       // 73728
#define MM_SMEM (2 * STAGE_BYTES)         // 147456

__device__ __forceinline__ void mm_load_chunk(
    const __nv_bfloat16* __restrict__ Ah, const __nv_bfloat16* __restrict__ Al,
    const __nv_bfloat16* __restrict__ Bh, const __nv_bfloat16* __restrict__ Bl,
    int m0, int n0, int K, int t, uint32_t stage_base, int tid) {
    const size_t k0 = (size_t)t * BK;
#pragma unroll
    for (int e = 0; e < 16; e++) {
        int idx = e * 256 + tid;
        int arr = idx >> 10;
        int row = (idx >> 3) & 127;
        int ck  = idx & 7;
        const __nv_bfloat16* src;
        if (arr == 0)      src = Ah + (size_t)(m0 + row) * K + k0 + ck * 8;
        else if (arr == 1) src = Al + (size_t)(m0 + row) * K + k0 + ck * 8;
        else if (arr == 2) src = Bh + (size_t)(n0 + row) * K + k0 + ck * 8;
        else               src = Bl + (size_t)(n0 + row) * K + k0 + ck * 8;
        uint32_t dst = stage_base + (uint32_t)arr * ARR_BYTES + (uint32_t)(row * 144 + ck * 16);
        cpa16(dst, src);
    }
    asm volatile("cp.async.commit_group;" ::: "memory");
}

template <int EPI>
__global__ void __launch_bounds__(256, 1) mm_kernel(
    const __nv_bfloat16* __restrict__ Ah, const __nv_bfloat16* __restrict__ Al,
    const __nv_bfloat16* __restrict__ Bh, const __nv_bfloat16* __restrict__ Bl,
    const float* __restrict__ bias, const float* __restrict__ Rm,
    float* __restrict__ Cf, __nv_bfloat16* __restrict__ Ch, __nv_bfloat16* __restrict__ Cl,
    const float* __restrict__ rwb, const float* __restrict__ rrb,
    __nv_bfloat16* __restrict__ qwh, __nv_bfloat16* __restrict__ qwl,
    __nv_bfloat16* __restrict__ qrh, __nv_bfloat16* __restrict__ qrl,
    __nv_bfloat16* __restrict__ kkh, __nv_bfloat16* __restrict__ kkl,
    int M, int N, int K) {
    extern __shared__ char smem[];
    const uint32_t sbase = smem_u32(smem);
    const int tid = threadIdx.x;
    const int wid = tid >> 5, lane = tid & 31;
    const int m0 = blockIdx.y * BM, n0 = blockIdx.x * BN;
    const int mrow = (wid & 3) * 32;
    const int nrow = (wid >> 2) * 64;

    float c[2][8][4] = {};
    const int nch = K / BK;

    mm_load_chunk(Ah, Al, Bh, Bl, m0, n0, K, 0, sbase, tid);

    for (int t = 0; t < nch; t++) {
        asm volatile("cp.async.wait_group 0;" ::: "memory");
        __syncthreads();
        if (t + 1 < nch)
            mm_load_chunk(Ah, Al, Bh, Bl, m0, n0, K, t + 1, sbase + ((t + 1) & 1) * STAGE_BYTES, tid);
        const uint32_t sb = sbase + (t & 1) * STAGE_BYTES;
#pragma unroll
        for (int kk = 0; kk < 4; kk++) {
            uint32_t ah[2][4], al[2][4], bh[4][4], bl[4][4];
            ldsm_x4(ah[0], faddr(sb,                 mrow,      kk, lane));
            ldsm_x4(ah[1], faddr(sb,                 mrow + 16, kk, lane));
            ldsm_x4(al[0], faddr(sb + ARR_BYTES,     mrow,      kk, lane));
            ldsm_x4(al[1], faddr(sb + ARR_BYTES,     mrow + 16, kk, lane));
#pragma unroll
            for (int nf = 0; nf < 4; nf++)
                ldsm_x4(bh[nf], faddr(sb + 2 * ARR_BYTES, nrow + nf * 16, kk, lane));
#pragma unroll
            for (int nf = 0; nf < 4; nf++)
                ldsm_x4(bl[nf], faddr(sb + 3 * ARR_BYTES, nrow + nf * 16, kk, lane));
#pragma unroll
            for (int mi = 0; mi < 2; mi++)
#pragma unroll
                for (int nb = 0; nb < 8; nb++) {
                    const int nf = nb >> 1, o = nb & 1;
                    mma16816(c[mi][nb], ah[mi], bh[nf][o], bh[nf][2 + o]);
                    mma16816(c[mi][nb], ah[mi], bl[nf][o], bl[nf][2 + o]);
                    mma16816(c[mi][nb], al[mi], bh[nf][o], bh[nf][2 + o]);
                }
        }
    }

    const int tq = lane >> 2, tr = lane & 3;
#pragma unroll
    for (int mi = 0; mi < 2; mi++)
#pragma unroll
        for (int nb = 0; nb < 8; nb++)
#pragma unroll
            for (int hh = 0; hh < 2; hh++) {
                int gr = m0 + mrow + mi * 16 + tq + hh * 8;
                int gc = n0 + nrow + nb * 8 + tr * 2;
                float v0 = c[mi][nb][hh * 2 + 0];
                float v1 = c[mi][nb][hh * 2 + 1];
                if (EPI & 16) {
                    if (gc < D) {
                        size_t o = (size_t)gr * D + gc;
                        split2p(v0 + rwb[gc], v1 + rwb[gc + 1], qwh, qwl, o);
                        split2p(v0 + rrb[gc], v1 + rrb[gc + 1], qrh, qrl, o);
                    } else if (gc < 2 * D) {
                        split2p(v0, v1, kkh, kkl, (size_t)gr * D + gc - D);
                    } else {
                        float2 o2; o2.x = v0; o2.y = v1;
                        *(float2*)&Cf[(size_t)gr * N + gc] = o2;
                    }
                    continue;
                }
                if (EPI & 1) { v0 += bias[gc]; v1 += bias[gc + 1]; }
                if (EPI & 2) { v0 = fmaxf(v0, 0.f); v1 = fmaxf(v1, 0.f); }
                if (EPI & 4) {
                    float2 r = *(const float2*)&Rm[(size_t)gr * N + gc];
                    v0 += r.x; v1 += r.y;
                }
                if (EPI & 8) {
                    split2p(v0, v1, Ch, Cl, (size_t)gr * N + gc);
                } else {
                    float2 o; o.x = v0; o.y = v1;
                    *(float2*)&Cf[(size_t)gr * N + gc] = o;
                }
            }
}

// ======================= HMMA attention scores =======================
#define SA 18432
#define SC_RB   (6 * SA)
#define SC_SMEM (6 * SA + 2 * 36864)  // 184320

__global__ void __launch_bounds__(256, 1) scores_mma_kernel(
    const __nv_bfloat16* __restrict__ qwh, const __nv_bfloat16* __restrict__ qwl,
    const __nv_bfloat16* __restrict__ qrh, const __nv_bfloat16* __restrict__ qrl,
    const __nv_bfloat16* __restrict__ kh,  const __nv_bfloat16* __restrict__ kl,
    const __nv_bfloat16* __restrict__ rkh, const __nv_bfloat16* __restrict__ rkl,
    float* __restrict__ sc) {
    const int h = blockIdx.z;
    const int n = blockIdx.x;
    float rf = (sqrtf(8.f * n + 1.f) - 1.f) * 0.5f;
    int iT = (int)rf;
    if ((iT + 1) * (iT + 2) / 2 <= n) iT++;
    if (iT * (iT + 1) / 2 > n) iT--;
    const int jT = n - iT * (iT + 1) / 2;
    const int i0 = iT * 128, j0 = jT * 128;
    extern __shared__ char smem[];
    const uint32_t sb = smem_u32(smem);
    const int tid = threadIdx.x;
    const int wid = tid >> 5, lane = tid & 31;
    const int mrow = (wid & 3) * 32;
    const int nrow = (wid >> 2) * 64;
    const int pbase = T - 1 - i0 + j0 - 127;
    float* bdbuf = (float*)(smem);

#pragma unroll
    for (int e = 0; e < 24; e++) {
        int idx = e * 256 + tid;
        int arr = idx >> 10;
        int row = (idx >> 3) & 127;
        int ck  = idx & 7;
        const __nv_bfloat16* src;
        int grow = ((arr == 2 || arr == 3) ? j0 : i0) + row;
        if (arr == 0) src = qwh; else if (arr == 1) src = qwl;
        else if (arr == 2) src = kh; else if (arr == 3) src = kl;
        else if (arr == 4) src = qrh; else src = qrl;
        cpa16(sb + (uint32_t)arr * SA + (uint32_t)(row * 144 + ck * 16),
              src + (size_t)grow * D + h * DH + ck * 8);
    }
    asm volatile("cp.async.commit_group;" ::: "memory");
#pragma unroll
    for (int e = 0; e < 16; e++) {
        int idx = e * 256 + tid;
        int arr = idx >> 11;
        int row = (idx >> 3) & 255;
        int ck  = idx & 7;
        int p = pbase + row;
        bool valid = (p >= 0 && p < T);
        size_t off = valid ? ((size_t)p * D + h * DH + ck * 8) : 0;
        cpa16z(sb + SC_RB + (uint32_t)arr * 36864u + (uint32_t)(row * 144 + ck * 16),
               (arr == 0 ? rkh : rkl) + off, valid ? 16 : 0);
    }
    asm volatile("cp.async.commit_group;" ::: "memory");
    asm volatile("cp.async.wait_group 1;" ::: "memory");
    __syncthreads();

    const uint32_t bqwh = sb, bqwl = sb + SA, bkh = sb + 2 * SA, bkl = sb + 3 * SA;
    const uint32_t bqrh = sb + 4 * SA, bqrl = sb + 5 * SA;
    const uint32_t brh = sb + SC_RB, brl = sb + SC_RB + 36864;

    float acc[2][8][4] = {};
#pragma unroll
    for (int kk = 0; kk < 4; kk++) {
        uint32_t ah[2][4], al[2][4], bh[4][4], bl[4][4];
        ldsm_x4(ah[0], faddr(bqwh, mrow,      kk, lane));
        ldsm_x4(ah[1], faddr(bqwh, mrow + 16, kk, lane));
        ldsm_x4(al[0], faddr(bqwl, mrow,      kk, lane));
        ldsm_x4(al[1], faddr(bqwl, mrow + 16, kk, lane));
#pragma unroll
        for (int nf = 0; nf < 4; nf++) ldsm_x4(bh[nf], faddr(bkh, nrow + nf * 16, kk, lane));
#pragma unroll
        for (int nf = 0; nf < 4; nf++) ldsm_x4(bl[nf], faddr(bkl, nrow + nf * 16, kk, lane));
#pragma unroll
        for (int mi = 0; mi < 2; mi++)
#pragma unroll
            for (int nb = 0; nb < 8; nb++) {
                const int nf = nb >> 1, o = nb & 1;
                mma16816(acc[mi][nb], ah[mi], bh[nf][o], bh[nf][2 + o]);
                mma16816(acc[mi][nb], ah[mi], bl[nf][o], bl[nf][2 + o]);
                mma16816(acc[mi][nb], al[mi], bh[nf][o], bh[nf][2 + o]);
            }
    }
    asm volatile("cp.async.wait_group 0;" ::: "memory");
    __syncthreads();

    const int tq = lane >> 2, tr = lane & 3;
#pragma unroll 1
    for (int half = 0; half < 2; half++) {
        float c2[2][8][4] = {};
#pragma unroll
        for (int kk = 0; kk < 4; kk++) {
            uint32_t ah[2][4], al[2][4], bh[4][4], bl[4][4];
            ldsm_x4(ah[0], faddr(bqrh, mrow,      kk, lane));
            ldsm_x4(ah[1], faddr(bqrh, mrow + 16, kk, lane));
            ldsm_x4(al[0], faddr(bqrl, mrow,      kk, lane));
            ldsm_x4(al[1], faddr(bqrl, mrow + 16, kk, lane));
#pragma unroll
            for (int nf = 0; nf < 4; nf++)
                ldsm_x4(bh[nf], faddr(brh, half * 128 + nrow + nf * 16, kk, lane));
#pragma unroll
            for (int nf = 0; nf < 4; nf++)
                ldsm_x4(bl[nf], faddr(brl, half * 128 + nrow + nf * 16, kk, lane));
#pragma unroll
            for (int mi = 0; mi < 2; mi++)
#pragma unroll
                for (int nb = 0; nb < 8; nb++) {
                    const int nf = nb >> 1, o = nb & 1;
                    mma16816(c2[mi][nb], ah[mi], bh[nf][o], bh[nf][2 + o]);
                    mma16816(c2[mi][nb], ah[mi], bl[nf][o], bl[nf][2 + o]);
                    mma16816(c2[mi][nb], al[mi], bh[nf][o], bh[nf][2 + o]);
                }
        }
        __syncthreads();
#pragma unroll
        for (int mi = 0; mi < 2; mi++)
#pragma unroll
            for (int nb = 0; nb < 8; nb++)
#pragma unroll
                for (int hh = 0; hh < 2; hh++) {
                    int di = mrow + mi * 16 + tq + hh * 8;
                    int dj = nrow + nb * 8 + tr * 2;
                    bdbuf[di * 130 + dj]     = c2[mi][nb][hh * 2 + 0];
                    bdbuf[di * 130 + dj + 1] = c2[mi][nb][hh * 2 + 1];
                }
        __syncthreads();
#pragma unroll
        for (int mi = 0; mi < 2; mi++)
#pragma unroll
            for (int nb = 0; nb < 8; nb++)
#pragma unroll
                for (int hh = 0; hh < 2; hh++) {
                    int di = mrow + mi * 16 + tq + hh * 8;
                    int dj = nrow + nb * 8 + tr * 2;
#pragma unroll
                    for (int cc = 0; cc < 2; cc++) {
                        int pl = 127 + (dj + cc) - di;
                        if ((pl >> 7) == half)
                            acc[mi][nb][hh * 2 + cc] += bdbuf[di * 130 + (pl & 127)];
                    }
                }
        __syncthreads();
    }

    const float scale = 0.125f;
#pragma unroll
    for (int mi = 0; mi < 2; mi++)
#pragma unroll
        for (int nb = 0; nb < 8; nb++)
#pragma unroll
            for (int hh = 0; hh < 2; hh++) {
                int gi = i0 + mrow + mi * 16 + tq + hh * 8;
                int gj = j0 + nrow + nb * 8 + tr * 2;
                float2 o;
                o.x = acc[mi][nb][hh * 2 + 0] * scale;
                o.y = acc[mi][nb][hh * 2 + 1] * scale;
                *(float2*)&sc[((size_t)h * T + gi) * T + gj] = o;
            }
}

// ======================= causal softmax -> bf16 hi/lo probs (pad to 128) =====
__global__ void softmax_kernel(const float* __restrict__ sc, __nv_bfloat16* __restrict__ ph,
                               __nv_bfloat16* __restrict__ pl) {
    const int i = blockIdx.x;
    const int h = blockIdx.y;
    const size_t roff = ((size_t)h * T + i) * T;
    const float* row = sc + roff;
    const int t = threadIdx.x;
    const int n = i + 1;
    const int nup = (i & ~127) + 128;
    float4 v[2];
    float mx = -3.4e38f;
#pragma unroll
    for (int p = 0; p < 2; p++) {
        int j = (p * 256 + t) * 4;
        if (j < nup) {
            float4 w = *(const float4*)(row + j);
            w.x = (j + 0 < n) ? w.x : -3.4e38f;
            w.y = (j + 1 < n) ? w.y : -3.4e38f;
            w.z = (j + 2 < n) ? w.z : -3.4e38f;
            w.w = (j + 3 < n) ? w.w : -3.4e38f;
            v[p] = w;
            mx = fmaxf(mx, fmaxf(fmaxf(w.x, w.y), fmaxf(w.z, w.w)));
        } else {
            v[p].x = v[p].y = v[p].z = v[p].w = -3.4e38f;
        }
    }
    __shared__ float red1[8], red2[8];
    mx = warpMax(mx);
    if ((t & 31) == 0) red1[t >> 5] = mx;
    __syncthreads();
    mx = fmaxf(fmaxf(fmaxf(red1[0], red1[1]), fmaxf(red1[2], red1[3])),
               fmaxf(fmaxf(red1[4], red1[5]), fmaxf(red1[6], red1[7])));
    float s = 0.f;
#pragma unroll
    for (int p = 0; p < 2; p++) {
        float e0 = (v[p].x > -3.0e38f) ? __expf(v[p].x - mx) : 0.f;
        float e1 = (v[p].y > -3.0e38f) ? __expf(v[p].y - mx) : 0.f;
        float e2 = (v[p].z > -3.0e38f) ? __expf(v[p].z - mx) : 0.f;
        float e3 = (v[p].w > -3.0e38f) ? __expf(v[p].w - mx) : 0.f;
        v[p].x = e0; v[p].y = e1; v[p].z = e2; v[p].w = e3;
        s += e0 + e1 + e2 + e3;
    }
    s = warpSum(s);
    if ((t & 31) == 0) red2[t >> 5] = s;
    __syncthreads();
    float tot = red2[0] + red2[1] + red2[2] + red2[3] + red2[4] + red2[5] + red2[6] + red2[7];
    float inv = 1.0f / tot;
#pragma unroll
    for (int p = 0; p < 2; p++) {
        int j = (p * 256 + t) * 4;
        if (j < nup) {
            float p0 = v[p].x * inv, p1 = v[p].y * inv, p2 = v[p].z * inv, p3 = v[p].w * inv;
            float h0 = __bfloat162float(__float2bfloat16(p0));
            float h1 = __bfloat162float(__float2bfloat16(p1));
            float h2 = __bfloat162float(__float2bfloat16(p2));
            float h3 = __bfloat162float(__float2bfloat16(p3));
            uint2 hu, lu;
            hu.x = bf2pack(p0, p1); hu.y = bf2pack(p2, p3);
            lu.x = bf2pack(p0 - h0, p1 - h1); lu.y = bf2pack(p2 - h2, p3 - h3);
            *(uint2*)&ph[roff + j] = hu;
            *(uint2*)&pl[roff + j] = lu;
        }
    }
}

// ======================= probs layout: hi/lo [h][i][j] -> f32 [i][j][h] ========
// 4 j-subtiles per block (grid 8 x 2048)
__global__ void probs_out_kernel(const __nv_bfloat16* __restrict__ ph,
                                 const __nv_bfloat16* __restrict__ pl,
                                 float* __restrict__ out) {
    const int i = blockIdx.y;
    const int t = threadIdx.x;  // 256
    const int nup = (i & ~63) + 64;
    __shared__ float sm[16][66];
#pragma unroll 1
    for (int s = 0; s < 4; s++) {
        const int j0 = (blockIdx.x * 4 + s) * 64;
        float* dst = out + ((size_t)i * T + j0) * H;
        if (j0 < nup) {
#pragma unroll
            for (int e = 0; e < 2; e++) {
                int idx = e * 256 + t;
                int hh = idx >> 5, jp = idx & 31;
                size_t o = ((size_t)hh * T + i) * T + j0 + jp * 2;
                __nv_bfloat162 a = *(const __nv_bfloat162*)&ph[o];
                __nv_bfloat162 b = *(const __nv_bfloat162*)&pl[o];
                sm[hh][jp * 2]     = __bfloat162float(a.x) + __bfloat162float(b.x);
                sm[hh][jp * 2 + 1] = __bfloat162float(a.y) + __bfloat162float(b.y);
            }
            __syncthreads();
            int base = t * 4;
            float4 o4;
            o4.x = sm[(base + 0) & 15][(base + 0) >> 4];
            o4.y = sm[(base + 1) & 15][(base + 1) >> 4];
            o4.z = sm[(base + 2) & 15][(base + 2) >> 4];
            o4.w = sm[(base + 3) & 15][(base + 3) >> 4];
            *(float4*)&dst[base] = o4;
            __syncthreads();
        } else {
            float4 z; z.x = z.y = z.z = z.w = 0.f;
            *(float4*)&dst[t * 4] = z;
        }
    }
}

// ======================= HMMA PV: attn_vec = P @ V (128-row tiles) ===========
#define PV_PARR 18432
#define PV_VARR 9216
#define PV_STAGE (2 * PV_PARR + 2 * PV_VARR)  // 55296
#define PV_SMEM (2 * PV_STAGE)                // 110592

__device__ __forceinline__ void pv_load_chunk(
    const __nv_bfloat16* __restrict__ Ph, const __nv_bfloat16* __restrict__ Pl,
    const __nv_bfloat16* __restrict__ Vh, const __nv_bfloat16* __restrict__ Vl,
    int h, int i0, int t, uint32_t stage_base, int tid) {
    const size_t j0 = (size_t)t * 64;
#pragma unroll
    for (int e = 0; e < 12; e++) {
        int idx = e * 256 + tid;
        const __nv_bfloat16* src;
        uint32_t dst;
        if (idx < 2048) {
            int arr = idx >> 10;
            int row = (idx >> 3) & 127;
            int ck  = idx & 7;
            src = (arr == 0 ? Ph : Pl) + ((size_t)h * T + i0 + row) * T + j0 + ck * 8;
            dst = stage_base + (uint32_t)arr * PV_PARR + (uint32_t)(row * 144 + ck * 16);
        } else {
            int k = idx - 2048;
            int arr = k >> 9;
            int row = (k >> 3) & 63;
            int ck  = k & 7;
            src = (arr == 0 ? Vh : Vl) + (size_t)(h * DH + row) * T + j0 + ck * 8;
            dst = stage_base + 2 * PV_PARR + (uint32_t)arr * PV_VARR + (uint32_t)(row * 144 + ck * 16);
        }
        cpa16(dst, src);
    }
    asm volatile("cp.async.commit_group;" ::: "memory");
}

__global__ void __launch_bounds__(256, 1) pv_mma_kernel(
    const __nv_bfloat16* __restrict__ Ph, const __nv_bfloat16* __restrict__ Pl,
    const __nv_bfloat16* __restrict__ Vh, const __nv_bfloat16* __restrict__ Vl,
    __nv_bfloat16* __restrict__ avh, __nv_bfloat16* __restrict__ avl) {
    extern __shared__ char smem[];
    const uint32_t sbase = smem_u32(smem);
    const int h = blockIdx.y;
    const int i0 = (gridDim.x - 1 - blockIdx.x) * 128;   // longest first
    const int tid = threadIdx.x;
    const int wid = tid >> 5, lane = tid & 31;
    const int mrow = (wid & 3) * 32;
    const int nrow = (wid >> 2) * 32;

    float c[2][4][4] = {};
    const int nch = i0 / 64 + 2;

    pv_load_chunk(Ph, Pl, Vh, Vl, h, i0, 0, sbase, tid);

    for (int t = 0; t < nch; t++) {
        asm volatile("cp.async.wait_group 0;" ::: "memory");
        __syncthreads();
        if (t + 1 < nch)
            pv_load_chunk(Ph, Pl, Vh, Vl, h, i0, t + 1, sbase + ((t + 1) & 1) * PV_STAGE, tid);
        const uint32_t sb = sbase + (t & 1) * PV_STAGE;
        const uint32_t vb = sb + 2 * PV_PARR;
#pragma unroll
        for (int kk = 0; kk < 4; kk++) {
            uint32_t ah[2][4], al[2][4], bh[2][4], bl[2][4];
            ldsm_x4(ah[0], faddr(sb,           mrow,      kk, lane));
            ldsm_x4(ah[1], faddr(sb,           mrow + 16, kk, lane));
            ldsm_x4(al[0], faddr(sb + PV_PARR, mrow,      kk, lane));
            ldsm_x4(al[1], faddr(sb + PV_PARR, mrow + 16, kk, lane));
            ldsm_x4(bh[0], faddr(vb,           nrow,      kk, lane));
            ldsm_x4(bh[1], faddr(vb,           nrow + 16, kk, lane));
            ldsm_x4(bl[0], faddr(vb + PV_VARR, nrow,      kk, lane));
            ldsm_x4(bl[1], faddr(vb + PV_VARR, nrow + 16, kk, lane));
#pragma unroll
            for (int mi = 0; mi < 2; mi++)
#pragma unroll
                for (int nb = 0; nb < 4; nb++) {
                    const int nf = nb >> 1, o = nb & 1;
                    mma16816(c[mi][nb], ah[mi], bh[nf][o], bh[nf][2 + o]);
                    mma16816(c[mi][nb], ah[mi], bl[nf][o], bl[nf][2 + o]);
                    mma16816(c[mi][nb], al[mi], bh[nf][o], bh[nf][2 + o]);
                }
        }
    }

    const int tq = lane >> 2, tr = lane & 3;
#pragma unroll
    for (int mi = 0; mi < 2; mi++)
#pragma unroll
        for (int nb = 0; nb < 4; nb++)
#pragma unroll
            for (int hh = 0; hh < 2; hh++) {
                int gi = i0 + mrow + mi * 16 + tq + hh * 8;
                int gd = nrow + nb * 8 + tr * 2;
                size_t o = (size_t)gi * D + h * DH + gd;
                split2p(c[mi][nb][hh * 2 + 0], c[mi][nb][hh * 2 + 1], avh, avl, o);
            }
}

// ======================= host launch =======================
extern "C" void kernel_launch(void* const* d_in, const int* in_sizes, int n_in,
                              void* d_out, int out_size) {
    const float* input = (const float*)d_in[0];
    const float* pos   = (const float*)d_in[1];
    const float* rwb   = (const float*)d_in[2];
    const float* rrb   = (const float*)d_in[3];
    const float* ln1g  = (const float*)d_in[5];
    const float* ln1b  = (const float*)d_in[6];
    const float* qkvw  = (const float*)d_in[7];
    const float* rw    = (const float*)d_in[8];
    const float* ow    = (const float*)d_in[9];
    const float* ln2g  = (const float*)d_in[10];
    const float* ln2b  = (const float*)d_in[11];
    const float* ffw1  = (const float*)d_in[12];
    const float* ffb1  = (const float*)d_in[13];
    const float* ffw2  = (const float*)d_in[14];
    const float* ffb2  = (const float*)d_in[15];
    float* out = (float*)d_out;

    float *wheads, *scores, *x;
    cudaGetSymbolAddress((void**)&wheads, g_wheads);
    cudaGetSymbolAddress((void**)&scores, g_scores);
    cudaGetSymbolAddress((void**)&x,      g_x);
    __nv_bfloat16 *qin_h, *qin_l, *y_h, *y_l, *pos_h, *pos_l, *av_h, *av_l, *ff_h, *ff_l;
    cudaGetSymbolAddress((void**)&qin_h, g_qin_h); cudaGetSymbolAddress((void**)&qin_l, g_qin_l);
    cudaGetSymbolAddress((void**)&y_h,   g_y_h);   cudaGetSymbolAddress((void**)&y_l,   g_y_l);
    cudaGetSymbolAddress((void**)&pos_h, g_pos_h); cudaGetSymbolAddress((void**)&pos_l, g_pos_l);
    cudaGetSymbolAddress((void**)&av_h,  g_av_h);  cudaGetSymbolAddress((void**)&av_l,  g_av_l);
    cudaGetSymbolAddress((void**)&ff_h,  g_ff_h);  cudaGetSymbolAddress((void**)&ff_l,  g_ff_l);
    __nv_bfloat16 *qkvwT_h, *qkvwT_l, *rwT_h, *rwT_l, *owT_h, *owT_l, *w1T_h, *w1T_l, *w2T_h, *w2T_l;
    cudaGetSymbolAddress((void**)&qkvwT_h, g_qkvwT_h); cudaGetSymbolAddress((void**)&qkvwT_l, g_qkvwT_l);
    cudaGetSymbolAddress((void**)&rwT_h,   g_rwT_h);   cudaGetSymbolAddress((void**)&rwT_l,   g_rwT_l);
    cudaGetSymbolAddress((void**)&owT_h,   g_owT_h);   cudaGetSymbolAddress((void**)&owT_l,   g_owT_l);
    cudaGetSymbolAddress((void**)&w1T_h,   g_w1T_h);   cudaGetSymbolAddress((void**)&w1T_l,   g_w1T_l);
    cudaGetSymbolAddress((void**)&w2T_h,   g_w2T_h);   cudaGetSymbolAddress((void**)&w2T_l,   g_w2T_l);
    __nv_bfloat16 *ph, *pl, *vt_h, *vt_l;
    cudaGetSymbolAddress((void**)&ph, g_ph);     cudaGetSymbolAddress((void**)&pl, g_pl);
    cudaGetSymbolAddress((void**)&vt_h, g_vt_h); cudaGetSymbolAddress((void**)&vt_l, g_vt_l);
    __nv_bfloat16 *qw_h, *qw_l, *qr_h, *qr_l, *k_h, *k_l, *rk_h, *rk_l;
    cudaGetSymbolAddress((void**)&qw_h, g_qw_h); cudaGetSymbolAddress((void**)&qw_l, g_qw_l);
    cudaGetSymbolAddress((void**)&qr_h, g_qr_h); cudaGetSymbolAddress((void**)&qr_l, g_qr_l);
    cudaGetSymbolAddress((void**)&k_h,  g_k_h);  cudaGetSymbolAddress((void**)&k_l,  g_k_l);
    cudaGetSymbolAddress((void**)&rk_h, g_rk_h); cudaGetSymbolAddress((void**)&rk_l, g_rk_l);

    cudaFuncSetAttribute((const void*)mm_kernel<16>, cudaFuncAttributeMaxDynamicSharedMemorySize, MM_SMEM);
    cudaFuncSetAttribute((const void*)mm_kernel<4>,  cudaFuncAttributeMaxDynamicSharedMemorySize, MM_SMEM);
    cudaFuncSetAttribute((const void*)mm_kernel<8>,  cudaFuncAttributeMaxDynamicSharedMemorySize, MM_SMEM);
    cudaFuncSetAttribute((const void*)mm_kernel<11>, cudaFuncAttributeMaxDynamicSharedMemorySize, MM_SMEM);
    cudaFuncSetAttribute((const void*)mm_kernel<5>,  cudaFuncAttributeMaxDynamicSharedMemorySize, MM_SMEM);
    cudaFuncSetAttribute((const void*)scores_mma_kernel, cudaFuncAttributeMaxDynamicSharedMemorySize, SC_SMEM);
    cudaFuncSetAttribute((const void*)pv_mma_kernel,  cudaFuncAttributeMaxDynamicSharedMemorySize, PV_SMEM);

    const dim3 wthr(32, 8);
    const bool probs_fit =
        (long long)out_size >= (long long)T * D + (long long)H * T * T;

    // reordered so launch idx 3 (profiled slot) = QKV GEMM
    ln_kernel<<<T, 256>>>(input, ln1g, ln1b, qin_h, qin_l);                          // 0
    wconvT_kernel<<<dim3(D3 / 32, D / 32), wthr>>>(qkvw, qkvwT_h, qkvwT_l, D, D3);   // 1
    splitcvt_kernel<<<(T * D) / 1024, 256>>>(pos, pos_h, pos_l, T * D);              // 2
    mm_kernel<16><<<dim3(D3 / 128, T / 128), 256, MM_SMEM>>>(                         // 3
        qin_h, qin_l, qkvwT_h, qkvwT_l, nullptr, nullptr, wheads, nullptr, nullptr,
        rwb, rrb, qw_h, qw_l, qr_h, qr_l, k_h, k_l, T, D3, D);
    wconvT_kernel<<<dim3(D / 32,  D / 32), wthr>>>(rw,   rwT_h,   rwT_l,   D, D);    // 4
    vconvT_kernel<<<dim3(T / 32, D / 32), wthr>>>(wheads, vt_h, vt_l);               // 5
    mm_kernel<8><<<dim3(D / 128, T / 128), 256, MM_SMEM>>>(                           // 6
        pos_h, pos_l, rwT_h, rwT_l, nullptr, nullptr, nullptr, rk_h, rk_l,
        nullptr, nullptr, nullptr, nullptr, nullptr, nullptr, nullptr, nullptr, T, D, D);
    wconvT_kernel<<<dim3(D / 32,  D / 32), wthr>>>(ow,   owT_h,   owT_l,   D, D);    // 7
    scores_mma_kernel<<<dim3(136, 1, H), 256, SC_SMEM>>>(
        qw_h, qw_l, qr_h, qr_l, k_h, k_l, rk_h, rk_l, scores);
    softmax_kernel<<<dim3(T, H), 256>>>(scores, ph, pl);
    if (probs_fit) {
        probs_out_kernel<<<dim3(T / 256, T), 256>>>(ph, pl, out + (size_t)T * D);
    }
    pv_mma_kernel<<<dim3(T / 128, H), 256, PV_SMEM>>>(ph, pl, vt_h, vt_l, av_h, av_l);
    mm_kernel<4><<<dim3(D / 128, T / 128), 256, MM_SMEM>>>(
        av_h, av_l, owT_h, owT_l, nullptr, input, x, nullptr, nullptr,
        nullptr, nullptr, nullptr, nullptr, nullptr, nullptr, nullptr, nullptr, T, D, D);
    ln_kernel<<<T, 256>>>(x, ln2g, ln2b, y_h, y_l);
    wconvT_kernel<<<dim3(DFF / 32, D / 32), wthr>>>(ffw1, w1T_h, w1T_l, D, DFF);
    wconvT_kernel<<<dim3(D / 32, DFF / 32), wthr>>>(ffw2, w2T_h, w2T_l, DFF, D);
    mm_kernel<11><<<dim3(DFF / 128, T / 128), 256, MM_SMEM>>>(
        y_h, y_l, w1T_h, w1T_l, ffb1, nullptr, nullptr, ff_h, ff_l,
        nullptr, nullptr, nullptr, nullptr, nullptr, nullptr, nullptr, nullptr, T, DFF, D);
    mm_kernel<5><<<dim3(D / 128, T / 128), 256, MM_SMEM>>>(
        ff_h, ff_l, w2T_h, w2T_l, ffb2, x, out, nullptr, nullptr,
        nullptr, nullptr, nullptr, nullptr, nullptr, nullptr, nullptr, nullptr, T, D, DFF);
}

// round 11
// speedup vs baseline: 1.0347x; 1.0347x over previous
#include <cuda_runtime.h>
#include <cuda_bf16.h>
#include <math.h>
#include <stdint.h>

#define T 2048
#define D 1024
#define H 16
#define DH 64
#define DFF 4096
#define D3 3072

// ======================= scratch (device globals) =======================
__device__ float g_wheads[(size_t)T * D3];
__device__ float g_scores[(size_t)H * T * T];
__device__ float g_x[(size_t)T * D];

__device__ __nv_bfloat16 g_qin_h[(size_t)T * D],  g_qin_l[(size_t)T * D];
__device__ __nv_bfloat16 g_y_h[(size_t)T * D],    g_y_l[(size_t)T * D];
__device__ __nv_bfloat16 g_pos_h[(size_t)T * D],  g_pos_l[(size_t)T * D];
__device__ __nv_bfloat16 g_av_h[(size_t)T * D],   g_av_l[(size_t)T * D];
__device__ __nv_bfloat16 g_ff_h[(size_t)T * DFF], g_ff_l[(size_t)T * DFF];

__device__ __nv_bfloat16 g_qkvwT_h[(size_t)D3 * D],  g_qkvwT_l[(size_t)D3 * D];
__device__ __nv_bfloat16 g_rwT_h[(size_t)D * D],     g_rwT_l[(size_t)D * D];
__device__ __nv_bfloat16 g_owT_h[(size_t)D * D],     g_owT_l[(size_t)D * D];
__device__ __nv_bfloat16 g_w1T_h[(size_t)DFF * D],   g_w1T_l[(size_t)DFF * D];
__device__ __nv_bfloat16 g_w2T_h[(size_t)D * DFF],   g_w2T_l[(size_t)D * DFF];

__device__ __nv_bfloat16 g_ph[(size_t)H * T * T];   // probs hi
__device__ __nv_bfloat16 g_pl[(size_t)H * T * T];   // probs lo
__device__ __nv_bfloat16 g_vt_h[(size_t)D * T];     // V^T hi: [h*64+d][t]
__device__ __nv_bfloat16 g_vt_l[(size_t)D * T];

// pre-split attention inputs
__device__ __nv_bfloat16 g_qw_h[(size_t)T * D], g_qw_l[(size_t)T * D];
__device__ __nv_bfloat16 g_qr_h[(size_t)T * D], g_qr_l[(size_t)T * D];
__device__ __nv_bfloat16 g_k_h[(size_t)T * D],  g_k_l[(size_t)T * D];
__device__ __nv_bfloat16 g_rk_h[(size_t)T * D], g_rk_l[(size_t)T * D];

// ======================= small utils =======================
__device__ __forceinline__ float warpSum(float v) {
#pragma unroll
    for (int o = 16; o > 0; o >>= 1) v += __shfl_xor_sync(0xffffffffu, v, o);
    return v;
}
__device__ __forceinline__ float warpMax(float v) {
#pragma unroll
    for (int o = 16; o > 0; o >>= 1) v = fmaxf(v, __shfl_xor_sync(0xffffffffu, v, o));
    return v;
}
__device__ __forceinline__ uint32_t bf2pack(float a, float b) {
    __nv_bfloat162 t = __floats2bfloat162_rn(a, b);
    return *reinterpret_cast<uint32_t*>(&t);
}
__device__ __forceinline__ void split2p(float v0, float v1, __nv_bfloat16* h, __nv_bfloat16* l, size_t idx) {
    float h0 = __bfloat162float(__float2bfloat16(v0));
    float h1 = __bfloat162float(__float2bfloat16(v1));
    *(uint32_t*)&h[idx] = bf2pack(v0, v1);
    *(uint32_t*)&l[idx] = bf2pack(v0 - h0, v1 - h1);
}
__device__ __forceinline__ void split4(float4 v, __nv_bfloat16* h, __nv_bfloat16* l, size_t idx) {
    float h0 = __bfloat162float(__float2bfloat16(v.x));
    float h1 = __bfloat162float(__float2bfloat16(v.y));
    float h2 = __bfloat162float(__float2bfloat16(v.z));
    float h3 = __bfloat162float(__float2bfloat16(v.w));
    uint2 hu, lu;
    hu.x = bf2pack(v.x, v.y);     hu.y = bf2pack(v.z, v.w);
    lu.x = bf2pack(v.x - h0, v.y - h1);
    lu.y = bf2pack(v.z - h2, v.w - h3);
    *(uint2*)&h[idx] = hu;
    *(uint2*)&l[idx] = lu;
}
__device__ __forceinline__ uint32_t smem_u32(const void* p) {
    uint32_t a;
    asm("{ .reg .u64 tmp; cvta.to.shared.u64 tmp, %1; cvt.u32.u64 %0, tmp; }" : "=r"(a) : "l"(p));
    return a;
}

// ======================= HMMA helpers =======================
__device__ __forceinline__ void ldsm_x4(uint32_t* r, uint32_t addr) {
    asm volatile("ldmatrix.sync.aligned.m8n8.x4.shared.b16 {%0,%1,%2,%3}, [%4];"
                 : "=r"(r[0]), "=r"(r[1]), "=r"(r[2]), "=r"(r[3]) : "r"(addr));
}
__device__ __forceinline__ void mma16816(float* c, const uint32_t* a, uint32_t b0, uint32_t b1) {
    asm volatile(
        "mma.sync.aligned.m16n8k16.row.col.f32.bf16.bf16.f32 "
        "{%0,%1,%2,%3}, {%4,%5,%6,%7}, {%8,%9}, {%0,%1,%2,%3};"
        : "+f"(c[0]), "+f"(c[1]), "+f"(c[2]), "+f"(c[3])
        : "r"(a[0]), "r"(a[1]), "r"(a[2]), "r"(a[3]), "r"(b0), "r"(b1));
}
#define MMSTRIDE 72
__device__ __forceinline__ uint32_t faddr(uint32_t base, int row0, int kk, int lane) {
    return base + (uint32_t)(((row0 + (lane & 15)) * MMSTRIDE + kk * 16 + ((lane >> 4) << 3)) * 2);
}
__device__ __forceinline__ void cpa16(uint32_t dst, const void* src) {
    asm volatile("cp.async.cg.shared.global [%0], [%1], 16;"
                 :: "r"(dst), "l"(__cvta_generic_to_global(src)) : "memory");
}
__device__ __forceinline__ void cpa16z(uint32_t dst, const void* src, int bytes) {
    asm volatile("cp.async.cg.shared.global [%0], [%1], 16, %2;"
                 :: "r"(dst), "l"(__cvta_generic_to_global(src)), "r"(bytes) : "memory");
}

// ======================= convert kernels =======================
__global__ void splitcvt_kernel(const float* __restrict__ x, __nv_bfloat16* __restrict__ h,
                                __nv_bfloat16* __restrict__ l, int n) {
    int i = (blockIdx.x * 256 + threadIdx.x) * 4;
    if (i >= n) return;
    split4(*(const float4*)(x + i), h, l, i);
}

__global__ void wconvT_kernel(const float* __restrict__ W, __nv_bfloat16* __restrict__ th,
                              __nv_bfloat16* __restrict__ tl, int K, int N) {
    __shared__ float sm[32][33];
    const int k0 = blockIdx.y * 32, n0 = blockIdx.x * 32;
    const int tx = threadIdx.x, ty = threadIdx.y;   // 32 x 8
    const int t = ty * 32 + tx;
#pragma unroll
    for (int i = 0; i < 4; i++)
        sm[ty + 8 * i][tx] = W[(size_t)(k0 + ty + 8 * i) * N + n0 + tx];
    __syncthreads();
#pragma unroll
    for (int e = 0; e < 2; e++) {
        int pid = e * 256 + t;
        int n = pid >> 4, kp = pid & 15;
        float v0 = sm[2 * kp][n], v1 = sm[2 * kp + 1][n];
        split2p(v0, v1, th, tl, (size_t)(n0 + n) * K + k0 + 2 * kp);
    }
}

__global__ void vconvT_kernel(const float* __restrict__ wh, __nv_bfloat16* __restrict__ th,
                              __nv_bfloat16* __restrict__ tl) {
    __shared__ float sm[32][33];
    const int t0 = blockIdx.x * 32, c0 = blockIdx.y * 32;
    const int tx = threadIdx.x, ty = threadIdx.y;
    const int t = ty * 32 + tx;
#pragma unroll
    for (int i = 0; i < 4; i++)
        sm[ty + 8 * i][tx] = wh[(size_t)(t0 + ty + 8 * i) * D3 + 2 * D + c0 + tx];
    __syncthreads();
#pragma unroll
    for (int e = 0; e < 2; e++) {
        int pid = e * 256 + t;
        int c = pid >> 4, tp = pid & 15;
        float v0 = sm[2 * tp][c], v1 = sm[2 * tp + 1][c];
        split2p(v0, v1, th, tl, (size_t)(c0 + c) * T + t0 + 2 * tp);
    }
}

// ======================= layernorm =======================
__global__ void ln_kernel(const float* __restrict__ x, const float* __restrict__ g,
                          const float* __restrict__ b, __nv_bfloat16* __restrict__ oh,
                          __nv_bfloat16* __restrict__ ol) {
    const int row = blockIdx.x;
    const int t = threadIdx.x;
    const float* xr = x + (size_t)row * D;
    float4 v = *(const float4*)&xr[t * 4];
    float s = v.x + v.y + v.z + v.w;
    __shared__ float red1[8], red2[8];
    s = warpSum(s);
    if ((t & 31) == 0) red1[t >> 5] = s;
    __syncthreads();
    float tot = red1[0] + red1[1] + red1[2] + red1[3] + red1[4] + red1[5] + red1[6] + red1[7];
    const float mean = tot * (1.0f / D);
    float dx = v.x - mean, dy = v.y - mean, dz = v.z - mean, dw = v.w - mean;
    float s2 = dx * dx + dy * dy + dz * dz + dw * dw;
    s2 = warpSum(s2);
    if ((t & 31) == 0) red2[t >> 5] = s2;
    __syncthreads();
    float var = (red2[0] + red2[1] + red2[2] + red2[3] + red2[4] + red2[5] + red2[6] + red2[7]) * (1.0f / D);
    const float inv = rsqrtf(var + 1e-5f);
    float4 gg = *(const float4*)&g[t * 4];
    float4 bb = *(const float4*)&b[t * 4];
    float4 o;
    o.x = dx * inv * gg.x + bb.x;
    o.y = dy * inv * gg.y + bb.y;
    o.z = dz * inv * gg.z + bb.z;
    o.w = dw * inv * gg.w + bb.w;
    split4(o, oh, ol, (size_t)row * D + t * 4);
}

// ======================= HMMA GEMM: 128x64 tile, 2 CTAs/SM =======================
// EPI bits: 1=bias, 2=relu, 4=residual, 8=split-output, 16=QKV attn-prep epilogue
#define BM 128
#define BN 64
#define BK 64
#define A_ARR (128 * MMSTRIDE * 2)        // 18432
#define B_ARR (64 * MMSTRIDE * 2)         // 9216
#define STAGE_BYTES (2 * A_ARR + 2 * B_ARR)  // 55296
#define MM_SMEM (2 * STAGE_BYTES)            // 110592

__device__ __forceinline__ void mm_load_chunk(
    const __nv_bfloat16* __restrict__ Ah, const __nv_bfloat16* __restrict__ Al,
    const __nv_bfloat16* __restrict__ Bh, const __nv_bfloat16* __restrict__ Bl,
    int m0, int n0, int K, int t, uint32_t stage_base, int tid) {
    const size_t k0 = (size_t)t * BK;
#pragma unroll
    for (int e = 0; e < 12; e++) {
        int idx = e * 256 + tid;          // 0..3071
        const __nv_bfloat16* src;
        uint32_t dst;
        if (idx < 2048) {
            int arr = idx >> 10;          // 0: Ah, 1: Al
            int row = (idx >> 3) & 127;
            int ck  = idx & 7;
            src = (arr == 0 ? Ah : Al) + (size_t)(m0 + row) * K + k0 + ck * 8;
            dst = stage_base + (uint32_t)arr * A_ARR + (uint32_t)(row * 144 + ck * 16);
        } else {
            int k = idx - 2048;
            int arr = k >> 9;             // 0: Bh, 1: Bl
            int row = (k >> 3) & 63;
            int ck  = k & 7;
            src = (arr == 0 ? Bh : Bl) + (size_t)(n0 + row) * K + k0 + ck * 8;
            dst = stage_base + 2 * A_ARR + (uint32_t)arr * B_ARR + (uint32_t)(row * 144 + ck * 16);
        }
        cpa16(dst, src);
    }
    asm volatile("cp.async.commit_group;" ::: "memory");
}

template <int EPI>
__global__ void __launch_bounds__(256, 2) mm_kernel(
    const __nv_bfloat16* __restrict__ Ah, const __nv_bfloat16* __restrict__ Al,
    const __nv_bfloat16* __restrict__ Bh, const __nv_bfloat16* __restrict__ Bl,
    const float* __restrict__ bias, const float* __restrict__ Rm,
    float* __restrict__ Cf, __nv_bfloat16* __restrict__ Ch, __nv_bfloat16* __restrict__ Cl,
    const float* __restrict__ rwb, const float* __restrict__ rrb,
    __nv_bfloat16* __restrict__ qwh, __nv_bfloat16* __restrict__ qwl,
    __nv_bfloat16* __restrict__ qrh, __nv_bfloat16* __restrict__ qrl,
    __nv_bfloat16* __restrict__ kkh, __nv_bfloat16* __restrict__ kkl,
    int M, int N, int K) {
    extern __shared__ char smem[];
    const uint32_t sbase = smem_u32(smem);
    const int tid = threadIdx.x;
    const int wid = tid >> 5, lane = tid & 31;
    const int m0 = blockIdx.y * BM, n0 = blockIdx.x * BN;
    const int mrow = (wid & 3) * 32;
    const int nrow = (wid >> 2) * 32;

    float c[2][4][4] = {};
    const int nch = K / BK;

    mm_load_chunk(Ah, Al, Bh, Bl, m0, n0, K, 0, sbase, tid);

    for (int t = 0; t < nch; t++) {
        asm volatile("cp.async.wait_group 0;" ::: "memory");
        __syncthreads();
        if (t + 1 < nch)
            mm_load_chunk(Ah, Al, Bh, Bl, m0, n0, K, t + 1, sbase + ((t + 1) & 1) * STAGE_BYTES, tid);
        const uint32_t sb = sbase + (t & 1) * STAGE_BYTES;
        const uint32_t vb = sb + 2 * A_ARR;
#pragma unroll
        for (int kk = 0; kk < 4; kk++) {
            uint32_t ah[2][4], al[2][4], bh[2][4], bl[2][4];
            ldsm_x4(ah[0], faddr(sb,          mrow,      kk, lane));
            ldsm_x4(ah[1], faddr(sb,          mrow + 16, kk, lane));
            ldsm_x4(al[0], faddr(sb + A_ARR,  mrow,      kk, lane));
            ldsm_x4(al[1], faddr(sb + A_ARR,  mrow + 16, kk, lane));
            ldsm_x4(bh[0], faddr(vb,          nrow,      kk, lane));
            ldsm_x4(bh[1], faddr(vb,          nrow + 16, kk, lane));
            ldsm_x4(bl[0], faddr(vb + B_ARR,  nrow,      kk, lane));
            ldsm_x4(bl[1], faddr(vb + B_ARR,  nrow + 16, kk, lane));
#pragma unroll
            for (int mi = 0; mi < 2; mi++)
#pragma unroll
                for (int nb = 0; nb < 4; nb++) {
                    const int nf = nb >> 1, o = nb & 1;
                    mma16816(c[mi][nb], ah[mi], bh[nf][o], bh[nf][2 + o]);
                    mma16816(c[mi][nb], ah[mi], bl[nf][o], bl[nf][2 + o]);
                    mma16816(c[mi][nb], al[mi], bh[nf][o], bh[nf][2 + o]);
                }
        }
    }

    const int tq = lane >> 2, tr = lane & 3;
#pragma unroll
    for (int mi = 0; mi < 2; mi++)
#pragma unroll
        for (int nb = 0; nb < 4; nb++)
#pragma unroll
            for (int hh = 0; hh < 2; hh++) {
                int gr = m0 + mrow + mi * 16 + tq + hh * 8;
                int gc = n0 + nrow + nb * 8 + tr * 2;
                float v0 = c[mi][nb][hh * 2 + 0];
                float v1 = c[mi][nb][hh * 2 + 1];
                if (EPI & 16) {
                    if (gc < D) {
                        size_t o = (size_t)gr * D + gc;
                        split2p(v0 + rwb[gc], v1 + rwb[gc + 1], qwh, qwl, o);
                        split2p(v0 + rrb[gc], v1 + rrb[gc + 1], qrh, qrl, o);
                    } else if (gc < 2 * D) {
                        split2p(v0, v1, kkh, kkl, (size_t)gr * D + gc - D);
                    } else {
                        float2 o2; o2.x = v0; o2.y = v1;
                        *(float2*)&Cf[(size_t)gr * N + gc] = o2;
                    }
                    continue;
                }
                if (EPI & 1) { v0 += bias[gc]; v1 += bias[gc + 1]; }
                if (EPI & 2) { v0 = fmaxf(v0, 0.f); v1 = fmaxf(v1, 0.f); }
                if (EPI & 4) {
                    float2 r = *(const float2*)&Rm[(size_t)gr * N + gc];
                    v0 += r.x; v1 += r.y;
                }
                if (EPI & 8) {
                    split2p(v0, v1, Ch, Cl, (size_t)gr * N + gc);
                } else {
                    float2 o; o.x = v0; o.y = v1;
                    *(float2*)&Cf[(size_t)gr * N + gc] = o;
                }
            }
}

// ======================= HMMA attention scores =======================
#define SA 18432
#define SC_RB   (6 * SA)
#define SC_SMEM (6 * SA + 2 * 36864)  // 184320

__global__ void __launch_bounds__(256, 1) scores_mma_kernel(
    const __nv_bfloat16* __restrict__ qwh, const __nv_bfloat16* __restrict__ qwl,
    const __nv_bfloat16* __restrict__ qrh, const __nv_bfloat16* __restrict__ qrl,
    const __nv_bfloat16* __restrict__ kh,  const __nv_bfloat16* __restrict__ kl,
    const __nv_bfloat16* __restrict__ rkh, const __nv_bfloat16* __restrict__ rkl,
    float* __restrict__ sc) {
    const int h = blockIdx.z;
    const int n = blockIdx.x;
    float rf = (sqrtf(8.f * n + 1.f) - 1.f) * 0.5f;
    int iT = (int)rf;
    if ((iT + 1) * (iT + 2) / 2 <= n) iT++;
    if (iT * (iT + 1) / 2 > n) iT--;
    const int jT = n - iT * (iT + 1) / 2;
    const int i0 = iT * 128, j0 = jT * 128;
    extern __shared__ char smem[];
    const uint32_t sb = smem_u32(smem);
    const int tid = threadIdx.x;
    const int wid = tid >> 5, lane = tid & 31;
    const int mrow = (wid & 3) * 32;
    const int nrow = (wid >> 2) * 64;
    const int pbase = T - 1 - i0 + j0 - 127;
    float* bdbuf = (float*)(smem);

#pragma unroll
    for (int e = 0; e < 24; e++) {
        int idx = e * 256 + tid;
        int arr = idx >> 10;
        int row = (idx >> 3) & 127;
        int ck  = idx & 7;
        const __nv_bfloat16* src;
        int grow = ((arr == 2 || arr == 3) ? j0 : i0) + row;
        if (arr == 0) src = qwh; else if (arr == 1) src = qwl;
        else if (arr == 2) src = kh; else if (arr == 3) src = kl;
        else if (arr == 4) src = qrh; else src = qrl;
        cpa16(sb + (uint32_t)arr * SA + (uint32_t)(row * 144 + ck * 16),
              src + (size_t)grow * D + h * DH + ck * 8);
    }
    asm volatile("cp.async.commit_group;" ::: "memory");
#pragma unroll
    for (int e = 0; e < 16; e++) {
        int idx = e * 256 + tid;
        int arr = idx >> 11;
        int row = (idx >> 3) & 255;
        int ck  = idx & 7;
        int p = pbase + row;
        bool valid = (p >= 0 && p < T);
        size_t off = valid ? ((size_t)p * D + h * DH + ck * 8) : 0;
        cpa16z(sb + SC_RB + (uint32_t)arr * 36864u + (uint32_t)(row * 144 + ck * 16),
               (arr == 0 ? rkh : rkl) + off, valid ? 16 : 0);
    }
    asm volatile("cp.async.commit_group;" ::: "memory");
    asm volatile("cp.async.wait_group 1;" ::: "memory");
    __syncthreads();

    const uint32_t bqwh = sb, bqwl = sb + SA, bkh = sb + 2 * SA, bkl = sb + 3 * SA;
    const uint32_t bqrh = sb + 4 * SA, bqrl = sb + 5 * SA;
    const uint32_t brh = sb + SC_RB, brl = sb + SC_RB + 36864;

    float acc[2][8][4] = {};
#pragma unroll
    for (int kk = 0; kk < 4; kk++) {
        uint32_t ah[2][4], al[2][4], bh[4][4], bl[4][4];
        ldsm_x4(ah[0], faddr(bqwh, mrow,      kk, lane));
        ldsm_x4(ah[1], faddr(bqwh, mrow + 16, kk, lane));
        ldsm_x4(al[0], faddr(bqwl, mrow,      kk, lane));
        ldsm_x4(al[1], faddr(bqwl, mrow + 16, kk, lane));
#pragma unroll
        for (int nf = 0; nf < 4; nf++) ldsm_x4(bh[nf], faddr(bkh, nrow + nf * 16, kk, lane));
#pragma unroll
        for (int nf = 0; nf < 4; nf++) ldsm_x4(bl[nf], faddr(bkl, nrow + nf * 16, kk, lane));
#pragma unroll
        for (int mi = 0; mi < 2; mi++)
#pragma unroll
            for (int nb = 0; nb < 8; nb++) {
                const int nf = nb >> 1, o = nb & 1;
                mma16816(acc[mi][nb], ah[mi], bh[nf][o], bh[nf][2 + o]);
                mma16816(acc[mi][nb], ah[mi], bl[nf][o], bl[nf][2 + o]);
                mma16816(acc[mi][nb], al[mi], bh[nf][o], bh[nf][2 + o]);
            }
    }
    asm volatile("cp.async.wait_group 0;" ::: "memory");
    __syncthreads();

    const int tq = lane >> 2, tr = lane & 3;
#pragma unroll 1
    for (int half = 0; half < 2; half++) {
        float c2[2][8][4] = {};
#pragma unroll
        for (int kk = 0; kk < 4; kk++) {
            uint32_t ah[2][4], al[2][4], bh[4][4], bl[4][4];
            ldsm_x4(ah[0], faddr(bqrh, mrow,      kk, lane));
            ldsm_x4(ah[1], faddr(bqrh, mrow + 16, kk, lane));
            ldsm_x4(al[0], faddr(bqrl, mrow,      kk, lane));
            ldsm_x4(al[1], faddr(bqrl, mrow + 16, kk, lane));
#pragma unroll
            for (int nf = 0; nf < 4; nf++)
                ldsm_x4(bh[nf], faddr(brh, half * 128 + nrow + nf * 16, kk, lane));
#pragma unroll
            for (int nf = 0; nf < 4; nf++)
                ldsm_x4(bl[nf], faddr(brl, half * 128 + nrow + nf * 16, kk, lane));
#pragma unroll
            for (int mi = 0; mi < 2; mi++)
#pragma unroll
                for (int nb = 0; nb < 8; nb++) {
                    const int nf = nb >> 1, o = nb & 1;
                    mma16816(c2[mi][nb], ah[mi], bh[nf][o], bh[nf][2 + o]);
                    mma16816(c2[mi][nb], ah[mi], bl[nf][o], bl[nf][2 + o]);
                    mma16816(c2[mi][nb], al[mi], bh[nf][o], bh[nf][2 + o]);
                }
        }
        __syncthreads();
#pragma unroll
        for (int mi = 0; mi < 2; mi++)
#pragma unroll
            for (int nb = 0; nb < 8; nb++)
#pragma unroll
                for (int hh = 0; hh < 2; hh++) {
                    int di = mrow + mi * 16 + tq + hh * 8;
                    int dj = nrow + nb * 8 + tr * 2;
                    bdbuf[di * 130 + dj]     = c2[mi][nb][hh * 2 + 0];
                    bdbuf[di * 130 + dj + 1] = c2[mi][nb][hh * 2 + 1];
                }
        __syncthreads();
#pragma unroll
        for (int mi = 0; mi < 2; mi++)
#pragma unroll
            for (int nb = 0; nb < 8; nb++)
#pragma unroll
                for (int hh = 0; hh < 2; hh++) {
                    int di = mrow + mi * 16 + tq + hh * 8;
                    int dj = nrow + nb * 8 + tr * 2;
#pragma unroll
                    for (int cc = 0; cc < 2; cc++) {
                        int pl = 127 + (dj + cc) - di;
                        if ((pl >> 7) == half)
                            acc[mi][nb][hh * 2 + cc] += bdbuf[di * 130 + (pl & 127)];
                    }
                }
        __syncthreads();
    }

    const float scale = 0.125f;
#pragma unroll
    for (int mi = 0; mi < 2; mi++)
#pragma unroll
        for (int nb = 0; nb < 8; nb++)
#pragma unroll
            for (int hh = 0; hh < 2; hh++) {
                int gi = i0 + mrow + mi * 16 + tq + hh * 8;
                int gj = j0 + nrow + nb * 8 + tr * 2;
                float2 o;
                o.x = acc[mi][nb][hh * 2 + 0] * scale;
                o.y = acc[mi][nb][hh * 2 + 1] * scale;
                *(float2*)&sc[((size_t)h * T + gi) * T + gj] = o;
            }
}

// ======================= causal softmax -> bf16 hi/lo probs (pad to 128) =====
__global__ void softmax_kernel(const float* __restrict__ sc, __nv_bfloat16* __restrict__ ph,
                               __nv_bfloat16* __restrict__ pl) {
    const int i = blockIdx.x;
    const int h = blockIdx.y;
    const size_t roff = ((size_t)h * T + i) * T;
    const float* row = sc + roff;
    const int t = threadIdx.x;
    const int n = i + 1;
    const int nup = (i & ~127) + 128;
    float4 v[2];
    float mx = -3.4e38f;
#pragma unroll
    for (int p = 0; p < 2; p++) {
        int j = (p * 256 + t) * 4;
        if (j < nup) {
            float4 w = *(const float4*)(row + j);
            w.x = (j + 0 < n) ? w.x : -3.4e38f;
            w.y = (j + 1 < n) ? w.y : -3.4e38f;
            w.z = (j + 2 < n) ? w.z : -3.4e38f;
            w.w = (j + 3 < n) ? w.w : -3.4e38f;
            v[p] = w;
            mx = fmaxf(mx, fmaxf(fmaxf(w.x, w.y), fmaxf(w.z, w.w)));
        } else {
            v[p].x = v[p].y = v[p].z = v[p].w = -3.4e38f;
        }
    }
    __shared__ float red1[8], red2[8];
    mx = warpMax(mx);
    if ((t & 31) == 0) red1[t >> 5] = mx;
    __syncthreads();
    mx = fmaxf(fmaxf(fmaxf(red1[0], red1[1]), fmaxf(red1[2], red1[3])),
               fmaxf(fmaxf(red1[4], red1[5]), fmaxf(red1[6], red1[7])));
    float s = 0.f;
#pragma unroll
    for (int p = 0; p < 2; p++) {
        float e0 = (v[p].x > -3.0e38f) ? __expf(v[p].x - mx) : 0.f;
        float e1 = (v[p].y > -3.0e38f) ? __expf(v[p].y - mx) : 0.f;
        float e2 = (v[p].z > -3.0e38f) ? __expf(v[p].z - mx) : 0.f;
        float e3 = (v[p].w > -3.0e38f) ? __expf(v[p].w - mx) : 0.f;
        v[p].x = e0; v[p].y = e1; v[p].z = e2; v[p].w = e3;
        s += e0 + e1 + e2 + e3;
    }
    s = warpSum(s);
    if ((t & 31) == 0) red2[t >> 5] = s;
    __syncthreads();
    float tot = red2[0] + red2[1] + red2[2] + red2[3] + red2[4] + red2[5] + red2[6] + red2[7];
    float inv = 1.0f / tot;
#pragma unroll
    for (int p = 0; p < 2; p++) {
        int j = (p * 256 + t) * 4;
        if (j < nup) {
            float p0 = v[p].x * inv, p1 = v[p].y * inv, p2 = v[p].z * inv, p3 = v[p].w * inv;
            float h0 = __bfloat162float(__float2bfloat16(p0));
            float h1 = __bfloat162float(__float2bfloat16(p1));
            float h2 = __bfloat162float(__float2bfloat16(p2));
            float h3 = __bfloat162float(__float2bfloat16(p3));
            uint2 hu, lu;
            hu.x = bf2pack(p0, p1); hu.y = bf2pack(p2, p3);
            lu.x = bf2pack(p0 - h0, p1 - h1); lu.y = bf2pack(p2 - h2, p3 - h3);
            *(uint2*)&ph[roff + j] = hu;
            *(uint2*)&pl[roff + j] = lu;
        }
    }
}

// ======================= probs layout: hi/lo [h][i][j] -> f32 [i][j][h] ========
__global__ void probs_out_kernel(const __nv_bfloat16* __restrict__ ph,
                                 const __nv_bfloat16* __restrict__ pl,
                                 float* __restrict__ out) {
    const int i = blockIdx.y;
    const int t = threadIdx.x;
    const int nup = (i & ~63) + 64;
    __shared__ float sm[16][66];
#pragma unroll 1
    for (int s = 0; s < 4; s++) {
        const int j0 = (blockIdx.x * 4 + s) * 64;
        float* dst = out + ((size_t)i * T + j0) * H;
        if (j0 < nup) {
#pragma unroll
            for (int e = 0; e < 2; e++) {
                int idx = e * 256 + t;
                int hh = idx >> 5, jp = idx & 31;
                size_t o = ((size_t)hh * T + i) * T + j0 + jp * 2;
                __nv_bfloat162 a = *(const __nv_bfloat162*)&ph[o];
                __nv_bfloat162 b = *(const __nv_bfloat162*)&pl[o];
                sm[hh][jp * 2]     = __bfloat162float(a.x) + __bfloat162float(b.x);
                sm[hh][jp * 2 + 1] = __bfloat162float(a.y) + __bfloat162float(b.y);
            }
            __syncthreads();
            int base = t * 4;
            float4 o4;
            o4.x = sm[(base + 0) & 15][(base + 0) >> 4];
            o4.y = sm[(base + 1) & 15][(base + 1) >> 4];
            o4.z = sm[(base + 2) & 15][(base + 2) >> 4];
            o4.w = sm[(base + 3) & 15][(base + 3) >> 4];
            *(float4*)&dst[base] = o4;
            __syncthreads();
        } else {
            float4 z; z.x = z.y = z.z = z.w = 0.f;
            *(float4*)&dst[t * 4] = z;
        }
    }
}

// ======================= HMMA PV: attn_vec = P @ V (128-row tiles, 2 CTA/SM) ===
#define PV_PARR 18432
#define PV_VARR 9216
#define PV_STAGE (2 * PV_PARR + 2 * PV_VARR)  // 55296
#define PV_SMEM (2 * PV_STAGE)                // 110592

__device__ __forceinline__ void pv_load_chunk(
    const __nv_bfloat16* __restrict__ Ph, const __nv_bfloat16* __restrict__ Pl,
    const __nv_bfloat16* __restrict__ Vh, const __nv_bfloat16* __restrict__ Vl,
    int h, int i0, int t, uint32_t stage_base, int tid) {
    const size_t j0 = (size_t)t * 64;
#pragma unroll
    for (int e = 0; e < 12; e++) {
        int idx = e * 256 + tid;
        const __nv_bfloat16* src;
        uint32_t dst;
        if (idx < 2048) {
            int arr = idx >> 10;
            int row = (idx >> 3) & 127;
            int ck  = idx & 7;
            src = (arr == 0 ? Ph : Pl) + ((size_t)h * T + i0 + row) * T + j0 + ck * 8;
            dst = stage_base + (uint32_t)arr * PV_PARR + (uint32_t)(row * 144 + ck * 16);
        } else {
            int k = idx - 2048;
            int arr = k >> 9;
            int row = (k >> 3) & 63;
            int ck  = k & 7;
            src = (arr == 0 ? Vh : Vl) + (size_t)(h * DH + row) * T + j0 + ck * 8;
            dst = stage_base + 2 * PV_PARR + (uint32_t)arr * PV_VARR + (uint32_t)(row * 144 + ck * 16);
        }
        cpa16(dst, src);
    }
    asm volatile("cp.async.commit_group;" ::: "memory");
}

__global__ void __launch_bounds__(256, 2) pv_mma_kernel(
    const __nv_bfloat16* __restrict__ Ph, const __nv_bfloat16* __restrict__ Pl,
    const __nv_bfloat16* __restrict__ Vh, const __nv_bfloat16* __restrict__ Vl,
    __nv_bfloat16* __restrict__ avh, __nv_bfloat16* __restrict__ avl) {
    extern __shared__ char smem[];
    const uint32_t sbase = smem_u32(smem);
    const int h = blockIdx.y;
    const int i0 = (gridDim.x - 1 - blockIdx.x) * 128;   // longest first
    const int tid = threadIdx.x;
    const int wid = tid >> 5, lane = tid & 31;
    const int mrow = (wid & 3) * 32;
    const int nrow = (wid >> 2) * 32;

    float c[2][4][4] = {};
    const int nch = i0 / 64 + 2;

    pv_load_chunk(Ph, Pl, Vh, Vl, h, i0, 0, sbase, tid);

    for (int t = 0; t < nch; t++) {
        asm volatile("cp.async.wait_group 0;" ::: "memory");
        __syncthreads();
        if (t + 1 < nch)
            pv_load_chunk(Ph, Pl, Vh, Vl, h, i0, t + 1, sbase + ((t + 1) & 1) * PV_STAGE, tid);
        const uint32_t sb = sbase + (t & 1) * PV_STAGE;
        const uint32_t vb = sb + 2 * PV_PARR;
#pragma unroll
        for (int kk = 0; kk < 4; kk++) {
            uint32_t ah[2][4], al[2][4], bh[2][4], bl[2][4];
            ldsm_x4(ah[0], faddr(sb,           mrow,      kk, lane));
            ldsm_x4(ah[1], faddr(sb,           mrow + 16, kk, lane));
            ldsm_x4(al[0], faddr(sb + PV_PARR, mrow,      kk, lane));
            ldsm_x4(al[1], faddr(sb + PV_PARR, mrow + 16, kk, lane));
            ldsm_x4(bh[0], faddr(vb,           nrow,      kk, lane));
            ldsm_x4(bh[1], faddr(vb,           nrow + 16, kk, lane));
            ldsm_x4(bl[0], faddr(vb + PV_VARR, nrow,      kk, lane));
            ldsm_x4(bl[1], faddr(vb + PV_VARR, nrow + 16, kk, lane));
#pragma unroll
            for (int mi = 0; mi < 2; mi++)
#pragma unroll
                for (int nb = 0; nb < 4; nb++) {
                    const int nf = nb >> 1, o = nb & 1;
                    mma16816(c[mi][nb], ah[mi], bh[nf][o], bh[nf][2 + o]);
                    mma16816(c[mi][nb], ah[mi], bl[nf][o], bl[nf][2 + o]);
                    mma16816(c[mi][nb], al[mi], bh[nf][o], bh[nf][2 + o]);
                }
        }
    }

    const int tq = lane >> 2, tr = lane & 3;
#pragma unroll
    for (int mi = 0; mi < 2; mi++)
#pragma unroll
        for (int nb = 0; nb < 4; nb++)
#pragma unroll
            for (int hh = 0; hh < 2; hh++) {
                int gi = i0 + mrow + mi * 16 + tq + hh * 8;
                int gd = nrow + nb * 8 + tr * 2;
                size_t o = (size_t)gi * D + h * DH + gd;
                split2p(c[mi][nb][hh * 2 + 0], c[mi][nb][hh * 2 + 1], avh, avl, o);
            }
}

// ======================= host launch =======================
extern "C" void kernel_launch(void* const* d_in, const int* in_sizes, int n_in,
                              void* d_out, int out_size) {
    const float* input = (const float*)d_in[0];
    const float* pos   = (const float*)d_in[1];
    const float* rwb   = (const float*)d_in[2];
    const float* rrb   = (const float*)d_in[3];
    const float* ln1g  = (const float*)d_in[5];
    const float* ln1b  = (const float*)d_in[6];
    const float* qkvw  = (const float*)d_in[7];
    const float* rw    = (const float*)d_in[8];
    const float* ow    = (const float*)d_in[9];
    const float* ln2g  = (const float*)d_in[10];
    const float* ln2b  = (const float*)d_in[11];
    const float* ffw1  = (const float*)d_in[12];
    const float* ffb1  = (const float*)d_in[13];
    const float* ffw2  = (const float*)d_in[14];
    const float* ffb2  = (const float*)d_in[15];
    float* out = (float*)d_out;

    float *wheads, *scores, *x;
    cudaGetSymbolAddress((void**)&wheads, g_wheads);
    cudaGetSymbolAddress((void**)&scores, g_scores);
    cudaGetSymbolAddress((void**)&x,      g_x);
    __nv_bfloat16 *qin_h, *qin_l, *y_h, *y_l, *pos_h, *pos_l, *av_h, *av_l, *ff_h, *ff_l;
    cudaGetSymbolAddress((void**)&qin_h, g_qin_h); cudaGetSymbolAddress((void**)&qin_l, g_qin_l);
    cudaGetSymbolAddress((void**)&y_h,   g_y_h);   cudaGetSymbolAddress((void**)&y_l,   g_y_l);
    cudaGetSymbolAddress((void**)&pos_h, g_pos_h); cudaGetSymbolAddress((void**)&pos_l, g_pos_l);
    cudaGetSymbolAddress((void**)&av_h,  g_av_h);  cudaGetSymbolAddress((void**)&av_l,  g_av_l);
    cudaGetSymbolAddress((void**)&ff_h,  g_ff_h);  cudaGetSymbolAddress((void**)&ff_l,  g_ff_l);
    __nv_bfloat16 *qkvwT_h, *qkvwT_l, *rwT_h, *rwT_l, *owT_h, *owT_l, *w1T_h, *w1T_l, *w2T_h, *w2T_l;
    cudaGetSymbolAddress((void**)&qkvwT_h, g_qkvwT_h); cudaGetSymbolAddress((void**)&qkvwT_l, g_qkvwT_l);
    cudaGetSymbolAddress((void**)&rwT_h,   g_rwT_h);   cudaGetSymbolAddress((void**)&rwT_l,   g_rwT_l);
    cudaGetSymbolAddress((void**)&owT_h,   g_owT_h);   cudaGetSymbolAddress((void**)&owT_l,   g_owT_l);
    cudaGetSymbolAddress((void**)&w1T_h,   g_w1T_h);   cudaGetSymbolAddress((void**)&w1T_l,   g_w1T_l);
    cudaGetSymbolAddress((void**)&w2T_h,   g_w2T_h);   cudaGetSymbolAddress((void**)&w2T_l,   g_w2T_l);
    __nv_bfloat16 *ph, *pl, *vt_h, *vt_l;
    cudaGetSymbolAddress((void**)&ph, g_ph);     cudaGetSymbolAddress((void**)&pl, g_pl);
    cudaGetSymbolAddress((void**)&vt_h, g_vt_h); cudaGetSymbolAddress((void**)&vt_l, g_vt_l);
    __nv_bfloat16 *qw_h, *qw_l, *qr_h, *qr_l, *k_h, *k_l, *rk_h, *rk_l;
    cudaGetSymbolAddress((void**)&qw_h, g_qw_h); cudaGetSymbolAddress((void**)&qw_l, g_qw_l);
    cudaGetSymbolAddress((void**)&qr_h, g_qr_h); cudaGetSymbolAddress((void**)&qr_l, g_qr_l);
    cudaGetSymbolAddress((void**)&k_h,  g_k_h);  cudaGetSymbolAddress((void**)&k_l,  g_k_l);
    cudaGetSymbolAddress((void**)&rk_h, g_rk_h); cudaGetSymbolAddress((void**)&rk_l, g_rk_l);

    cudaFuncSetAttribute((const void*)mm_kernel<16>, cudaFuncAttributeMaxDynamicSharedMemorySize, MM_SMEM);
    cudaFuncSetAttribute((const void*)mm_kernel<4>,  cudaFuncAttributeMaxDynamicSharedMemorySize, MM_SMEM);
    cudaFuncSetAttribute((const void*)mm_kernel<8>,  cudaFuncAttributeMaxDynamicSharedMemorySize, MM_SMEM);
    cudaFuncSetAttribute((const void*)mm_kernel<11>, cudaFuncAttributeMaxDynamicSharedMemorySize, MM_SMEM);
    cudaFuncSetAttribute((const void*)mm_kernel<5>,  cudaFuncAttributeMaxDynamicSharedMemorySize, MM_SMEM);
    cudaFuncSetAttribute((const void*)scores_mma_kernel, cudaFuncAttributeMaxDynamicSharedMemorySize, SC_SMEM);
    cudaFuncSetAttribute((const void*)pv_mma_kernel,  cudaFuncAttributeMaxDynamicSharedMemorySize, PV_SMEM);

    const dim3 wthr(32, 8);
    const bool probs_fit =
        (long long)out_size >= (long long)T * D + (long long)H * T * T;

    ln_kernel<<<T, 256>>>(input, ln1g, ln1b, qin_h, qin_l);                          // 0
    wconvT_kernel<<<dim3(D3 / 32, D / 32), wthr>>>(qkvw, qkvwT_h, qkvwT_l, D, D3);   // 1
    splitcvt_kernel<<<(T * D) / 1024, 256>>>(pos, pos_h, pos_l, T * D);              // 2
    mm_kernel<16><<<dim3(D3 / 64, T / 128), 256, MM_SMEM>>>(                          // 3 (profiled)
        qin_h, qin_l, qkvwT_h, qkvwT_l, nullptr, nullptr, wheads, nullptr, nullptr,
        rwb, rrb, qw_h, qw_l, qr_h, qr_l, k_h, k_l, T, D3, D);
    wconvT_kernel<<<dim3(D / 32,  D / 32), wthr>>>(rw,   rwT_h,   rwT_l,   D, D);    // 4
    vconvT_kernel<<<dim3(T / 32, D / 32), wthr>>>(wheads, vt_h, vt_l);               // 5
    mm_kernel<8><<<dim3(D / 64, T / 128), 256, MM_SMEM>>>(                            // 6
        pos_h, pos_l, rwT_h, rwT_l, nullptr, nullptr, nullptr, rk_h, rk_l,
        nullptr, nullptr, nullptr, nullptr, nullptr, nullptr, nullptr, nullptr, T, D, D);
    wconvT_kernel<<<dim3(D / 32,  D / 32), wthr>>>(ow,   owT_h,   owT_l,   D, D);    // 7
    scores_mma_kernel<<<dim3(136, 1, H), 256, SC_SMEM>>>(
        qw_h, qw_l, qr_h, qr_l, k_h, k_l, rk_h, rk_l, scores);
    softmax_kernel<<<dim3(T, H), 256>>>(scores, ph, pl);
    if (probs_fit) {
        probs_out_kernel<<<dim3(T / 256, T), 256>>>(ph, pl, out + (size_t)T * D);
    }
    pv_mma_kernel<<<dim3(T / 128, H), 256, PV_SMEM>>>(ph, pl, vt_h, vt_l, av_h, av_l);
    mm_kernel<4><<<dim3(D / 64, T / 128), 256, MM_SMEM>>>(
        av_h, av_l, owT_h, owT_l, nullptr, input, x, nullptr, nullptr,
        nullptr, nullptr, nullptr, nullptr, nullptr, nullptr, nullptr, nullptr, T, D, D);
    ln_kernel<<<T, 256>>>(x, ln2g, ln2b, y_h, y_l);
    wconvT_kernel<<<dim3(DFF / 32, D / 32), wthr>>>(ffw1, w1T_h, w1T_l, D, DFF);
    wconvT_kernel<<<dim3(D / 32, DFF / 32), wthr>>>(ffw2, w2T_h, w2T_l, DFF, D);
    mm_kernel<11><<<dim3(DFF / 64, T / 128), 256, MM_SMEM>>>(
        y_h, y_l, w1T_h, w1T_l, ffb1, nullptr, nullptr, ff_h, ff_l,
        nullptr, nullptr, nullptr, nullptr, nullptr, nullptr, nullptr, nullptr, T, DFF, D);
    mm_kernel<5><<<dim3(D / 64, T / 128), 256, MM_SMEM>>>(
        ff_h, ff_l, w2T_h, w2T_l, ffb2, x, out, nullptr, nullptr,
        nullptr, nullptr, nullptr, nullptr, nullptr, nullptr, nullptr, nullptr, T, D, DFF);
}

// round 12
// speedup vs baseline: 1.2990x; 1.2554x over previous
#include <cuda_runtime.h>
#include <cuda_bf16.h>
#include <cuda_fp16.h>
#include <math.h>
#include <stdint.h>

#define T 2048
#define D 1024
#define H 16
#define DH 64
#define DFF 4096
#define D3 3072

// ======================= scratch (device globals) =======================
__device__ float g_wheads[(size_t)T * D3];
__device__ float g_scores[(size_t)H * T * T];
__device__ float g_x[(size_t)T * D];

__device__ __nv_bfloat16 g_qin_h[(size_t)T * D],  g_qin_l[(size_t)T * D];
__device__ __nv_bfloat16 g_pos_h[(size_t)T * D],  g_pos_l[(size_t)T * D];
__device__ __nv_bfloat16 g_av_h[(size_t)T * D],   g_av_l[(size_t)T * D];

__device__ __nv_bfloat16 g_qkvwT_h[(size_t)D3 * D],  g_qkvwT_l[(size_t)D3 * D];
__device__ __nv_bfloat16 g_rwT_h[(size_t)D * D],     g_rwT_l[(size_t)D * D];
__device__ __nv_bfloat16 g_owT_h[(size_t)D * D],     g_owT_l[(size_t)D * D];

__device__ __nv_bfloat16 g_ph[(size_t)H * T * T];
__device__ __nv_bfloat16 g_pl[(size_t)H * T * T];
__device__ __nv_bfloat16 g_vt_h[(size_t)D * T];
__device__ __nv_bfloat16 g_vt_l[(size_t)D * T];

__device__ __nv_bfloat16 g_qw_h[(size_t)T * D], g_qw_l[(size_t)T * D];
__device__ __nv_bfloat16 g_qr_h[(size_t)T * D], g_qr_l[(size_t)T * D];
__device__ __nv_bfloat16 g_k_h[(size_t)T * D],  g_k_l[(size_t)T * D];
__device__ __nv_bfloat16 g_rk_h[(size_t)T * D], g_rk_l[(size_t)T * D];

// fp16 FFN path
__device__ __half g_y16[(size_t)T * D];
__device__ __half g_ff16[(size_t)T * DFF];
__device__ __half g_w1T16[(size_t)DFF * D];
__device__ __half g_w2T16[(size_t)D * DFF];

// ======================= small utils =======================
__device__ __forceinline__ float warpSum(float v) {
#pragma unroll
    for (int o = 16; o > 0; o >>= 1) v += __shfl_xor_sync(0xffffffffu, v, o);
    return v;
}
__device__ __forceinline__ float warpMax(float v) {
#pragma unroll
    for (int o = 16; o > 0; o >>= 1) v = fmaxf(v, __shfl_xor_sync(0xffffffffu, v, o));
    return v;
}
__device__ __forceinline__ uint32_t bf2pack(float a, float b) {
    __nv_bfloat162 t = __floats2bfloat162_rn(a, b);
    return *reinterpret_cast<uint32_t*>(&t);
}
__device__ __forceinline__ uint32_t h2pack(float a, float b) {
    __half2 t = __floats2half2_rn(a, b);
    return *reinterpret_cast<uint32_t*>(&t);
}
__device__ __forceinline__ void split2p(float v0, float v1, __nv_bfloat16* h, __nv_bfloat16* l, size_t idx) {
    float h0 = __bfloat162float(__float2bfloat16(v0));
    float h1 = __bfloat162float(__float2bfloat16(v1));
    *(uint32_t*)&h[idx] = bf2pack(v0, v1);
    *(uint32_t*)&l[idx] = bf2pack(v0 - h0, v1 - h1);
}
__device__ __forceinline__ void split4(float4 v, __nv_bfloat16* h, __nv_bfloat16* l, size_t idx) {
    float h0 = __bfloat162float(__float2bfloat16(v.x));
    float h1 = __bfloat162float(__float2bfloat16(v.y));
    float h2 = __bfloat162float(__float2bfloat16(v.z));
    float h3 = __bfloat162float(__float2bfloat16(v.w));
    uint2 hu, lu;
    hu.x = bf2pack(v.x, v.y);     hu.y = bf2pack(v.z, v.w);
    lu.x = bf2pack(v.x - h0, v.y - h1);
    lu.y = bf2pack(v.z - h2, v.w - h3);
    *(uint2*)&h[idx] = hu;
    *(uint2*)&l[idx] = lu;
}
__device__ __forceinline__ uint32_t smem_u32(const void* p) {
    uint32_t a;
    asm("{ .reg .u64 tmp; cvta.to.shared.u64 tmp, %1; cvt.u32.u64 %0, tmp; }" : "=r"(a) : "l"(p));
    return a;
}

// ======================= HMMA helpers =======================
__device__ __forceinline__ void ldsm_x4(uint32_t* r, uint32_t addr) {
    asm volatile("ldmatrix.sync.aligned.m8n8.x4.shared.b16 {%0,%1,%2,%3}, [%4];"
                 : "=r"(r[0]), "=r"(r[1]), "=r"(r[2]), "=r"(r[3]) : "r"(addr));
}
__device__ __forceinline__ void mma16816(float* c, const uint32_t* a, uint32_t b0, uint32_t b1) {
    asm volatile(
        "mma.sync.aligned.m16n8k16.row.col.f32.bf16.bf16.f32 "
        "{%0,%1,%2,%3}, {%4,%5,%6,%7}, {%8,%9}, {%0,%1,%2,%3};"
        : "+f"(c[0]), "+f"(c[1]), "+f"(c[2]), "+f"(c[3])
        : "r"(a[0]), "r"(a[1]), "r"(a[2]), "r"(a[3]), "r"(b0), "r"(b1));
}
__device__ __forceinline__ void mma16816h(float* c, const uint32_t* a, uint32_t b0, uint32_t b1) {
    asm volatile(
        "mma.sync.aligned.m16n8k16.row.col.f32.f16.f16.f32 "
        "{%0,%1,%2,%3}, {%4,%5,%6,%7}, {%8,%9}, {%0,%1,%2,%3};"
        : "+f"(c[0]), "+f"(c[1]), "+f"(c[2]), "+f"(c[3])
        : "r"(a[0]), "r"(a[1]), "r"(a[2]), "r"(a[3]), "r"(b0), "r"(b1));
}
#define MMSTRIDE 72
__device__ __forceinline__ uint32_t faddr(uint32_t base, int row0, int kk, int lane) {
    return base + (uint32_t)(((row0 + (lane & 15)) * MMSTRIDE + kk * 16 + ((lane >> 4) << 3)) * 2);
}
__device__ __forceinline__ void cpa16(uint32_t dst, const void* src) {
    asm volatile("cp.async.cg.shared.global [%0], [%1], 16;"
                 :: "r"(dst), "l"(__cvta_generic_to_global(src)) : "memory");
}
__device__ __forceinline__ void cpa16z(uint32_t dst, const void* src, int bytes) {
    asm volatile("cp.async.cg.shared.global [%0], [%1], 16, %2;"
                 :: "r"(dst), "l"(__cvta_generic_to_global(src)), "r"(bytes) : "memory");
}

// ======================= convert kernels =======================
__global__ void splitcvt_kernel(const float* __restrict__ x, __nv_bfloat16* __restrict__ h,
                                __nv_bfloat16* __restrict__ l, int n) {
    int i = (blockIdx.x * 256 + threadIdx.x) * 4;
    if (i >= n) return;
    split4(*(const float4*)(x + i), h, l, i);
}

__global__ void wconvT_kernel(const float* __restrict__ W, __nv_bfloat16* __restrict__ th,
                              __nv_bfloat16* __restrict__ tl, int K, int N) {
    __shared__ float sm[32][33];
    const int k0 = blockIdx.y * 32, n0 = blockIdx.x * 32;
    const int tx = threadIdx.x, ty = threadIdx.y;
    const int t = ty * 32 + tx;
#pragma unroll
    for (int i = 0; i < 4; i++)
        sm[ty + 8 * i][tx] = W[(size_t)(k0 + ty + 8 * i) * N + n0 + tx];
    __syncthreads();
#pragma unroll
    for (int e = 0; e < 2; e++) {
        int pid = e * 256 + t;
        int n = pid >> 4, kp = pid & 15;
        float v0 = sm[2 * kp][n], v1 = sm[2 * kp + 1][n];
        split2p(v0, v1, th, tl, (size_t)(n0 + n) * K + k0 + 2 * kp);
    }
}

// transpose: W [K,N] f32 -> WT fp16 [N,K]
__global__ void wconvT16_kernel(const float* __restrict__ W, __half* __restrict__ th,
                                int K, int N) {
    __shared__ float sm[32][33];
    const int k0 = blockIdx.y * 32, n0 = blockIdx.x * 32;
    const int tx = threadIdx.x, ty = threadIdx.y;
    const int t = ty * 32 + tx;
#pragma unroll
    for (int i = 0; i < 4; i++)
        sm[ty + 8 * i][tx] = W[(size_t)(k0 + ty + 8 * i) * N + n0 + tx];
    __syncthreads();
#pragma unroll
    for (int e = 0; e < 2; e++) {
        int pid = e * 256 + t;
        int n = pid >> 4, kp = pid & 15;
        *(uint32_t*)&th[(size_t)(n0 + n) * K + k0 + 2 * kp] =
            h2pack(sm[2 * kp][n], sm[2 * kp + 1][n]);
    }
}

__global__ void vconvT_kernel(const float* __restrict__ wh, __nv_bfloat16* __restrict__ th,
                              __nv_bfloat16* __restrict__ tl) {
    __shared__ float sm[32][33];
    const int t0 = blockIdx.x * 32, c0 = blockIdx.y * 32;
    const int tx = threadIdx.x, ty = threadIdx.y;
    const int t = ty * 32 + tx;
#pragma unroll
    for (int i = 0; i < 4; i++)
        sm[ty + 8 * i][tx] = wh[(size_t)(t0 + ty + 8 * i) * D3 + 2 * D + c0 + tx];
    __syncthreads();
#pragma unroll
    for (int e = 0; e < 2; e++) {
        int pid = e * 256 + t;
        int c = pid >> 4, tp = pid & 15;
        float v0 = sm[2 * tp][c], v1 = sm[2 * tp + 1][c];
        split2p(v0, v1, th, tl, (size_t)(c0 + c) * T + t0 + 2 * tp);
    }
}

// ======================= layernorm (bf16 hi/lo) =======================
__global__ void ln_kernel(const float* __restrict__ x, const float* __restrict__ g,
                          const float* __restrict__ b, __nv_bfloat16* __restrict__ oh,
                          __nv_bfloat16* __restrict__ ol) {
    const int row = blockIdx.x;
    const int t = threadIdx.x;
    const float* xr = x + (size_t)row * D;
    float4 v = *(const float4*)&xr[t * 4];
    float s = v.x + v.y + v.z + v.w;
    __shared__ float red1[8], red2[8];
    s = warpSum(s);
    if ((t & 31) == 0) red1[t >> 5] = s;
    __syncthreads();
    float tot = red1[0] + red1[1] + red1[2] + red1[3] + red1[4] + red1[5] + red1[6] + red1[7];
    const float mean = tot * (1.0f / D);
    float dx = v.x - mean, dy = v.y - mean, dz = v.z - mean, dw = v.w - mean;
    float s2 = dx * dx + dy * dy + dz * dz + dw * dw;
    s2 = warpSum(s2);
    if ((t & 31) == 0) red2[t >> 5] = s2;
    __syncthreads();
    float var = (red2[0] + red2[1] + red2[2] + red2[3] + red2[4] + red2[5] + red2[6] + red2[7]) * (1.0f / D);
    const float inv = rsqrtf(var + 1e-5f);
    float4 gg = *(const float4*)&g[t * 4];
    float4 bb = *(const float4*)&b[t * 4];
    float4 o;
    o.x = dx * inv * gg.x + bb.x;
    o.y = dy * inv * gg.y + bb.y;
    o.z = dz * inv * gg.z + bb.z;
    o.w = dw * inv * gg.w + bb.w;
    split4(o, oh, ol, (size_t)row * D + t * 4);
}

// layernorm -> fp16 single
__global__ void ln16_kernel(const float* __restrict__ x, const float* __restrict__ g,
                            const float* __restrict__ b, __half* __restrict__ o16) {
    const int row = blockIdx.x;
    const int t = threadIdx.x;
    const float* xr = x + (size_t)row * D;
    float4 v = *(const float4*)&xr[t * 4];
    float s = v.x + v.y + v.z + v.w;
    __shared__ float red1[8], red2[8];
    s = warpSum(s);
    if ((t & 31) == 0) red1[t >> 5] = s;
    __syncthreads();
    float tot = red1[0] + red1[1] + red1[2] + red1[3] + red1[4] + red1[5] + red1[6] + red1[7];
    const float mean = tot * (1.0f / D);
    float dx = v.x - mean, dy = v.y - mean, dz = v.z - mean, dw = v.w - mean;
    float s2 = dx * dx + dy * dy + dz * dz + dw * dw;
    s2 = warpSum(s2);
    if ((t & 31) == 0) red2[t >> 5] = s2;
    __syncthreads();
    float var = (red2[0] + red2[1] + red2[2] + red2[3] + red2[4] + red2[5] + red2[6] + red2[7]) * (1.0f / D);
    const float inv = rsqrtf(var + 1e-5f);
    float4 gg = *(const float4*)&g[t * 4];
    float4 bb = *(const float4*)&b[t * 4];
    uint2 o;
    o.x = h2pack(dx * inv * gg.x + bb.x, dy * inv * gg.y + bb.y);
    o.y = h2pack(dz * inv * gg.z + bb.z, dw * inv * gg.w + bb.w);
    *(uint2*)&o16[(size_t)row * D + t * 4] = o;
}

// ======================= bf16 3-term GEMM: 128x64 tile, 2 CTAs/SM ============
#define BM 128
#define BN 64
#define BK 64
#define A_ARR (128 * MMSTRIDE * 2)
#define B_ARR (64 * MMSTRIDE * 2)
#define STAGE_BYTES (2 * A_ARR + 2 * B_ARR)  // 55296
#define MM_SMEM (2 * STAGE_BYTES)            // 110592

__device__ __forceinline__ void mm_load_chunk(
    const __nv_bfloat16* __restrict__ Ah, const __nv_bfloat16* __restrict__ Al,
    const __nv_bfloat16* __restrict__ Bh, const __nv_bfloat16* __restrict__ Bl,
    int m0, int n0, int K, int t, uint32_t stage_base, int tid) {
    const size_t k0 = (size_t)t * BK;
#pragma unroll
    for (int e = 0; e < 12; e++) {
        int idx = e * 256 + tid;
        const __nv_bfloat16* src;
        uint32_t dst;
        if (idx < 2048) {
            int arr = idx >> 10;
            int row = (idx >> 3) & 127;
            int ck  = idx & 7;
            src = (arr == 0 ? Ah : Al) + (size_t)(m0 + row) * K + k0 + ck * 8;
            dst = stage_base + (uint32_t)arr * A_ARR + (uint32_t)(row * 144 + ck * 16);
        } else {
            int k = idx - 2048;
            int arr = k >> 9;
            int row = (k >> 3) & 63;
            int ck  = k & 7;
            src = (arr == 0 ? Bh : Bl) + (size_t)(n0 + row) * K + k0 + ck * 8;
            dst = stage_base + 2 * A_ARR + (uint32_t)arr * B_ARR + (uint32_t)(row * 144 + ck * 16);
        }
        cpa16(dst, src);
    }
    asm volatile("cp.async.commit_group;" ::: "memory");
}

template <int EPI>
__global__ void __launch_bounds__(256, 2) mm_kernel(
    const __nv_bfloat16* __restrict__ Ah, const __nv_bfloat16* __restrict__ Al,
    const __nv_bfloat16* __restrict__ Bh, const __nv_bfloat16* __restrict__ Bl,
    const float* __restrict__ bias, const float* __restrict__ Rm,
    float* __restrict__ Cf, __nv_bfloat16* __restrict__ Ch, __nv_bfloat16* __restrict__ Cl,
    const float* __restrict__ rwb, const float* __restrict__ rrb,
    __nv_bfloat16* __restrict__ qwh, __nv_bfloat16* __restrict__ qwl,
    __nv_bfloat16* __restrict__ qrh, __nv_bfloat16* __restrict__ qrl,
    __nv_bfloat16* __restrict__ kkh, __nv_bfloat16* __restrict__ kkl,
    int M, int N, int K) {
    extern __shared__ char smem[];
    const uint32_t sbase = smem_u32(smem);
    const int tid = threadIdx.x;
    const int wid = tid >> 5, lane = tid & 31;
    const int m0 = blockIdx.y * BM, n0 = blockIdx.x * BN;
    const int mrow = (wid & 3) * 32;
    const int nrow = (wid >> 2) * 32;

    float c[2][4][4] = {};
    const int nch = K / BK;

    mm_load_chunk(Ah, Al, Bh, Bl, m0, n0, K, 0, sbase, tid);

    for (int t = 0; t < nch; t++) {
        asm volatile("cp.async.wait_group 0;" ::: "memory");
        __syncthreads();
        if (t + 1 < nch)
            mm_load_chunk(Ah, Al, Bh, Bl, m0, n0, K, t + 1, sbase + ((t + 1) & 1) * STAGE_BYTES, tid);
        const uint32_t sb = sbase + (t & 1) * STAGE_BYTES;
        const uint32_t vb = sb + 2 * A_ARR;
#pragma unroll
        for (int kk = 0; kk < 4; kk++) {
            uint32_t ah[2][4], al[2][4], bh[2][4], bl[2][4];
            ldsm_x4(ah[0], faddr(sb,          mrow,      kk, lane));
            ldsm_x4(ah[1], faddr(sb,          mrow + 16, kk, lane));
            ldsm_x4(al[0], faddr(sb + A_ARR,  mrow,      kk, lane));
            ldsm_x4(al[1], faddr(sb + A_ARR,  mrow + 16, kk, lane));
            ldsm_x4(bh[0], faddr(vb,          nrow,      kk, lane));
            ldsm_x4(bh[1], faddr(vb,          nrow + 16, kk, lane));
            ldsm_x4(bl[0], faddr(vb + B_ARR,  nrow,      kk, lane));
            ldsm_x4(bl[1], faddr(vb + B_ARR,  nrow + 16, kk, lane));
#pragma unroll
            for (int mi = 0; mi < 2; mi++)
#pragma unroll
                for (int nb = 0; nb < 4; nb++) {
                    const int nf = nb >> 1, o = nb & 1;
                    mma16816(c[mi][nb], ah[mi], bh[nf][o], bh[nf][2 + o]);
                    mma16816(c[mi][nb], ah[mi], bl[nf][o], bl[nf][2 + o]);
                    mma16816(c[mi][nb], al[mi], bh[nf][o], bh[nf][2 + o]);
                }
        }
    }

    const int tq = lane >> 2, tr = lane & 3;
#pragma unroll
    for (int mi = 0; mi < 2; mi++)
#pragma unroll
        for (int nb = 0; nb < 4; nb++)
#pragma unroll
            for (int hh = 0; hh < 2; hh++) {
                int gr = m0 + mrow + mi * 16 + tq + hh * 8;
                int gc = n0 + nrow + nb * 8 + tr * 2;
                float v0 = c[mi][nb][hh * 2 + 0];
                float v1 = c[mi][nb][hh * 2 + 1];
                if (EPI & 16) {
                    if (gc < D) {
                        size_t o = (size_t)gr * D + gc;
                        split2p(v0 + rwb[gc], v1 + rwb[gc + 1], qwh, qwl, o);
                        split2p(v0 + rrb[gc], v1 + rrb[gc + 1], qrh, qrl, o);
                    } else if (gc < 2 * D) {
                        split2p(v0, v1, kkh, kkl, (size_t)gr * D + gc - D);
                    } else {
                        float2 o2; o2.x = v0; o2.y = v1;
                        *(float2*)&Cf[(size_t)gr * N + gc] = o2;
                    }
                    continue;
                }
                if (EPI & 1) { v0 += bias[gc]; v1 += bias[gc + 1]; }
                if (EPI & 2) { v0 = fmaxf(v0, 0.f); v1 = fmaxf(v1, 0.f); }
                if (EPI & 4) {
                    float2 r = *(const float2*)&Rm[(size_t)gr * N + gc];
                    v0 += r.x; v1 += r.y;
                }
                if (EPI & 8) {
                    split2p(v0, v1, Ch, Cl, (size_t)gr * N + gc);
                } else {
                    float2 o; o.x = v0; o.y = v1;
                    *(float2*)&Cf[(size_t)gr * N + gc] = o;
                }
            }
}

// ======================= fp16 1-term GEMM: 128x128 tile, 2 CTAs/SM ============
// EPI bits: 1=bias, 2=relu, 4=residual, 8=fp16-out
#define H_ARR (128 * MMSTRIDE * 2)          // 18432
#define H_STAGE (2 * H_ARR)                 // 36864
#define MMH_SMEM (2 * H_STAGE)              // 73728

__device__ __forceinline__ void mmh_load_chunk(
    const __half* __restrict__ A, const __half* __restrict__ B,
    int m0, int n0, int K, int t, uint32_t stage_base, int tid) {
    const size_t k0 = (size_t)t * 64;
#pragma unroll
    for (int e = 0; e < 8; e++) {
        int idx = e * 256 + tid;          // 0..2047
        int arr = idx >> 10;              // 0: A, 1: B
        int row = (idx >> 3) & 127;
        int ck  = idx & 7;
        const __half* src = (arr == 0 ? A + (size_t)(m0 + row) * K
                                      : B + (size_t)(n0 + row) * K) + k0 + ck * 8;
        cpa16(stage_base + (uint32_t)arr * H_ARR + (uint32_t)(row * 144 + ck * 16), src);
    }
    asm volatile("cp.async.commit_group;" ::: "memory");
}

template <int EPI>
__global__ void __launch_bounds__(256, 2) mmh_kernel(
    const __half* __restrict__ A, const __half* __restrict__ B,
    const float* __restrict__ bias, const float* __restrict__ Rm,
    float* __restrict__ Cf, __half* __restrict__ C16,
    int M, int N, int K) {
    extern __shared__ char smem[];
    const uint32_t sbase = smem_u32(smem);
    const int tid = threadIdx.x;
    const int wid = tid >> 5, lane = tid & 31;
    const int m0 = blockIdx.y * 128, n0 = blockIdx.x * 128;
    const int mrow = (wid & 3) * 32;      // 4x2 warp grid, warp tile 32x64
    const int nrow = (wid >> 2) * 64;

    float c[2][8][4] = {};
    const int nch = K / 64;

    mmh_load_chunk(A, B, m0, n0, K, 0, sbase, tid);

    for (int t = 0; t < nch; t++) {
        asm volatile("cp.async.wait_group 0;" ::: "memory");
        __syncthreads();
        if (t + 1 < nch)
            mmh_load_chunk(A, B, m0, n0, K, t + 1, sbase + ((t + 1) & 1) * H_STAGE, tid);
        const uint32_t sb = sbase + (t & 1) * H_STAGE;
        const uint32_t vb = sb + H_ARR;
#pragma unroll
        for (int kk = 0; kk < 4; kk++) {
            uint32_t a[2][4], b[4][4];
            ldsm_x4(a[0], faddr(sb, mrow,      kk, lane));
            ldsm_x4(a[1], faddr(sb, mrow + 16, kk, lane));
#pragma unroll
            for (int nf = 0; nf < 4; nf++)
                ldsm_x4(b[nf], faddr(vb, nrow + nf * 16, kk, lane));
#pragma unroll
            for (int mi = 0; mi < 2; mi++)
#pragma unroll
                for (int nb = 0; nb < 8; nb++) {
                    const int nf = nb >> 1, o = nb & 1;
                    mma16816h(c[mi][nb], a[mi], b[nf][o], b[nf][2 + o]);
                }
        }
    }

    const int tq = lane >> 2, tr = lane & 3;
#pragma unroll
    for (int mi = 0; mi < 2; mi++)
#pragma unroll
        for (int nb = 0; nb < 8; nb++)
#pragma unroll
            for (int hh = 0; hh < 2; hh++) {
                int gr = m0 + mrow + mi * 16 + tq + hh * 8;
                int gc = n0 + nrow + nb * 8 + tr * 2;
                float v0 = c[mi][nb][hh * 2 + 0];
                float v1 = c[mi][nb][hh * 2 + 1];
                if (EPI & 1) { v0 += bias[gc]; v1 += bias[gc + 1]; }
                if (EPI & 2) { v0 = fmaxf(v0, 0.f); v1 = fmaxf(v1, 0.f); }
                if (EPI & 4) {
                    float2 r = *(const float2*)&Rm[(size_t)gr * N + gc];
                    v0 += r.x; v1 += r.y;
                }
                if (EPI & 8) {
                    *(uint32_t*)&C16[(size_t)gr * N + gc] = h2pack(v0, v1);
                } else {
                    float2 o; o.x = v0; o.y = v1;
                    *(float2*)&Cf[(size_t)gr * N + gc] = o;
                }
            }
}

// ======================= HMMA attention scores =======================
#define SA 18432
#define SC_RB   (6 * SA)
#define SC_SMEM (6 * SA + 2 * 36864)  // 184320

__global__ void __launch_bounds__(256, 1) scores_mma_kernel(
    const __nv_bfloat16* __restrict__ qwh, const __nv_bfloat16* __restrict__ qwl,
    const __nv_bfloat16* __restrict__ qrh, const __nv_bfloat16* __restrict__ qrl,
    const __nv_bfloat16* __restrict__ kh,  const __nv_bfloat16* __restrict__ kl,
    const __nv_bfloat16* __restrict__ rkh, const __nv_bfloat16* __restrict__ rkl,
    float* __restrict__ sc) {
    const int h = blockIdx.z;
    const int n = blockIdx.x;
    float rf = (sqrtf(8.f * n + 1.f) - 1.f) * 0.5f;
    int iT = (int)rf;
    if ((iT + 1) * (iT + 2) / 2 <= n) iT++;
    if (iT * (iT + 1) / 2 > n) iT--;
    const int jT = n - iT * (iT + 1) / 2;
    const int i0 = iT * 128, j0 = jT * 128;
    extern __shared__ char smem[];
    const uint32_t sb = smem_u32(smem);
    const int tid = threadIdx.x;
    const int wid = tid >> 5, lane = tid & 31;
    const int mrow = (wid & 3) * 32;
    const int nrow = (wid >> 2) * 64;
    const int pbase = T - 1 - i0 + j0 - 127;
    float* bdbuf = (float*)(smem);

#pragma unroll
    for (int e = 0; e < 24; e++) {
        int idx = e * 256 + tid;
        int arr = idx >> 10;
        int row = (idx >> 3) & 127;
        int ck  = idx & 7;
        const __nv_bfloat16* src;
        int grow = ((arr == 2 || arr == 3) ? j0 : i0) + row;
        if (arr == 0) src = qwh; else if (arr == 1) src = qwl;
        else if (arr == 2) src = kh; else if (arr == 3) src = kl;
        else if (arr == 4) src = qrh; else src = qrl;
        cpa16(sb + (uint32_t)arr * SA + (uint32_t)(row * 144 + ck * 16),
              src + (size_t)grow * D + h * DH + ck * 8);
    }
    asm volatile("cp.async.commit_group;" ::: "memory");
#pragma unroll
    for (int e = 0; e < 16; e++) {
        int idx = e * 256 + tid;
        int arr = idx >> 11;
        int row = (idx >> 3) & 255;
        int ck  = idx & 7;
        int p = pbase + row;
        bool valid = (p >= 0 && p < T);
        size_t off = valid ? ((size_t)p * D + h * DH + ck * 8) : 0;
        cpa16z(sb + SC_RB + (uint32_t)arr * 36864u + (uint32_t)(row * 144 + ck * 16),
               (arr == 0 ? rkh : rkl) + off, valid ? 16 : 0);
    }
    asm volatile("cp.async.commit_group;" ::: "memory");
    asm volatile("cp.async.wait_group 1;" ::: "memory");
    __syncthreads();

    const uint32_t bqwh = sb, bqwl = sb + SA, bkh = sb + 2 * SA, bkl = sb + 3 * SA;
    const uint32_t bqrh = sb + 4 * SA, bqrl = sb + 5 * SA;
    const uint32_t brh = sb + SC_RB, brl = sb + SC_RB + 36864;

    float acc[2][8][4] = {};
#pragma unroll
    for (int kk = 0; kk < 4; kk++) {
        uint32_t ah[2][4], al[2][4], bh[4][4], bl[4][4];
        ldsm_x4(ah[0], faddr(bqwh, mrow,      kk, lane));
        ldsm_x4(ah[1], faddr(bqwh, mrow + 16, kk, lane));
        ldsm_x4(al[0], faddr(bqwl, mrow,      kk, lane));
        ldsm_x4(al[1], faddr(bqwl, mrow + 16, kk, lane));
#pragma unroll
        for (int nf = 0; nf < 4; nf++) ldsm_x4(bh[nf], faddr(bkh, nrow + nf * 16, kk, lane));
#pragma unroll
        for (int nf = 0; nf < 4; nf++) ldsm_x4(bl[nf], faddr(bkl, nrow + nf * 16, kk, lane));
#pragma unroll
        for (int mi = 0; mi < 2; mi++)
#pragma unroll
            for (int nb = 0; nb < 8; nb++) {
                const int nf = nb >> 1, o = nb & 1;
                mma16816(acc[mi][nb], ah[mi], bh[nf][o], bh[nf][2 + o]);
                mma16816(acc[mi][nb], ah[mi], bl[nf][o], bl[nf][2 + o]);
                mma16816(acc[mi][nb], al[mi], bh[nf][o], bh[nf][2 + o]);
            }
    }
    asm volatile("cp.async.wait_group 0;" ::: "memory");
    __syncthreads();

    const int tq = lane >> 2, tr = lane & 3;
#pragma unroll 1
    for (int half = 0; half < 2; half++) {
        float c2[2][8][4] = {};
#pragma unroll
        for (int kk = 0; kk < 4; kk++) {
            uint32_t ah[2][4], al[2][4], bh[4][4], bl[4][4];
            ldsm_x4(ah[0], faddr(bqrh, mrow,      kk, lane));
            ldsm_x4(ah[1], faddr(bqrh, mrow + 16, kk, lane));
            ldsm_x4(al[0], faddr(bqrl, mrow,      kk, lane));
            ldsm_x4(al[1], faddr(bqrl, mrow + 16, kk, lane));
#pragma unroll
            for (int nf = 0; nf < 4; nf++)
                ldsm_x4(bh[nf], faddr(brh, half * 128 + nrow + nf * 16, kk, lane));
#pragma unroll
            for (int nf = 0; nf < 4; nf++)
                ldsm_x4(bl[nf], faddr(brl, half * 128 + nrow + nf * 16, kk, lane));
#pragma unroll
            for (int mi = 0; mi < 2; mi++)
#pragma unroll
                for (int nb = 0; nb < 8; nb++) {
                    const int nf = nb >> 1, o = nb & 1;
                    mma16816(c2[mi][nb], ah[mi], bh[nf][o], bh[nf][2 + o]);
                    mma16816(c2[mi][nb], ah[mi], bl[nf][o], bl[nf][2 + o]);
                    mma16816(c2[mi][nb], al[mi], bh[nf][o], bh[nf][2 + o]);
                }
        }
        __syncthreads();
#pragma unroll
        for (int mi = 0; mi < 2; mi++)
#pragma unroll
            for (int nb = 0; nb < 8; nb++)
#pragma unroll
                for (int hh = 0; hh < 2; hh++) {
                    int di = mrow + mi * 16 + tq + hh * 8;
                    int dj = nrow + nb * 8 + tr * 2;
                    bdbuf[di * 130 + dj]     = c2[mi][nb][hh * 2 + 0];
                    bdbuf[di * 130 + dj + 1] = c2[mi][nb][hh * 2 + 1];
                }
        __syncthreads();
#pragma unroll
        for (int mi = 0; mi < 2; mi++)
#pragma unroll
            for (int nb = 0; nb < 8; nb++)
#pragma unroll
                for (int hh = 0; hh < 2; hh++) {
                    int di = mrow + mi * 16 + tq + hh * 8;
                    int dj = nrow + nb * 8 + tr * 2;
#pragma unroll
                    for (int cc = 0; cc < 2; cc++) {
                        int pl = 127 + (dj + cc) - di;
                        if ((pl >> 7) == half)
                            acc[mi][nb][hh * 2 + cc] += bdbuf[di * 130 + (pl & 127)];
                    }
                }
        __syncthreads();
    }

    const float scale = 0.125f;
#pragma unroll
    for (int mi = 0; mi < 2; mi++)
#pragma unroll
        for (int nb = 0; nb < 8; nb++)
#pragma unroll
            for (int hh = 0; hh < 2; hh++) {
                int gi = i0 + mrow + mi * 16 + tq + hh * 8;
                int gj = j0 + nrow + nb * 8 + tr * 2;
                float2 o;
                o.x = acc[mi][nb][hh * 2 + 0] * scale;
                o.y = acc[mi][nb][hh * 2 + 1] * scale;
                *(float2*)&sc[((size_t)h * T + gi) * T + gj] = o;
            }
}

// ======================= causal softmax -> bf16 hi/lo probs (pad to 128) =====
__global__ void softmax_kernel(const float* __restrict__ sc, __nv_bfloat16* __restrict__ ph,
                               __nv_bfloat16* __restrict__ pl) {
    const int i = blockIdx.x;
    const int h = blockIdx.y;
    const size_t roff = ((size_t)h * T + i) * T;
    const float* row = sc + roff;
    const int t = threadIdx.x;
    const int n = i + 1;
    const int nup = (i & ~127) + 128;
    float4 v[2];
    float mx = -3.4e38f;
#pragma unroll
    for (int p = 0; p < 2; p++) {
        int j = (p * 256 + t) * 4;
        if (j < nup) {
            float4 w = *(const float4*)(row + j);
            w.x = (j + 0 < n) ? w.x : -3.4e38f;
            w.y = (j + 1 < n) ? w.y : -3.4e38f;
            w.z = (j + 2 < n) ? w.z : -3.4e38f;
            w.w = (j + 3 < n) ? w.w : -3.4e38f;
            v[p] = w;
            mx = fmaxf(mx, fmaxf(fmaxf(w.x, w.y), fmaxf(w.z, w.w)));
        } else {
            v[p].x = v[p].y = v[p].z = v[p].w = -3.4e38f;
        }
    }
    __shared__ float red1[8], red2[8];
    mx = warpMax(mx);
    if ((t & 31) == 0) red1[t >> 5] = mx;
    __syncthreads();
    mx = fmaxf(fmaxf(fmaxf(red1[0], red1[1]), fmaxf(red1[2], red1[3])),
               fmaxf(fmaxf(red1[4], red1[5]), fmaxf(red1[6], red1[7])));
    float s = 0.f;
#pragma unroll
    for (int p = 0; p < 2; p++) {
        float e0 = (v[p].x > -3.0e38f) ? __expf(v[p].x - mx) : 0.f;
        float e1 = (v[p].y > -3.0e38f) ? __expf(v[p].y - mx) : 0.f;
        float e2 = (v[p].z > -3.0e38f) ? __expf(v[p].z - mx) : 0.f;
        float e3 = (v[p].w > -3.0e38f) ? __expf(v[p].w - mx) : 0.f;
        v[p].x = e0; v[p].y = e1; v[p].z = e2; v[p].w = e3;
        s += e0 + e1 + e2 + e3;
    }
    s = warpSum(s);
    if ((t & 31) == 0) red2[t >> 5] = s;
    __syncthreads();
    float tot = red2[0] + red2[1] + red2[2] + red2[3] + red2[4] + red2[5] + red2[6] + red2[7];
    float inv = 1.0f / tot;
#pragma unroll
    for (int p = 0; p < 2; p++) {
        int j = (p * 256 + t) * 4;
        if (j < nup) {
            float p0 = v[p].x * inv, p1 = v[p].y * inv, p2 = v[p].z * inv, p3 = v[p].w * inv;
            float h0 = __bfloat162float(__float2bfloat16(p0));
            float h1 = __bfloat162float(__float2bfloat16(p1));
            float h2 = __bfloat162float(__float2bfloat16(p2));
            float h3 = __bfloat162float(__float2bfloat16(p3));
            uint2 hu, lu;
            hu.x = bf2pack(p0, p1); hu.y = bf2pack(p2, p3);
            lu.x = bf2pack(p0 - h0, p1 - h1); lu.y = bf2pack(p2 - h2, p3 - h3);
            *(uint2*)&ph[roff + j] = hu;
            *(uint2*)&pl[roff + j] = lu;
        }
    }
}

// ======================= probs layout: hi/lo [h][i][j] -> f32 [i][j][h] ========
__global__ void probs_out_kernel(const __nv_bfloat16* __restrict__ ph,
                                 const __nv_bfloat16* __restrict__ pl,
                                 float* __restrict__ out) {
    const int i = blockIdx.y;
    const int t = threadIdx.x;
    const int nup = (i & ~63) + 64;
    __shared__ float sm[16][66];
#pragma unroll 1
    for (int s = 0; s < 4; s++) {
        const int j0 = (blockIdx.x * 4 + s) * 64;
        float* dst = out + ((size_t)i * T + j0) * H;
        if (j0 < nup) {
#pragma unroll
            for (int e = 0; e < 2; e++) {
                int idx = e * 256 + t;
                int hh = idx >> 5, jp = idx & 31;
                size_t o = ((size_t)hh * T + i) * T + j0 + jp * 2;
                __nv_bfloat162 a = *(const __nv_bfloat162*)&ph[o];
                __nv_bfloat162 b = *(const __nv_bfloat162*)&pl[o];
                sm[hh][jp * 2]     = __bfloat162float(a.x) + __bfloat162float(b.x);
                sm[hh][jp * 2 + 1] = __bfloat162float(a.y) + __bfloat162float(b.y);
            }
            __syncthreads();
            int base = t * 4;
            float4 o4;
            o4.x = sm[(base + 0) & 15][(base + 0) >> 4];
            o4.y = sm[(base + 1) & 15][(base + 1) >> 4];
            o4.z = sm[(base + 2) & 15][(base + 2) >> 4];
            o4.w = sm[(base + 3) & 15][(base + 3) >> 4];
            *(float4*)&dst[base] = o4;
            __syncthreads();
        } else {
            float4 z; z.x = z.y = z.z = z.w = 0.f;
            *(float4*)&dst[t * 4] = z;
        }
    }
}

// ======================= HMMA PV (128-row tiles, 2 CTA/SM) ===================
#define PV_PARR 18432
#define PV_VARR 9216
#define PV_STAGE (2 * PV_PARR + 2 * PV_VARR)
#define PV_SMEM (2 * PV_STAGE)

__device__ __forceinline__ void pv_load_chunk(
    const __nv_bfloat16* __restrict__ Ph, const __nv_bfloat16* __restrict__ Pl,
    const __nv_bfloat16* __restrict__ Vh, const __nv_bfloat16* __restrict__ Vl,
    int h, int i0, int t, uint32_t stage_base, int tid) {
    const size_t j0 = (size_t)t * 64;
#pragma unroll
    for (int e = 0; e < 12; e++) {
        int idx = e * 256 + tid;
        const __nv_bfloat16* src;
        uint32_t dst;
        if (idx < 2048) {
            int arr = idx >> 10;
            int row = (idx >> 3) & 127;
            int ck  = idx & 7;
            src = (arr == 0 ? Ph : Pl) + ((size_t)h * T + i0 + row) * T + j0 + ck * 8;
            dst = stage_base + (uint32_t)arr * PV_PARR + (uint32_t)(row * 144 + ck * 16);
        } else {
            int k = idx - 2048;
            int arr = k >> 9;
            int row = (k >> 3) & 63;
            int ck  = k & 7;
            src = (arr == 0 ? Vh : Vl) + (size_t)(h * DH + row) * T + j0 + ck * 8;
            dst = stage_base + 2 * PV_PARR + (uint32_t)arr * PV_VARR + (uint32_t)(row * 144 + ck * 16);
        }
        cpa16(dst, src);
    }
    asm volatile("cp.async.commit_group;" ::: "memory");
}

__global__ void __launch_bounds__(256, 2) pv_mma_kernel(
    const __nv_bfloat16* __restrict__ Ph, const __nv_bfloat16* __restrict__ Pl,
    const __nv_bfloat16* __restrict__ Vh, const __nv_bfloat16* __restrict__ Vl,
    __nv_bfloat16* __restrict__ avh, __nv_bfloat16* __restrict__ avl) {
    extern __shared__ char smem[];
    const uint32_t sbase = smem_u32(smem);
    const int h = blockIdx.y;
    const int i0 = (gridDim.x - 1 - blockIdx.x) * 128;
    const int tid = threadIdx.x;
    const int wid = tid >> 5, lane = tid & 31;
    const int mrow = (wid & 3) * 32;
    const int nrow = (wid >> 2) * 32;

    float c[2][4][4] = {};
    const int nch = i0 / 64 + 2;

    pv_load_chunk(Ph, Pl, Vh, Vl, h, i0, 0, sbase, tid);

    for (int t = 0; t < nch; t++) {
        asm volatile("cp.async.wait_group 0;" ::: "memory");
        __syncthreads();
        if (t + 1 < nch)
            pv_load_chunk(Ph, Pl, Vh, Vl, h, i0, t + 1, sbase + ((t + 1) & 1) * PV_STAGE, tid);
        const uint32_t sb = sbase + (t & 1) * PV_STAGE;
        const uint32_t vb = sb + 2 * PV_PARR;
#pragma unroll
        for (int kk = 0; kk < 4; kk++) {
            uint32_t ah[2][4], al[2][4], bh[2][4], bl[2][4];
            ldsm_x4(ah[0], faddr(sb,           mrow,      kk, lane));
            ldsm_x4(ah[1], faddr(sb,           mrow + 16, kk, lane));
            ldsm_x4(al[0], faddr(sb + PV_PARR, mrow,      kk, lane));
            ldsm_x4(al[1], faddr(sb + PV_PARR, mrow + 16, kk, lane));
            ldsm_x4(bh[0], faddr(vb,           nrow,      kk, lane));
            ldsm_x4(bh[1], faddr(vb,           nrow + 16, kk, lane));
            ldsm_x4(bl[0], faddr(vb + PV_VARR, nrow,      kk, lane));
            ldsm_x4(bl[1], faddr(vb + PV_VARR, nrow + 16, kk, lane));
#pragma unroll
            for (int mi = 0; mi < 2; mi++)
#pragma unroll
                for (int nb = 0; nb < 4; nb++) {
                    const int nf = nb >> 1, o = nb & 1;
                    mma16816(c[mi][nb], ah[mi], bh[nf][o], bh[nf][2 + o]);
                    mma16816(c[mi][nb], ah[mi], bl[nf][o], bl[nf][2 + o]);
                    mma16816(c[mi][nb], al[mi], bh[nf][o], bh[nf][2 + o]);
                }
        }
    }

    const int tq = lane >> 2, tr = lane & 3;
#pragma unroll
    for (int mi = 0; mi < 2; mi++)
#pragma unroll
        for (int nb = 0; nb < 4; nb++)
#pragma unroll
            for (int hh = 0; hh < 2; hh++) {
                int gi = i0 + mrow + mi * 16 + tq + hh * 8;
                int gd = nrow + nb * 8 + tr * 2;
                size_t o = (size_t)gi * D + h * DH + gd;
                split2p(c[mi][nb][hh * 2 + 0], c[mi][nb][hh * 2 + 1], avh, avl, o);
            }
}

// ======================= host launch =======================
extern "C" void kernel_launch(void* const* d_in, const int* in_sizes, int n_in,
                              void* d_out, int out_size) {
    const float* input = (const float*)d_in[0];
    const float* pos   = (const float*)d_in[1];
    const float* rwb   = (const float*)d_in[2];
    const float* rrb   = (const float*)d_in[3];
    const float* ln1g  = (const float*)d_in[5];
    const float* ln1b  = (const float*)d_in[6];
    const float* qkvw  = (const float*)d_in[7];
    const float* rw    = (const float*)d_in[8];
    const float* ow    = (const float*)d_in[9];
    const float* ln2g  = (const float*)d_in[10];
    const float* ln2b  = (const float*)d_in[11];
    const float* ffw1  = (const float*)d_in[12];
    const float* ffb1  = (const float*)d_in[13];
    const float* ffw2  = (const float*)d_in[14];
    const float* ffb2  = (const float*)d_in[15];
    float* out = (float*)d_out;

    float *wheads, *scores, *x;
    cudaGetSymbolAddress((void**)&wheads, g_wheads);
    cudaGetSymbolAddress((void**)&scores, g_scores);
    cudaGetSymbolAddress((void**)&x,      g_x);
    __nv_bfloat16 *qin_h, *qin_l, *pos_h, *pos_l, *av_h, *av_l;
    cudaGetSymbolAddress((void**)&qin_h, g_qin_h); cudaGetSymbolAddress((void**)&qin_l, g_qin_l);
    cudaGetSymbolAddress((void**)&pos_h, g_pos_h); cudaGetSymbolAddress((void**)&pos_l, g_pos_l);
    cudaGetSymbolAddress((void**)&av_h,  g_av_h);  cudaGetSymbolAddress((void**)&av_l,  g_av_l);
    __nv_bfloat16 *qkvwT_h, *qkvwT_l, *rwT_h, *rwT_l, *owT_h, *owT_l;
    cudaGetSymbolAddress((void**)&qkvwT_h, g_qkvwT_h); cudaGetSymbolAddress((void**)&qkvwT_l, g_qkvwT_l);
    cudaGetSymbolAddress((void**)&rwT_h,   g_rwT_h);   cudaGetSymbolAddress((void**)&rwT_l,   g_rwT_l);
    cudaGetSymbolAddress((void**)&owT_h,   g_owT_h);   cudaGetSymbolAddress((void**)&owT_l,   g_owT_l);
    __nv_bfloat16 *ph, *pl, *vt_h, *vt_l;
    cudaGetSymbolAddress((void**)&ph, g_ph);     cudaGetSymbolAddress((void**)&pl, g_pl);
    cudaGetSymbolAddress((void**)&vt_h, g_vt_h); cudaGetSymbolAddress((void**)&vt_l, g_vt_l);
    __nv_bfloat16 *qw_h, *qw_l, *qr_h, *qr_l, *k_h, *k_l, *rk_h, *rk_l;
    cudaGetSymbolAddress((void**)&qw_h, g_qw_h); cudaGetSymbolAddress((void**)&qw_l, g_qw_l);
    cudaGetSymbolAddress((void**)&qr_h, g_qr_h); cudaGetSymbolAddress((void**)&qr_l, g_qr_l);
    cudaGetSymbolAddress((void**)&k_h,  g_k_h);  cudaGetSymbolAddress((void**)&k_l,  g_k_l);
    cudaGetSymbolAddress((void**)&rk_h, g_rk_h); cudaGetSymbolAddress((void**)&rk_l, g_rk_l);
    __half *y16, *ff16, *w1T16, *w2T16;
    cudaGetSymbolAddress((void**)&y16,   g_y16);
    cudaGetSymbolAddress((void**)&ff16,  g_ff16);
    cudaGetSymbolAddress((void**)&w1T16, g_w1T16);
    cudaGetSymbolAddress((void**)&w2T16, g_w2T16);

    cudaFuncSetAttribute((const void*)mm_kernel<16>, cudaFuncAttributeMaxDynamicSharedMemorySize, MM_SMEM);
    cudaFuncSetAttribute((const void*)mm_kernel<4>,  cudaFuncAttributeMaxDynamicSharedMemorySize, MM_SMEM);
    cudaFuncSetAttribute((const void*)mm_kernel<8>,  cudaFuncAttributeMaxDynamicSharedMemorySize, MM_SMEM);
    cudaFuncSetAttribute((const void*)mmh_kernel<11>, cudaFuncAttributeMaxDynamicSharedMemorySize, MMH_SMEM);
    cudaFuncSetAttribute((const void*)mmh_kernel<5>,  cudaFuncAttributeMaxDynamicSharedMemorySize, MMH_SMEM);
    cudaFuncSetAttribute((const void*)scores_mma_kernel, cudaFuncAttributeMaxDynamicSharedMemorySize, SC_SMEM);
    cudaFuncSetAttribute((const void*)pv_mma_kernel,  cudaFuncAttributeMaxDynamicSharedMemorySize, PV_SMEM);

    const dim3 wthr(32, 8);
    const bool probs_fit =
        (long long)out_size >= (long long)T * D + (long long)H * T * T;

    ln_kernel<<<T, 256>>>(input, ln1g, ln1b, qin_h, qin_l);                          // 0
    wconvT_kernel<<<dim3(D3 / 32, D / 32), wthr>>>(qkvw, qkvwT_h, qkvwT_l, D, D3);   // 1
    splitcvt_kernel<<<(T * D) / 1024, 256>>>(pos, pos_h, pos_l, T * D);              // 2
    mm_kernel<16><<<dim3(D3 / 64, T / 128), 256, MM_SMEM>>>(                          // 3 (profiled)
        qin_h, qin_l, qkvwT_h, qkvwT_l, nullptr, nullptr, wheads, nullptr, nullptr,
        rwb, rrb, qw_h, qw_l, qr_h, qr_l, k_h, k_l, T, D3, D);
    wconvT_kernel<<<dim3(D / 32,  D / 32), wthr>>>(rw,   rwT_h,   rwT_l,   D, D);    // 4
    vconvT_kernel<<<dim3(T / 32, D / 32), wthr>>>(wheads, vt_h, vt_l);               // 5
    mm_kernel<8><<<dim3(D / 64, T / 128), 256, MM_SMEM>>>(                            // 6
        pos_h, pos_l, rwT_h, rwT_l, nullptr, nullptr, nullptr, rk_h, rk_l,
        nullptr, nullptr, nullptr, nullptr, nullptr, nullptr, nullptr, nullptr, T, D, D);
    wconvT_kernel<<<dim3(D / 32,  D / 32), wthr>>>(ow,   owT_h,   owT_l,   D, D);    // 7
    scores_mma_kernel<<<dim3(136, 1, H), 256, SC_SMEM>>>(
        qw_h, qw_l, qr_h, qr_l, k_h, k_l, rk_h, rk_l, scores);
    softmax_kernel<<<dim3(T, H), 256>>>(scores, ph, pl);
    if (probs_fit) {
        probs_out_kernel<<<dim3(T / 256, T), 256>>>(ph, pl, out + (size_t)T * D);
    }
    pv_mma_kernel<<<dim3(T / 128, H), 256, PV_SMEM>>>(ph, pl, vt_h, vt_l, av_h, av_l);
    mm_kernel<4><<<dim3(D / 64, T / 128), 256, MM_SMEM>>>(
        av_h, av_l, owT_h, owT_l, nullptr, input, x, nullptr, nullptr,
        nullptr, nullptr, nullptr, nullptr, nullptr, nullptr, nullptr, nullptr, T, D, D);
    // FFN: fp16 single-term path
    ln16_kernel<<<T, 256>>>(x, ln2g, ln2b, y16);
    wconvT16_kernel<<<dim3(DFF / 32, D / 32), wthr>>>(ffw1, w1T16, D, DFF);
    wconvT16_kernel<<<dim3(D / 32, DFF / 32), wthr>>>(ffw2, w2T16, DFF, D);
    mmh_kernel<11><<<dim3(DFF / 128, T / 128), 256, MMH_SMEM>>>(
        y16, w1T16, ffb1, nullptr, nullptr, ff16, T, DFF, D);
    mmh_kernel<5><<<dim3(D / 128, T / 128), 256, MMH_SMEM>>>(
        ff16, w2T16, ffb2, x, out, nullptr, T, D, DFF);
}

// round 13
// speedup vs baseline: 1.4693x; 1.1312x over previous
#include <cuda_runtime.h>
#include <cuda_bf16.h>
#include <cuda_fp16.h>
#include <math.h>
#include <stdint.h>

#define T 2048
#define D 1024
#define H 16
#define DH 64
#define DFF 4096
#define D3 3072

// ======================= scratch (device globals) =======================
__device__ float g_wheads[(size_t)T * D3];
__device__ float g_scores[(size_t)H * T * T];
__device__ float g_x[(size_t)T * D];

__device__ __nv_bfloat16 g_qin_h[(size_t)T * D],  g_qin_l[(size_t)T * D];
__device__ __nv_bfloat16 g_pos_h[(size_t)T * D],  g_pos_l[(size_t)T * D];

__device__ __nv_bfloat16 g_qkvwT_h[(size_t)D3 * D],  g_qkvwT_l[(size_t)D3 * D];
__device__ __nv_bfloat16 g_rwT_h[(size_t)D * D],     g_rwT_l[(size_t)D * D];

__device__ __nv_bfloat16 g_qw_h[(size_t)T * D], g_qw_l[(size_t)T * D];
__device__ __nv_bfloat16 g_qr_h[(size_t)T * D], g_qr_l[(size_t)T * D];
__device__ __nv_bfloat16 g_k_h[(size_t)T * D],  g_k_l[(size_t)T * D];
__device__ __nv_bfloat16 g_rk_h[(size_t)T * D], g_rk_l[(size_t)T * D];

// fp16 paths
__device__ __half g_p16[(size_t)H * T * T];     // probs fp16
__device__ __half g_vt16[(size_t)D * T];        // V^T fp16 [h*64+d][t]
__device__ __half g_av16[(size_t)T * D];        // attn_vec fp16
__device__ __half g_owT16[(size_t)D * D];       // o_w^T fp16
__device__ __half g_y16[(size_t)T * D];
__device__ __half g_ff16[(size_t)T * DFF];
__device__ __half g_w1T16[(size_t)DFF * D];
__device__ __half g_w2T16[(size_t)D * DFF];

// ======================= small utils =======================
__device__ __forceinline__ float warpSum(float v) {
#pragma unroll
    for (int o = 16; o > 0; o >>= 1) v += __shfl_xor_sync(0xffffffffu, v, o);
    return v;
}
__device__ __forceinline__ float warpMax(float v) {
#pragma unroll
    for (int o = 16; o > 0; o >>= 1) v = fmaxf(v, __shfl_xor_sync(0xffffffffu, v, o));
    return v;
}
__device__ __forceinline__ uint32_t bf2pack(float a, float b) {
    __nv_bfloat162 t = __floats2bfloat162_rn(a, b);
    return *reinterpret_cast<uint32_t*>(&t);
}
__device__ __forceinline__ uint32_t h2pack(float a, float b) {
    __half2 t = __floats2half2_rn(a, b);
    return *reinterpret_cast<uint32_t*>(&t);
}
__device__ __forceinline__ void split2p(float v0, float v1, __nv_bfloat16* h, __nv_bfloat16* l, size_t idx) {
    float h0 = __bfloat162float(__float2bfloat16(v0));
    float h1 = __bfloat162float(__float2bfloat16(v1));
    *(uint32_t*)&h[idx] = bf2pack(v0, v1);
    *(uint32_t*)&l[idx] = bf2pack(v0 - h0, v1 - h1);
}
__device__ __forceinline__ void split4(float4 v, __nv_bfloat16* h, __nv_bfloat16* l, size_t idx) {
    float h0 = __bfloat162float(__float2bfloat16(v.x));
    float h1 = __bfloat162float(__float2bfloat16(v.y));
    float h2 = __bfloat162float(__float2bfloat16(v.z));
    float h3 = __bfloat162float(__float2bfloat16(v.w));
    uint2 hu, lu;
    hu.x = bf2pack(v.x, v.y);     hu.y = bf2pack(v.z, v.w);
    lu.x = bf2pack(v.x - h0, v.y - h1);
    lu.y = bf2pack(v.z - h2, v.w - h3);
    *(uint2*)&h[idx] = hu;
    *(uint2*)&l[idx] = lu;
}
__device__ __forceinline__ uint32_t smem_u32(const void* p) {
    uint32_t a;
    asm("{ .reg .u64 tmp; cvta.to.shared.u64 tmp, %1; cvt.u32.u64 %0, tmp; }" : "=r"(a) : "l"(p));
    return a;
}

// ======================= HMMA helpers =======================
__device__ __forceinline__ void ldsm_x4(uint32_t* r, uint32_t addr) {
    asm volatile("ldmatrix.sync.aligned.m8n8.x4.shared.b16 {%0,%1,%2,%3}, [%4];"
                 : "=r"(r[0]), "=r"(r[1]), "=r"(r[2]), "=r"(r[3]) : "r"(addr));
}
__device__ __forceinline__ void mma16816(float* c, const uint32_t* a, uint32_t b0, uint32_t b1) {
    asm volatile(
        "mma.sync.aligned.m16n8k16.row.col.f32.bf16.bf16.f32 "
        "{%0,%1,%2,%3}, {%4,%5,%6,%7}, {%8,%9}, {%0,%1,%2,%3};"
        : "+f"(c[0]), "+f"(c[1]), "+f"(c[2]), "+f"(c[3])
        : "r"(a[0]), "r"(a[1]), "r"(a[2]), "r"(a[3]), "r"(b0), "r"(b1));
}
__device__ __forceinline__ void mma16816h(float* c, const uint32_t* a, uint32_t b0, uint32_t b1) {
    asm volatile(
        "mma.sync.aligned.m16n8k16.row.col.f32.f16.f16.f32 "
        "{%0,%1,%2,%3}, {%4,%5,%6,%7}, {%8,%9}, {%0,%1,%2,%3};"
        : "+f"(c[0]), "+f"(c[1]), "+f"(c[2]), "+f"(c[3])
        : "r"(a[0]), "r"(a[1]), "r"(a[2]), "r"(a[3]), "r"(b0), "r"(b1));
}
#define MMSTRIDE 72
__device__ __forceinline__ uint32_t faddr(uint32_t base, int row0, int kk, int lane) {
    return base + (uint32_t)(((row0 + (lane & 15)) * MMSTRIDE + kk * 16 + ((lane >> 4) << 3)) * 2);
}
__device__ __forceinline__ void cpa16(uint32_t dst, const void* src) {
    asm volatile("cp.async.cg.shared.global [%0], [%1], 16;"
                 :: "r"(dst), "l"(__cvta_generic_to_global(src)) : "memory");
}
__device__ __forceinline__ void cpa16z(uint32_t dst, const void* src, int bytes) {
    asm volatile("cp.async.cg.shared.global [%0], [%1], 16, %2;"
                 :: "r"(dst), "l"(__cvta_generic_to_global(src)), "r"(bytes) : "memory");
}

// ======================= convert kernels =======================
__global__ void splitcvt_kernel(const float* __restrict__ x, __nv_bfloat16* __restrict__ h,
                                __nv_bfloat16* __restrict__ l, int n) {
    int i = (blockIdx.x * 256 + threadIdx.x) * 4;
    if (i >= n) return;
    split4(*(const float4*)(x + i), h, l, i);
}

__global__ void wconvT_kernel(const float* __restrict__ W, __nv_bfloat16* __restrict__ th,
                              __nv_bfloat16* __restrict__ tl, int K, int N) {
    __shared__ float sm[32][33];
    const int k0 = blockIdx.y * 32, n0 = blockIdx.x * 32;
    const int tx = threadIdx.x, ty = threadIdx.y;
    const int t = ty * 32 + tx;
#pragma unroll
    for (int i = 0; i < 4; i++)
        sm[ty + 8 * i][tx] = W[(size_t)(k0 + ty + 8 * i) * N + n0 + tx];
    __syncthreads();
#pragma unroll
    for (int e = 0; e < 2; e++) {
        int pid = e * 256 + t;
        int n = pid >> 4, kp = pid & 15;
        float v0 = sm[2 * kp][n], v1 = sm[2 * kp + 1][n];
        split2p(v0, v1, th, tl, (size_t)(n0 + n) * K + k0 + 2 * kp);
    }
}

// transpose: W [K,N] f32 -> WT fp16 [N,K]
__global__ void wconvT16_kernel(const float* __restrict__ W, __half* __restrict__ th,
                                int K, int N) {
    __shared__ float sm[32][33];
    const int k0 = blockIdx.y * 32, n0 = blockIdx.x * 32;
    const int tx = threadIdx.x, ty = threadIdx.y;
    const int t = ty * 32 + tx;
#pragma unroll
    for (int i = 0; i < 4; i++)
        sm[ty + 8 * i][tx] = W[(size_t)(k0 + ty + 8 * i) * N + n0 + tx];
    __syncthreads();
#pragma unroll
    for (int e = 0; e < 2; e++) {
        int pid = e * 256 + t;
        int n = pid >> 4, kp = pid & 15;
        *(uint32_t*)&th[(size_t)(n0 + n) * K + k0 + 2 * kp] =
            h2pack(sm[2 * kp][n], sm[2 * kp + 1][n]);
    }
}

// V^T conversion: wheads V section [t][2D + c] f32 -> VT fp16 [c][t]
__global__ void vconvT16_kernel(const float* __restrict__ wh, __half* __restrict__ th) {
    __shared__ float sm[32][33];
    const int t0 = blockIdx.x * 32, c0 = blockIdx.y * 32;
    const int tx = threadIdx.x, ty = threadIdx.y;
    const int t = ty * 32 + tx;
#pragma unroll
    for (int i = 0; i < 4; i++)
        sm[ty + 8 * i][tx] = wh[(size_t)(t0 + ty + 8 * i) * D3 + 2 * D + c0 + tx];
    __syncthreads();
#pragma unroll
    for (int e = 0; e < 2; e++) {
        int pid = e * 256 + t;
        int c = pid >> 4, tp = pid & 15;
        *(uint32_t*)&th[(size_t)(c0 + c) * T + t0 + 2 * tp] =
            h2pack(sm[2 * tp][c], sm[2 * tp + 1][c]);
    }
}

// ======================= layernorm (bf16 hi/lo) =======================
__global__ void ln_kernel(const float* __restrict__ x, const float* __restrict__ g,
                          const float* __restrict__ b, __nv_bfloat16* __restrict__ oh,
                          __nv_bfloat16* __restrict__ ol) {
    const int row = blockIdx.x;
    const int t = threadIdx.x;
    const float* xr = x + (size_t)row * D;
    float4 v = *(const float4*)&xr[t * 4];
    float s = v.x + v.y + v.z + v.w;
    __shared__ float red1[8], red2[8];
    s = warpSum(s);
    if ((t & 31) == 0) red1[t >> 5] = s;
    __syncthreads();
    float tot = red1[0] + red1[1] + red1[2] + red1[3] + red1[4] + red1[5] + red1[6] + red1[7];
    const float mean = tot * (1.0f / D);
    float dx = v.x - mean, dy = v.y - mean, dz = v.z - mean, dw = v.w - mean;
    float s2 = dx * dx + dy * dy + dz * dz + dw * dw;
    s2 = warpSum(s2);
    if ((t & 31) == 0) red2[t >> 5] = s2;
    __syncthreads();
    float var = (red2[0] + red2[1] + red2[2] + red2[3] + red2[4] + red2[5] + red2[6] + red2[7]) * (1.0f / D);
    const float inv = rsqrtf(var + 1e-5f);
    float4 gg = *(const float4*)&g[t * 4];
    float4 bb = *(const float4*)&b[t * 4];
    float4 o;
    o.x = dx * inv * gg.x + bb.x;
    o.y = dy * inv * gg.y + bb.y;
    o.z = dz * inv * gg.z + bb.z;
    o.w = dw * inv * gg.w + bb.w;
    split4(o, oh, ol, (size_t)row * D + t * 4);
}

// layernorm -> fp16 single
__global__ void ln16_kernel(const float* __restrict__ x, const float* __restrict__ g,
                            const float* __restrict__ b, __half* __restrict__ o16) {
    const int row = blockIdx.x;
    const int t = threadIdx.x;
    const float* xr = x + (size_t)row * D;
    float4 v = *(const float4*)&xr[t * 4];
    float s = v.x + v.y + v.z + v.w;
    __shared__ float red1[8], red2[8];
    s = warpSum(s);
    if ((t & 31) == 0) red1[t >> 5] = s;
    __syncthreads();
    float tot = red1[0] + red1[1] + red1[2] + red1[3] + red1[4] + red1[5] + red1[6] + red1[7];
    const float mean = tot * (1.0f / D);
    float dx = v.x - mean, dy = v.y - mean, dz = v.z - mean, dw = v.w - mean;
    float s2 = dx * dx + dy * dy + dz * dz + dw * dw;
    s2 = warpSum(s2);
    if ((t & 31) == 0) red2[t >> 5] = s2;
    __syncthreads();
    float var = (red2[0] + red2[1] + red2[2] + red2[3] + red2[4] + red2[5] + red2[6] + red2[7]) * (1.0f / D);
    const float inv = rsqrtf(var + 1e-5f);
    float4 gg = *(const float4*)&g[t * 4];
    float4 bb = *(const float4*)&b[t * 4];
    uint2 o;
    o.x = h2pack(dx * inv * gg.x + bb.x, dy * inv * gg.y + bb.y);
    o.y = h2pack(dz * inv * gg.z + bb.z, dw * inv * gg.w + bb.w);
    *(uint2*)&o16[(size_t)row * D + t * 4] = o;
}

// ======================= bf16 3-term GEMM: 128x64 tile, 2 CTAs/SM ============
#define BM 128
#define BN 64
#define BK 64
#define A_ARR (128 * MMSTRIDE * 2)
#define B_ARR (64 * MMSTRIDE * 2)
#define STAGE_BYTES (2 * A_ARR + 2 * B_ARR)  // 55296
#define MM_SMEM (2 * STAGE_BYTES)            // 110592

__device__ __forceinline__ void mm_load_chunk(
    const __nv_bfloat16* __restrict__ Ah, const __nv_bfloat16* __restrict__ Al,
    const __nv_bfloat16* __restrict__ Bh, const __nv_bfloat16* __restrict__ Bl,
    int m0, int n0, int K, int t, uint32_t stage_base, int tid) {
    const size_t k0 = (size_t)t * BK;
#pragma unroll
    for (int e = 0; e < 12; e++) {
        int idx = e * 256 + tid;
        const __nv_bfloat16* src;
        uint32_t dst;
        if (idx < 2048) {
            int arr = idx >> 10;
            int row = (idx >> 3) & 127;
            int ck  = idx & 7;
            src = (arr == 0 ? Ah : Al) + (size_t)(m0 + row) * K + k0 + ck * 8;
            dst = stage_base + (uint32_t)arr * A_ARR + (uint32_t)(row * 144 + ck * 16);
        } else {
            int k = idx - 2048;
            int arr = k >> 9;
            int row = (k >> 3) & 63;
            int ck  = k & 7;
            src = (arr == 0 ? Bh : Bl) + (size_t)(n0 + row) * K + k0 + ck * 8;
            dst = stage_base + 2 * A_ARR + (uint32_t)arr * B_ARR + (uint32_t)(row * 144 + ck * 16);
        }
        cpa16(dst, src);
    }
    asm volatile("cp.async.commit_group;" ::: "memory");
}

template <int EPI>
__global__ void __launch_bounds__(256, 2) mm_kernel(
    const __nv_bfloat16* __restrict__ Ah, const __nv_bfloat16* __restrict__ Al,
    const __nv_bfloat16* __restrict__ Bh, const __nv_bfloat16* __restrict__ Bl,
    const float* __restrict__ bias, const float* __restrict__ Rm,
    float* __restrict__ Cf, __nv_bfloat16* __restrict__ Ch, __nv_bfloat16* __restrict__ Cl,
    const float* __restrict__ rwb, const float* __restrict__ rrb,
    __nv_bfloat16* __restrict__ qwh, __nv_bfloat16* __restrict__ qwl,
    __nv_bfloat16* __restrict__ qrh, __nv_bfloat16* __restrict__ qrl,
    __nv_bfloat16* __restrict__ kkh, __nv_bfloat16* __restrict__ kkl,
    int M, int N, int K) {
    extern __shared__ char smem[];
    const uint32_t sbase = smem_u32(smem);
    const int tid = threadIdx.x;
    const int wid = tid >> 5, lane = tid & 31;
    const int m0 = blockIdx.y * BM, n0 = blockIdx.x * BN;
    const int mrow = (wid & 3) * 32;
    const int nrow = (wid >> 2) * 32;

    float c[2][4][4] = {};
    const int nch = K / BK;

    mm_load_chunk(Ah, Al, Bh, Bl, m0, n0, K, 0, sbase, tid);

    for (int t = 0; t < nch; t++) {
        asm volatile("cp.async.wait_group 0;" ::: "memory");
        __syncthreads();
        if (t + 1 < nch)
            mm_load_chunk(Ah, Al, Bh, Bl, m0, n0, K, t + 1, sbase + ((t + 1) & 1) * STAGE_BYTES, tid);
        const uint32_t sb = sbase + (t & 1) * STAGE_BYTES;
        const uint32_t vb = sb + 2 * A_ARR;
#pragma unroll
        for (int kk = 0; kk < 4; kk++) {
            uint32_t ah[2][4], al[2][4], bh[2][4], bl[2][4];
            ldsm_x4(ah[0], faddr(sb,          mrow,      kk, lane));
            ldsm_x4(ah[1], faddr(sb,          mrow + 16, kk, lane));
            ldsm_x4(al[0], faddr(sb + A_ARR,  mrow,      kk, lane));
            ldsm_x4(al[1], faddr(sb + A_ARR,  mrow + 16, kk, lane));
            ldsm_x4(bh[0], faddr(vb,          nrow,      kk, lane));
            ldsm_x4(bh[1], faddr(vb,          nrow + 16, kk, lane));
            ldsm_x4(bl[0], faddr(vb + B_ARR,  nrow,      kk, lane));
            ldsm_x4(bl[1], faddr(vb + B_ARR,  nrow + 16, kk, lane));
#pragma unroll
            for (int mi = 0; mi < 2; mi++)
#pragma unroll
                for (int nb = 0; nb < 4; nb++) {
                    const int nf = nb >> 1, o = nb & 1;
                    mma16816(c[mi][nb], ah[mi], bh[nf][o], bh[nf][2 + o]);
                    mma16816(c[mi][nb], ah[mi], bl[nf][o], bl[nf][2 + o]);
                    mma16816(c[mi][nb], al[mi], bh[nf][o], bh[nf][2 + o]);
                }
        }
    }

    const int tq = lane >> 2, tr = lane & 3;
#pragma unroll
    for (int mi = 0; mi < 2; mi++)
#pragma unroll
        for (int nb = 0; nb < 4; nb++)
#pragma unroll
            for (int hh = 0; hh < 2; hh++) {
                int gr = m0 + mrow + mi * 16 + tq + hh * 8;
                int gc = n0 + nrow + nb * 8 + tr * 2;
                float v0 = c[mi][nb][hh * 2 + 0];
                float v1 = c[mi][nb][hh * 2 + 1];
                if (EPI & 16) {
                    if (gc < D) {
                        size_t o = (size_t)gr * D + gc;
                        split2p(v0 + rwb[gc], v1 + rwb[gc + 1], qwh, qwl, o);
                        split2p(v0 + rrb[gc], v1 + rrb[gc + 1], qrh, qrl, o);
                    } else if (gc < 2 * D) {
                        split2p(v0, v1, kkh, kkl, (size_t)gr * D + gc - D);
                    } else {
                        float2 o2; o2.x = v0; o2.y = v1;
                        *(float2*)&Cf[(size_t)gr * N + gc] = o2;
                    }
                    continue;
                }
                if (EPI & 1) { v0 += bias[gc]; v1 += bias[gc + 1]; }
                if (EPI & 2) { v0 = fmaxf(v0, 0.f); v1 = fmaxf(v1, 0.f); }
                if (EPI & 4) {
                    float2 r = *(const float2*)&Rm[(size_t)gr * N + gc];
                    v0 += r.x; v1 += r.y;
                }
                if (EPI & 8) {
                    split2p(v0, v1, Ch, Cl, (size_t)gr * N + gc);
                } else {
                    float2 o; o.x = v0; o.y = v1;
                    *(float2*)&Cf[(size_t)gr * N + gc] = o;
                }
            }
}

// ======================= fp16 1-term GEMM: 128x128 tile, 2 CTAs/SM ============
// EPI bits: 1=bias, 2=relu, 4=residual, 8=fp16-out
#define H_ARR (128 * MMSTRIDE * 2)          // 18432
#define H_STAGE (2 * H_ARR)                 // 36864
#define MMH_SMEM (2 * H_STAGE)              // 73728

__device__ __forceinline__ void mmh_load_chunk(
    const __half* __restrict__ A, const __half* __restrict__ B,
    int m0, int n0, int K, int t, uint32_t stage_base, int tid) {
    const size_t k0 = (size_t)t * 64;
#pragma unroll
    for (int e = 0; e < 8; e++) {
        int idx = e * 256 + tid;
        int arr = idx >> 10;
        int row = (idx >> 3) & 127;
        int ck  = idx & 7;
        const __half* src = (arr == 0 ? A + (size_t)(m0 + row) * K
                                      : B + (size_t)(n0 + row) * K) + k0 + ck * 8;
        cpa16(stage_base + (uint32_t)arr * H_ARR + (uint32_t)(row * 144 + ck * 16), src);
    }
    asm volatile("cp.async.commit_group;" ::: "memory");
}

template <int EPI>
__global__ void __launch_bounds__(256, 2) mmh_kernel(
    const __half* __restrict__ A, const __half* __restrict__ B,
    const float* __restrict__ bias, const float* __restrict__ Rm,
    float* __restrict__ Cf, __half* __restrict__ C16,
    int M, int N, int K) {
    extern __shared__ char smem[];
    const uint32_t sbase = smem_u32(smem);
    const int tid = threadIdx.x;
    const int wid = tid >> 5, lane = tid & 31;
    const int m0 = blockIdx.y * 128, n0 = blockIdx.x * 128;
    const int mrow = (wid & 3) * 32;
    const int nrow = (wid >> 2) * 64;

    float c[2][8][4] = {};
    const int nch = K / 64;

    mmh_load_chunk(A, B, m0, n0, K, 0, sbase, tid);

    for (int t = 0; t < nch; t++) {
        asm volatile("cp.async.wait_group 0;" ::: "memory");
        __syncthreads();
        if (t + 1 < nch)
            mmh_load_chunk(A, B, m0, n0, K, t + 1, sbase + ((t + 1) & 1) * H_STAGE, tid);
        const uint32_t sb = sbase + (t & 1) * H_STAGE;
        const uint32_t vb = sb + H_ARR;
#pragma unroll
        for (int kk = 0; kk < 4; kk++) {
            uint32_t a[2][4], b[4][4];
            ldsm_x4(a[0], faddr(sb, mrow,      kk, lane));
            ldsm_x4(a[1], faddr(sb, mrow + 16, kk, lane));
#pragma unroll
            for (int nf = 0; nf < 4; nf++)
                ldsm_x4(b[nf], faddr(vb, nrow + nf * 16, kk, lane));
#pragma unroll
            for (int mi = 0; mi < 2; mi++)
#pragma unroll
                for (int nb = 0; nb < 8; nb++) {
                    const int nf = nb >> 1, o = nb & 1;
                    mma16816h(c[mi][nb], a[mi], b[nf][o], b[nf][2 + o]);
                }
        }
    }

    const int tq = lane >> 2, tr = lane & 3;
#pragma unroll
    for (int mi = 0; mi < 2; mi++)
#pragma unroll
        for (int nb = 0; nb < 8; nb++)
#pragma unroll
            for (int hh = 0; hh < 2; hh++) {
                int gr = m0 + mrow + mi * 16 + tq + hh * 8;
                int gc = n0 + nrow + nb * 8 + tr * 2;
                float v0 = c[mi][nb][hh * 2 + 0];
                float v1 = c[mi][nb][hh * 2 + 1];
                if (EPI & 1) { v0 += bias[gc]; v1 += bias[gc + 1]; }
                if (EPI & 2) { v0 = fmaxf(v0, 0.f); v1 = fmaxf(v1, 0.f); }
                if (EPI & 4) {
                    float2 r = *(const float2*)&Rm[(size_t)gr * N + gc];
                    v0 += r.x; v1 += r.y;
                }
                if (EPI & 8) {
                    *(uint32_t*)&C16[(size_t)gr * N + gc] = h2pack(v0, v1);
                } else {
                    float2 o; o.x = v0; o.y = v1;
                    *(float2*)&Cf[(size_t)gr * N + gc] = o;
                }
            }
}

// ======================= HMMA attention scores (bf16 3-term) ==================
#define SA 18432
#define SC_RB   (6 * SA)
#define SC_SMEM (6 * SA + 2 * 36864)  // 184320

__global__ void __launch_bounds__(256, 1) scores_mma_kernel(
    const __nv_bfloat16* __restrict__ qwh, const __nv_bfloat16* __restrict__ qwl,
    const __nv_bfloat16* __restrict__ qrh, const __nv_bfloat16* __restrict__ qrl,
    const __nv_bfloat16* __restrict__ kh,  const __nv_bfloat16* __restrict__ kl,
    const __nv_bfloat16* __restrict__ rkh, const __nv_bfloat16* __restrict__ rkl,
    float* __restrict__ sc) {
    const int h = blockIdx.z;
    const int n = blockIdx.x;
    float rf = (sqrtf(8.f * n + 1.f) - 1.f) * 0.5f;
    int iT = (int)rf;
    if ((iT + 1) * (iT + 2) / 2 <= n) iT++;
    if (iT * (iT + 1) / 2 > n) iT--;
    const int jT = n - iT * (iT + 1) / 2;
    const int i0 = iT * 128, j0 = jT * 128;
    extern __shared__ char smem[];
    const uint32_t sb = smem_u32(smem);
    const int tid = threadIdx.x;
    const int wid = tid >> 5, lane = tid & 31;
    const int mrow = (wid & 3) * 32;
    const int nrow = (wid >> 2) * 64;
    const int pbase = T - 1 - i0 + j0 - 127;
    float* bdbuf = (float*)(smem);

#pragma unroll
    for (int e = 0; e < 24; e++) {
        int idx = e * 256 + tid;
        int arr = idx >> 10;
        int row = (idx >> 3) & 127;
        int ck  = idx & 7;
        const __nv_bfloat16* src;
        int grow = ((arr == 2 || arr == 3) ? j0 : i0) + row;
        if (arr == 0) src = qwh; else if (arr == 1) src = qwl;
        else if (arr == 2) src = kh; else if (arr == 3) src = kl;
        else if (arr == 4) src = qrh; else src = qrl;
        cpa16(sb + (uint32_t)arr * SA + (uint32_t)(row * 144 + ck * 16),
              src + (size_t)grow * D + h * DH + ck * 8);
    }
    asm volatile("cp.async.commit_group;" ::: "memory");
#pragma unroll
    for (int e = 0; e < 16; e++) {
        int idx = e * 256 + tid;
        int arr = idx >> 11;
        int row = (idx >> 3) & 255;
        int ck  = idx & 7;
        int p = pbase + row;
        bool valid = (p >= 0 && p < T);
        size_t off = valid ? ((size_t)p * D + h * DH + ck * 8) : 0;
        cpa16z(sb + SC_RB + (uint32_t)arr * 36864u + (uint32_t)(row * 144 + ck * 16),
               (arr == 0 ? rkh : rkl) + off, valid ? 16 : 0);
    }
    asm volatile("cp.async.commit_group;" ::: "memory");
    asm volatile("cp.async.wait_group 1;" ::: "memory");
    __syncthreads();

    const uint32_t bqwh = sb, bqwl = sb + SA, bkh = sb + 2 * SA, bkl = sb + 3 * SA;
    const uint32_t bqrh = sb + 4 * SA, bqrl = sb + 5 * SA;
    const uint32_t brh = sb + SC_RB, brl = sb + SC_RB + 36864;

    float acc[2][8][4] = {};
#pragma unroll
    for (int kk = 0; kk < 4; kk++) {
        uint32_t ah[2][4], al[2][4], bh[4][4], bl[4][4];
        ldsm_x4(ah[0], faddr(bqwh, mrow,      kk, lane));
        ldsm_x4(ah[1], faddr(bqwh, mrow + 16, kk, lane));
        ldsm_x4(al[0], faddr(bqwl, mrow,      kk, lane));
        ldsm_x4(al[1], faddr(bqwl, mrow + 16, kk, lane));
#pragma unroll
        for (int nf = 0; nf < 4; nf++) ldsm_x4(bh[nf], faddr(bkh, nrow + nf * 16, kk, lane));
#pragma unroll
        for (int nf = 0; nf < 4; nf++) ldsm_x4(bl[nf], faddr(bkl, nrow + nf * 16, kk, lane));
#pragma unroll
        for (int mi = 0; mi < 2; mi++)
#pragma unroll
            for (int nb = 0; nb < 8; nb++) {
                const int nf = nb >> 1, o = nb & 1;
                mma16816(acc[mi][nb], ah[mi], bh[nf][o], bh[nf][2 + o]);
                mma16816(acc[mi][nb], ah[mi], bl[nf][o], bl[nf][2 + o]);
                mma16816(acc[mi][nb], al[mi], bh[nf][o], bh[nf][2 + o]);
            }
    }
    asm volatile("cp.async.wait_group 0;" ::: "memory");
    __syncthreads();

    const int tq = lane >> 2, tr = lane & 3;
#pragma unroll 1
    for (int half = 0; half < 2; half++) {
        float c2[2][8][4] = {};
#pragma unroll
        for (int kk = 0; kk < 4; kk++) {
            uint32_t ah[2][4], al[2][4], bh[4][4], bl[4][4];
            ldsm_x4(ah[0], faddr(bqrh, mrow,      kk, lane));
            ldsm_x4(ah[1], faddr(bqrh, mrow + 16, kk, lane));
            ldsm_x4(al[0], faddr(bqrl, mrow,      kk, lane));
            ldsm_x4(al[1], faddr(bqrl, mrow + 16, kk, lane));
#pragma unroll
            for (int nf = 0; nf < 4; nf++)
                ldsm_x4(bh[nf], faddr(brh, half * 128 + nrow + nf * 16, kk, lane));
#pragma unroll
            for (int nf = 0; nf < 4; nf++)
                ldsm_x4(bl[nf], faddr(brl, half * 128 + nrow + nf * 16, kk, lane));
#pragma unroll
            for (int mi = 0; mi < 2; mi++)
#pragma unroll
                for (int nb = 0; nb < 8; nb++) {
                    const int nf = nb >> 1, o = nb & 1;
                    mma16816(c2[mi][nb], ah[mi], bh[nf][o], bh[nf][2 + o]);
                    mma16816(c2[mi][nb], ah[mi], bl[nf][o], bl[nf][2 + o]);
                    mma16816(c2[mi][nb], al[mi], bh[nf][o], bh[nf][2 + o]);
                }
        }
        __syncthreads();
#pragma unroll
        for (int mi = 0; mi < 2; mi++)
#pragma unroll
            for (int nb = 0; nb < 8; nb++)
#pragma unroll
                for (int hh = 0; hh < 2; hh++) {
                    int di = mrow + mi * 16 + tq + hh * 8;
                    int dj = nrow + nb * 8 + tr * 2;
                    bdbuf[di * 130 + dj]     = c2[mi][nb][hh * 2 + 0];
                    bdbuf[di * 130 + dj + 1] = c2[mi][nb][hh * 2 + 1];
                }
        __syncthreads();
#pragma unroll
        for (int mi = 0; mi < 2; mi++)
#pragma unroll
            for (int nb = 0; nb < 8; nb++)
#pragma unroll
                for (int hh = 0; hh < 2; hh++) {
                    int di = mrow + mi * 16 + tq + hh * 8;
                    int dj = nrow + nb * 8 + tr * 2;
#pragma unroll
                    for (int cc = 0; cc < 2; cc++) {
                        int pl = 127 + (dj + cc) - di;
                        if ((pl >> 7) == half)
                            acc[mi][nb][hh * 2 + cc] += bdbuf[di * 130 + (pl & 127)];
                    }
                }
        __syncthreads();
    }

    const float scale = 0.125f;
#pragma unroll
    for (int mi = 0; mi < 2; mi++)
#pragma unroll
        for (int nb = 0; nb < 8; nb++)
#pragma unroll
            for (int hh = 0; hh < 2; hh++) {
                int gi = i0 + mrow + mi * 16 + tq + hh * 8;
                int gj = j0 + nrow + nb * 8 + tr * 2;
                float2 o;
                o.x = acc[mi][nb][hh * 2 + 0] * scale;
                o.y = acc[mi][nb][hh * 2 + 1] * scale;
                *(float2*)&sc[((size_t)h * T + gi) * T + gj] = o;
            }
}

// ======================= causal softmax -> fp16 probs (pad to 128) ===========
__global__ void softmax_kernel(const float* __restrict__ sc, __half* __restrict__ p16) {
    const int i = blockIdx.x;
    const int h = blockIdx.y;
    const size_t roff = ((size_t)h * T + i) * T;
    const float* row = sc + roff;
    const int t = threadIdx.x;
    const int n = i + 1;
    const int nup = (i & ~127) + 128;
    float4 v[2];
    float mx = -3.4e38f;
#pragma unroll
    for (int p = 0; p < 2; p++) {
        int j = (p * 256 + t) * 4;
        if (j < nup) {
            float4 w = *(const float4*)(row + j);
            w.x = (j + 0 < n) ? w.x : -3.4e38f;
            w.y = (j + 1 < n) ? w.y : -3.4e38f;
            w.z = (j + 2 < n) ? w.z : -3.4e38f;
            w.w = (j + 3 < n) ? w.w : -3.4e38f;
            v[p] = w;
            mx = fmaxf(mx, fmaxf(fmaxf(w.x, w.y), fmaxf(w.z, w.w)));
        } else {
            v[p].x = v[p].y = v[p].z = v[p].w = -3.4e38f;
        }
    }
    __shared__ float red1[8], red2[8];
    mx = warpMax(mx);
    if ((t & 31) == 0) red1[t >> 5] = mx;
    __syncthreads();
    mx = fmaxf(fmaxf(fmaxf(red1[0], red1[1]), fmaxf(red1[2], red1[3])),
               fmaxf(fmaxf(red1[4], red1[5]), fmaxf(red1[6], red1[7])));
    float s = 0.f;
#pragma unroll
    for (int p = 0; p < 2; p++) {
        float e0 = (v[p].x > -3.0e38f) ? __expf(v[p].x - mx) : 0.f;
        float e1 = (v[p].y > -3.0e38f) ? __expf(v[p].y - mx) : 0.f;
        float e2 = (v[p].z > -3.0e38f) ? __expf(v[p].z - mx) : 0.f;
        float e3 = (v[p].w > -3.0e38f) ? __expf(v[p].w - mx) : 0.f;
        v[p].x = e0; v[p].y = e1; v[p].z = e2; v[p].w = e3;
        s += e0 + e1 + e2 + e3;
    }
    s = warpSum(s);
    if ((t & 31) == 0) red2[t >> 5] = s;
    __syncthreads();
    float tot = red2[0] + red2[1] + red2[2] + red2[3] + red2[4] + red2[5] + red2[6] + red2[7];
    float inv = 1.0f / tot;
#pragma unroll
    for (int p = 0; p < 2; p++) {
        int j = (p * 256 + t) * 4;
        if (j < nup) {
            uint2 pu;
            pu.x = h2pack(v[p].x * inv, v[p].y * inv);
            pu.y = h2pack(v[p].z * inv, v[p].w * inv);
            *(uint2*)&p16[roff + j] = pu;
        }
    }
}

// ======================= probs layout: fp16 [h][i][j] -> f32 [i][j][h] ========
__global__ void probs_out_kernel(const __half* __restrict__ p16,
                                 float* __restrict__ out) {
    const int i = blockIdx.y;
    const int t = threadIdx.x;
    const int nup = (i & ~63) + 64;
    __shared__ float sm[16][66];
#pragma unroll 1
    for (int s = 0; s < 4; s++) {
        const int j0 = (blockIdx.x * 4 + s) * 64;
        float* dst = out + ((size_t)i * T + j0) * H;
        if (j0 < nup) {
#pragma unroll
            for (int e = 0; e < 2; e++) {
                int idx = e * 256 + t;
                int hh = idx >> 5, jp = idx & 31;
                size_t o = ((size_t)hh * T + i) * T + j0 + jp * 2;
                __half2 a = *(const __half2*)&p16[o];
                sm[hh][jp * 2]     = __half2float(a.x);
                sm[hh][jp * 2 + 1] = __half2float(a.y);
            }
            __syncthreads();
            int base = t * 4;
            float4 o4;
            o4.x = sm[(base + 0) & 15][(base + 0) >> 4];
            o4.y = sm[(base + 1) & 15][(base + 1) >> 4];
            o4.z = sm[(base + 2) & 15][(base + 2) >> 4];
            o4.w = sm[(base + 3) & 15][(base + 3) >> 4];
            *(float4*)&dst[base] = o4;
            __syncthreads();
        } else {
            float4 z; z.x = z.y = z.z = z.w = 0.f;
            *(float4*)&dst[t * 4] = z;
        }
    }
}

// ======================= fp16 PV: attn_vec = P @ V (128-row tiles) ===========
#define PVH_PARR 18432                 // 128*144
#define PVH_VARR 9216                  // 64*144
#define PVH_STAGE (PVH_PARR + PVH_VARR)   // 27648
#define PVH_SMEM (2 * PVH_STAGE)          // 55296

__device__ __forceinline__ void pvh_load_chunk(
    const __half* __restrict__ P, const __half* __restrict__ V,
    int h, int i0, int t, uint32_t stage_base, int tid) {
    const size_t j0 = (size_t)t * 64;
#pragma unroll
    for (int e = 0; e < 6; e++) {
        int idx = e * 256 + tid;          // 0..1535
        const __half* src;
        uint32_t dst;
        if (idx < 1024) {
            int row = (idx >> 3) & 127;
            int ck  = idx & 7;
            src = P + ((size_t)h * T + i0 + row) * T + j0 + ck * 8;
            dst = stage_base + (uint32_t)(row * 144 + ck * 16);
        } else {
            int k = idx - 1024;
            int row = (k >> 3) & 63;
            int ck  = k & 7;
            src = V + (size_t)(h * DH + row) * T + j0 + ck * 8;
            dst = stage_base + PVH_PARR + (uint32_t)(row * 144 + ck * 16);
        }
        cpa16(dst, src);
    }
    asm volatile("cp.async.commit_group;" ::: "memory");
}

__global__ void __launch_bounds__(256, 2) pv16_kernel(
    const __half* __restrict__ P, const __half* __restrict__ V,
    __half* __restrict__ av16) {
    extern __shared__ char smem[];
    const uint32_t sbase = smem_u32(smem);
    const int h = blockIdx.y;
    const int i0 = (gridDim.x - 1 - blockIdx.x) * 128;   // longest first
    const int tid = threadIdx.x;
    const int wid = tid >> 5, lane = tid & 31;
    const int mrow = (wid & 3) * 32;
    const int nrow = (wid >> 2) * 32;

    float c[2][4][4] = {};
    const int nch = i0 / 64 + 2;

    pvh_load_chunk(P, V, h, i0, 0, sbase, tid);

    for (int t = 0; t < nch; t++) {
        asm volatile("cp.async.wait_group 0;" ::: "memory");
        __syncthreads();
        if (t + 1 < nch)
            pvh_load_chunk(P, V, h, i0, t + 1, sbase + ((t + 1) & 1) * PVH_STAGE, tid);
        const uint32_t sb = sbase + (t & 1) * PVH_STAGE;
        const uint32_t vb = sb + PVH_PARR;
#pragma unroll
        for (int kk = 0; kk < 4; kk++) {
            uint32_t a[2][4], b[2][4];
            ldsm_x4(a[0], faddr(sb, mrow,      kk, lane));
            ldsm_x4(a[1], faddr(sb, mrow + 16, kk, lane));
            ldsm_x4(b[0], faddr(vb, nrow,      kk, lane));
            ldsm_x4(b[1], faddr(vb, nrow + 16, kk, lane));
#pragma unroll
            for (int mi = 0; mi < 2; mi++)
#pragma unroll
                for (int nb = 0; nb < 4; nb++) {
                    const int nf = nb >> 1, o = nb & 1;
                    mma16816h(c[mi][nb], a[mi], b[nf][o], b[nf][2 + o]);
                }
        }
    }

    const int tq = lane >> 2, tr = lane & 3;
#pragma unroll
    for (int mi = 0; mi < 2; mi++)
#pragma unroll
        for (int nb = 0; nb < 4; nb++)
#pragma unroll
            for (int hh = 0; hh < 2; hh++) {
                int gi = i0 + mrow + mi * 16 + tq + hh * 8;
                int gd = nrow + nb * 8 + tr * 2;
                size_t o = (size_t)gi * D + h * DH + gd;
                *(uint32_t*)&av16[o] = h2pack(c[mi][nb][hh * 2 + 0], c[mi][nb][hh * 2 + 1]);
            }
}

// ======================= host launch =======================
extern "C" void kernel_launch(void* const* d_in, const int* in_sizes, int n_in,
                              void* d_out, int out_size) {
    const float* input = (const float*)d_in[0];
    const float* pos   = (const float*)d_in[1];
    const float* rwb   = (const float*)d_in[2];
    const float* rrb   = (const float*)d_in[3];
    const float* ln1g  = (const float*)d_in[5];
    const float* ln1b  = (const float*)d_in[6];
    const float* qkvw  = (const float*)d_in[7];
    const float* rw    = (const float*)d_in[8];
    const float* ow    = (const float*)d_in[9];
    const float* ln2g  = (const float*)d_in[10];
    const float* ln2b  = (const float*)d_in[11];
    const float* ffw1  = (const float*)d_in[12];
    const float* ffb1  = (const float*)d_in[13];
    const float* ffw2  = (const float*)d_in[14];
    const float* ffb2  = (const float*)d_in[15];
    float* out = (float*)d_out;

    float *wheads, *scores, *x;
    cudaGetSymbolAddress((void**)&wheads, g_wheads);
    cudaGetSymbolAddress((void**)&scores, g_scores);
    cudaGetSymbolAddress((void**)&x,      g_x);
    __nv_bfloat16 *qin_h, *qin_l, *pos_h, *pos_l;
    cudaGetSymbolAddress((void**)&qin_h, g_qin_h); cudaGetSymbolAddress((void**)&qin_l, g_qin_l);
    cudaGetSymbolAddress((void**)&pos_h, g_pos_h); cudaGetSymbolAddress((void**)&pos_l, g_pos_l);
    __nv_bfloat16 *qkvwT_h, *qkvwT_l, *rwT_h, *rwT_l;
    cudaGetSymbolAddress((void**)&qkvwT_h, g_qkvwT_h); cudaGetSymbolAddress((void**)&qkvwT_l, g_qkvwT_l);
    cudaGetSymbolAddress((void**)&rwT_h,   g_rwT_h);   cudaGetSymbolAddress((void**)&rwT_l,   g_rwT_l);
    __nv_bfloat16 *qw_h, *qw_l, *qr_h, *qr_l, *k_h, *k_l, *rk_h, *rk_l;
    cudaGetSymbolAddress((void**)&qw_h, g_qw_h); cudaGetSymbolAddress((void**)&qw_l, g_qw_l);
    cudaGetSymbolAddress((void**)&qr_h, g_qr_h); cudaGetSymbolAddress((void**)&qr_l, g_qr_l);
    cudaGetSymbolAddress((void**)&k_h,  g_k_h);  cudaGetSymbolAddress((void**)&k_l,  g_k_l);
    cudaGetSymbolAddress((void**)&rk_h, g_rk_h); cudaGetSymbolAddress((void**)&rk_l, g_rk_l);
    __half *p16, *vt16, *av16, *owT16, *y16, *ff16, *w1T16, *w2T16;
    cudaGetSymbolAddress((void**)&p16,   g_p16);
    cudaGetSymbolAddress((void**)&vt16,  g_vt16);
    cudaGetSymbolAddress((void**)&av16,  g_av16);
    cudaGetSymbolAddress((void**)&owT16, g_owT16);
    cudaGetSymbolAddress((void**)&y16,   g_y16);
    cudaGetSymbolAddress((void**)&ff16,  g_ff16);
    cudaGetSymbolAddress((void**)&w1T16, g_w1T16);
    cudaGetSymbolAddress((void**)&w2T16, g_w2T16);

    cudaFuncSetAttribute((const void*)mm_kernel<16>, cudaFuncAttributeMaxDynamicSharedMemorySize, MM_SMEM);
    cudaFuncSetAttribute((const void*)mm_kernel<8>,  cudaFuncAttributeMaxDynamicSharedMemorySize, MM_SMEM);
    cudaFuncSetAttribute((const void*)mmh_kernel<4>,  cudaFuncAttributeMaxDynamicSharedMemorySize, MMH_SMEM);
    cudaFuncSetAttribute((const void*)mmh_kernel<11>, cudaFuncAttributeMaxDynamicSharedMemorySize, MMH_SMEM);
    cudaFuncSetAttribute((const void*)mmh_kernel<5>,  cudaFuncAttributeMaxDynamicSharedMemorySize, MMH_SMEM);
    cudaFuncSetAttribute((const void*)scores_mma_kernel, cudaFuncAttributeMaxDynamicSharedMemorySize, SC_SMEM);
    cudaFuncSetAttribute((const void*)pv16_kernel,  cudaFuncAttributeMaxDynamicSharedMemorySize, PVH_SMEM);

    const dim3 wthr(32, 8);
    const bool probs_fit =
        (long long)out_size >= (long long)T * D + (long long)H * T * T;

    ln_kernel<<<T, 256>>>(input, ln1g, ln1b, qin_h, qin_l);                          // 0
    wconvT_kernel<<<dim3(D3 / 32, D / 32), wthr>>>(qkvw, qkvwT_h, qkvwT_l, D, D3);   // 1
    splitcvt_kernel<<<(T * D) / 1024, 256>>>(pos, pos_h, pos_l, T * D);              // 2
    mm_kernel<16><<<dim3(D3 / 64, T / 128), 256, MM_SMEM>>>(                          // 3 (profiled)
        qin_h, qin_l, qkvwT_h, qkvwT_l, nullptr, nullptr, wheads, nullptr, nullptr,
        rwb, rrb, qw_h, qw_l, qr_h, qr_l, k_h, k_l, T, D3, D);
    wconvT_kernel<<<dim3(D / 32,  D / 32), wthr>>>(rw,   rwT_h,   rwT_l,   D, D);    // 4
    vconvT16_kernel<<<dim3(T / 32, D / 32), wthr>>>(wheads, vt16);                   // 5
    mm_kernel<8><<<dim3(D / 64, T / 128), 256, MM_SMEM>>>(                            // 6
        pos_h, pos_l, rwT_h, rwT_l, nullptr, nullptr, nullptr, rk_h, rk_l,
        nullptr, nullptr, nullptr, nullptr, nullptr, nullptr, nullptr, nullptr, T, D, D);
    wconvT16_kernel<<<dim3(D / 32,  D / 32), wthr>>>(ow, owT16, D, D);               // 7
    scores_mma_kernel<<<dim3(136, 1, H), 256, SC_SMEM>>>(
        qw_h, qw_l, qr_h, qr_l, k_h, k_l, rk_h, rk_l, scores);
    softmax_kernel<<<dim3(T, H), 256>>>(scores, p16);
    if (probs_fit) {
        probs_out_kernel<<<dim3(T / 256, T), 256>>>(p16, out + (size_t)T * D);
    }
    pv16_kernel<<<dim3(T / 128, H), 256, PVH_SMEM>>>(p16, vt16, av16);
    // x = input + attn_vec @ o_w (fp16 single-term)
    mmh_kernel<4><<<dim3(D / 128, T / 128), 256, MMH_SMEM>>>(
        av16, owT16, nullptr, input, x, nullptr, T, D, D);
    // FFN (fp16 single-term)
    ln16_kernel<<<T, 256>>>(x, ln2g, ln2b, y16);
    wconvT16_kernel<<<dim3(DFF / 32, D / 32), wthr>>>(ffw1, w1T16, D, DFF);
    wconvT16_kernel<<<dim3(D / 32, DFF / 32), wthr>>>(ffw2, w2T16, DFF, D);
    mmh_kernel<11><<<dim3(DFF / 128, T / 128), 256, MMH_SMEM>>>(
        y16, w1T16, ffb1, nullptr, nullptr, ff16, T, DFF, D);
    mmh_kernel<5><<<dim3(D / 128, T / 128), 256, MMH_SMEM>>>(
        ff16, w2T16, ffb2, x, out, nullptr, T, D, DFF);
}

// round 14
// speedup vs baseline: 1.7034x; 1.1593x over previous
#include <cuda_runtime.h>
#include <cuda_bf16.h>
#include <cuda_fp16.h>
#include <math.h>
#include <stdint.h>

#define T 2048
#define D 1024
#define H 16
#define DH 64
#define DFF 4096
#define D3 3072

// ======================= scratch (device globals) =======================
__device__ float g_wheads[(size_t)T * D3];
__device__ float g_scores[(size_t)H * T * T];
__device__ float g_x[(size_t)T * D];

__device__ __nv_bfloat16 g_qin_h[(size_t)T * D],  g_qin_l[(size_t)T * D];
__device__ __nv_bfloat16 g_qkvwT_h[(size_t)D3 * D],  g_qkvwT_l[(size_t)D3 * D];

// fp16 attention inputs
__device__ __half g_qw16[(size_t)T * D];     // Q + r_w_bias
__device__ __half g_qr16[(size_t)T * D];     // Q + r_r_bias
__device__ __half g_k16[(size_t)T * D];      // K
__device__ __half g_rk16[(size_t)T * D];     // r_k
__device__ __half g_pos16[(size_t)T * D];
__device__ __half g_rwT16[(size_t)D * D];

// fp16 paths
__device__ __half g_p16[(size_t)H * T * T];
__device__ __half g_vt16[(size_t)D * T];
__device__ __half g_av16[(size_t)T * D];
__device__ __half g_owT16[(size_t)D * D];
__device__ __half g_y16[(size_t)T * D];
__device__ __half g_ff16[(size_t)T * DFF];
__device__ __half g_w1T16[(size_t)DFF * D];
__device__ __half g_w2T16[(size_t)D * DFF];

// ======================= small utils =======================
__device__ __forceinline__ float warpSum(float v) {
#pragma unroll
    for (int o = 16; o > 0; o >>= 1) v += __shfl_xor_sync(0xffffffffu, v, o);
    return v;
}
__device__ __forceinline__ float warpMax(float v) {
#pragma unroll
    for (int o = 16; o > 0; o >>= 1) v = fmaxf(v, __shfl_xor_sync(0xffffffffu, v, o));
    return v;
}
__device__ __forceinline__ uint32_t bf2pack(float a, float b) {
    __nv_bfloat162 t = __floats2bfloat162_rn(a, b);
    return *reinterpret_cast<uint32_t*>(&t);
}
__device__ __forceinline__ uint32_t h2pack(float a, float b) {
    __half2 t = __floats2half2_rn(a, b);
    return *reinterpret_cast<uint32_t*>(&t);
}
__device__ __forceinline__ void split2p(float v0, float v1, __nv_bfloat16* h, __nv_bfloat16* l, size_t idx) {
    float h0 = __bfloat162float(__float2bfloat16(v0));
    float h1 = __bfloat162float(__float2bfloat16(v1));
    *(uint32_t*)&h[idx] = bf2pack(v0, v1);
    *(uint32_t*)&l[idx] = bf2pack(v0 - h0, v1 - h1);
}
__device__ __forceinline__ void split4(float4 v, __nv_bfloat16* h, __nv_bfloat16* l, size_t idx) {
    float h0 = __bfloat162float(__float2bfloat16(v.x));
    float h1 = __bfloat162float(__float2bfloat16(v.y));
    float h2 = __bfloat162float(__float2bfloat16(v.z));
    float h3 = __bfloat162float(__float2bfloat16(v.w));
    uint2 hu, lu;
    hu.x = bf2pack(v.x, v.y);     hu.y = bf2pack(v.z, v.w);
    lu.x = bf2pack(v.x - h0, v.y - h1);
    lu.y = bf2pack(v.z - h2, v.w - h3);
    *(uint2*)&h[idx] = hu;
    *(uint2*)&l[idx] = lu;
}
__device__ __forceinline__ uint32_t smem_u32(const void* p) {
    uint32_t a;
    asm("{ .reg .u64 tmp; cvta.to.shared.u64 tmp, %1; cvt.u32.u64 %0, tmp; }" : "=r"(a) : "l"(p));
    return a;
}

// ======================= HMMA helpers =======================
__device__ __forceinline__ void ldsm_x4(uint32_t* r, uint32_t addr) {
    asm volatile("ldmatrix.sync.aligned.m8n8.x4.shared.b16 {%0,%1,%2,%3}, [%4];"
                 : "=r"(r[0]), "=r"(r[1]), "=r"(r[2]), "=r"(r[3]) : "r"(addr));
}
__device__ __forceinline__ void mma16816(float* c, const uint32_t* a, uint32_t b0, uint32_t b1) {
    asm volatile(
        "mma.sync.aligned.m16n8k16.row.col.f32.bf16.bf16.f32 "
        "{%0,%1,%2,%3}, {%4,%5,%6,%7}, {%8,%9}, {%0,%1,%2,%3};"
        : "+f"(c[0]), "+f"(c[1]), "+f"(c[2]), "+f"(c[3])
        : "r"(a[0]), "r"(a[1]), "r"(a[2]), "r"(a[3]), "r"(b0), "r"(b1));
}
__device__ __forceinline__ void mma16816h(float* c, const uint32_t* a, uint32_t b0, uint32_t b1) {
    asm volatile(
        "mma.sync.aligned.m16n8k16.row.col.f32.f16.f16.f32 "
        "{%0,%1,%2,%3}, {%4,%5,%6,%7}, {%8,%9}, {%0,%1,%2,%3};"
        : "+f"(c[0]), "+f"(c[1]), "+f"(c[2]), "+f"(c[3])
        : "r"(a[0]), "r"(a[1]), "r"(a[2]), "r"(a[3]), "r"(b0), "r"(b1));
}
#define MMSTRIDE 72
__device__ __forceinline__ uint32_t faddr(uint32_t base, int row0, int kk, int lane) {
    return base + (uint32_t)(((row0 + (lane & 15)) * MMSTRIDE + kk * 16 + ((lane >> 4) << 3)) * 2);
}
__device__ __forceinline__ void cpa16(uint32_t dst, const void* src) {
    asm volatile("cp.async.cg.shared.global [%0], [%1], 16;"
                 :: "r"(dst), "l"(__cvta_generic_to_global(src)) : "memory");
}
__device__ __forceinline__ void cpa16z(uint32_t dst, const void* src, int bytes) {
    asm volatile("cp.async.cg.shared.global [%0], [%1], 16, %2;"
                 :: "r"(dst), "l"(__cvta_generic_to_global(src)), "r"(bytes) : "memory");
}

// ======================= convert kernels =======================
__global__ void splitcvt16_kernel(const float* __restrict__ x, __half* __restrict__ o16, int n) {
    int i = (blockIdx.x * 256 + threadIdx.x) * 4;
    if (i >= n) return;
    float4 v = *(const float4*)(x + i);
    uint2 o;
    o.x = h2pack(v.x, v.y);
    o.y = h2pack(v.z, v.w);
    *(uint2*)&o16[i] = o;
}

__global__ void wconvT_kernel(const float* __restrict__ W, __nv_bfloat16* __restrict__ th,
                              __nv_bfloat16* __restrict__ tl, int K, int N) {
    __shared__ float sm[32][33];
    const int k0 = blockIdx.y * 32, n0 = blockIdx.x * 32;
    const int tx = threadIdx.x, ty = threadIdx.y;
    const int t = ty * 32 + tx;
#pragma unroll
    for (int i = 0; i < 4; i++)
        sm[ty + 8 * i][tx] = W[(size_t)(k0 + ty + 8 * i) * N + n0 + tx];
    __syncthreads();
#pragma unroll
    for (int e = 0; e < 2; e++) {
        int pid = e * 256 + t;
        int n = pid >> 4, kp = pid & 15;
        float v0 = sm[2 * kp][n], v1 = sm[2 * kp + 1][n];
        split2p(v0, v1, th, tl, (size_t)(n0 + n) * K + k0 + 2 * kp);
    }
}

__global__ void wconvT16_kernel(const float* __restrict__ W, __half* __restrict__ th,
                                int K, int N) {
    __shared__ float sm[32][33];
    const int k0 = blockIdx.y * 32, n0 = blockIdx.x * 32;
    const int tx = threadIdx.x, ty = threadIdx.y;
    const int t = ty * 32 + tx;
#pragma unroll
    for (int i = 0; i < 4; i++)
        sm[ty + 8 * i][tx] = W[(size_t)(k0 + ty + 8 * i) * N + n0 + tx];
    __syncthreads();
#pragma unroll
    for (int e = 0; e < 2; e++) {
        int pid = e * 256 + t;
        int n = pid >> 4, kp = pid & 15;
        *(uint32_t*)&th[(size_t)(n0 + n) * K + k0 + 2 * kp] =
            h2pack(sm[2 * kp][n], sm[2 * kp + 1][n]);
    }
}

__global__ void vconvT16_kernel(const float* __restrict__ wh, __half* __restrict__ th) {
    __shared__ float sm[32][33];
    const int t0 = blockIdx.x * 32, c0 = blockIdx.y * 32;
    const int tx = threadIdx.x, ty = threadIdx.y;
    const int t = ty * 32 + tx;
#pragma unroll
    for (int i = 0; i < 4; i++)
        sm[ty + 8 * i][tx] = wh[(size_t)(t0 + ty + 8 * i) * D3 + 2 * D + c0 + tx];
    __syncthreads();
#pragma unroll
    for (int e = 0; e < 2; e++) {
        int pid = e * 256 + t;
        int c = pid >> 4, tp = pid & 15;
        *(uint32_t*)&th[(size_t)(c0 + c) * T + t0 + 2 * tp] =
            h2pack(sm[2 * tp][c], sm[2 * tp + 1][c]);
    }
}

// ======================= layernorm (bf16 hi/lo) =======================
__global__ void ln_kernel(const float* __restrict__ x, const float* __restrict__ g,
                          const float* __restrict__ b, __nv_bfloat16* __restrict__ oh,
                          __nv_bfloat16* __restrict__ ol) {
    const int row = blockIdx.x;
    const int t = threadIdx.x;
    const float* xr = x + (size_t)row * D;
    float4 v = *(const float4*)&xr[t * 4];
    float s = v.x + v.y + v.z + v.w;
    __shared__ float red1[8], red2[8];
    s = warpSum(s);
    if ((t & 31) == 0) red1[t >> 5] = s;
    __syncthreads();
    float tot = red1[0] + red1[1] + red1[2] + red1[3] + red1[4] + red1[5] + red1[6] + red1[7];
    const float mean = tot * (1.0f / D);
    float dx = v.x - mean, dy = v.y - mean, dz = v.z - mean, dw = v.w - mean;
    float s2 = dx * dx + dy * dy + dz * dz + dw * dw;
    s2 = warpSum(s2);
    if ((t & 31) == 0) red2[t >> 5] = s2;
    __syncthreads();
    float var = (red2[0] + red2[1] + red2[2] + red2[3] + red2[4] + red2[5] + red2[6] + red2[7]) * (1.0f / D);
    const float inv = rsqrtf(var + 1e-5f);
    float4 gg = *(const float4*)&g[t * 4];
    float4 bb = *(const float4*)&b[t * 4];
    float4 o;
    o.x = dx * inv * gg.x + bb.x;
    o.y = dy * inv * gg.y + bb.y;
    o.z = dz * inv * gg.z + bb.z;
    o.w = dw * inv * gg.w + bb.w;
    split4(o, oh, ol, (size_t)row * D + t * 4);
}

__global__ void ln16_kernel(const float* __restrict__ x, const float* __restrict__ g,
                            const float* __restrict__ b, __half* __restrict__ o16) {
    const int row = blockIdx.x;
    const int t = threadIdx.x;
    const float* xr = x + (size_t)row * D;
    float4 v = *(const float4*)&xr[t * 4];
    float s = v.x + v.y + v.z + v.w;
    __shared__ float red1[8], red2[8];
    s = warpSum(s);
    if ((t & 31) == 0) red1[t >> 5] = s;
    __syncthreads();
    float tot = red1[0] + red1[1] + red1[2] + red1[3] + red1[4] + red1[5] + red1[6] + red1[7];
    const float mean = tot * (1.0f / D);
    float dx = v.x - mean, dy = v.y - mean, dz = v.z - mean, dw = v.w - mean;
    float s2 = dx * dx + dy * dy + dz * dz + dw * dw;
    s2 = warpSum(s2);
    if ((t & 31) == 0) red2[t >> 5] = s2;
    __syncthreads();
    float var = (red2[0] + red2[1] + red2[2] + red2[3] + red2[4] + red2[5] + red2[6] + red2[7]) * (1.0f / D);
    const float inv = rsqrtf(var + 1e-5f);
    float4 gg = *(const float4*)&g[t * 4];
    float4 bb = *(const float4*)&b[t * 4];
    uint2 o;
    o.x = h2pack(dx * inv * gg.x + bb.x, dy * inv * gg.y + bb.y);
    o.y = h2pack(dz * inv * gg.z + bb.z, dw * inv * gg.w + bb.w);
    *(uint2*)&o16[(size_t)row * D + t * 4] = o;
}

// ======================= bf16 3-term GEMM (QKV only): 128x64, 2 CTA/SM =======
#define BM 128
#define BN 64
#define BK 64
#define A_ARR (128 * MMSTRIDE * 2)
#define B_ARR (64 * MMSTRIDE * 2)
#define STAGE_BYTES (2 * A_ARR + 2 * B_ARR)  // 55296
#define MM_SMEM (2 * STAGE_BYTES)            // 110592

__device__ __forceinline__ void mm_load_chunk(
    const __nv_bfloat16* __restrict__ Ah, const __nv_bfloat16* __restrict__ Al,
    const __nv_bfloat16* __restrict__ Bh, const __nv_bfloat16* __restrict__ Bl,
    int m0, int n0, int K, int t, uint32_t stage_base, int tid) {
    const size_t k0 = (size_t)t * BK;
#pragma unroll
    for (int e = 0; e < 12; e++) {
        int idx = e * 256 + tid;
        const __nv_bfloat16* src;
        uint32_t dst;
        if (idx < 2048) {
            int arr = idx >> 10;
            int row = (idx >> 3) & 127;
            int ck  = idx & 7;
            src = (arr == 0 ? Ah : Al) + (size_t)(m0 + row) * K + k0 + ck * 8;
            dst = stage_base + (uint32_t)arr * A_ARR + (uint32_t)(row * 144 + ck * 16);
        } else {
            int k = idx - 2048;
            int arr = k >> 9;
            int row = (k >> 3) & 63;
            int ck  = k & 7;
            src = (arr == 0 ? Bh : Bl) + (size_t)(n0 + row) * K + k0 + ck * 8;
            dst = stage_base + 2 * A_ARR + (uint32_t)arr * B_ARR + (uint32_t)(row * 144 + ck * 16);
        }
        cpa16(dst, src);
    }
    asm volatile("cp.async.commit_group;" ::: "memory");
}

// QKV GEMM with fused attention-prep epilogue (fp16 q/k outputs, f32 V)
__global__ void __launch_bounds__(256, 2) mmqkv_kernel(
    const __nv_bfloat16* __restrict__ Ah, const __nv_bfloat16* __restrict__ Al,
    const __nv_bfloat16* __restrict__ Bh, const __nv_bfloat16* __restrict__ Bl,
    float* __restrict__ Cf,
    const float* __restrict__ rwb, const float* __restrict__ rrb,
    __half* __restrict__ qw16, __half* __restrict__ qr16, __half* __restrict__ k16,
    int M, int N, int K) {
    extern __shared__ char smem[];
    const uint32_t sbase = smem_u32(smem);
    const int tid = threadIdx.x;
    const int wid = tid >> 5, lane = tid & 31;
    const int m0 = blockIdx.y * BM, n0 = blockIdx.x * BN;
    const int mrow = (wid & 3) * 32;
    const int nrow = (wid >> 2) * 32;

    float c[2][4][4] = {};
    const int nch = K / BK;

    mm_load_chunk(Ah, Al, Bh, Bl, m0, n0, K, 0, sbase, tid);

    for (int t = 0; t < nch; t++) {
        asm volatile("cp.async.wait_group 0;" ::: "memory");
        __syncthreads();
        if (t + 1 < nch)
            mm_load_chunk(Ah, Al, Bh, Bl, m0, n0, K, t + 1, sbase + ((t + 1) & 1) * STAGE_BYTES, tid);
        const uint32_t sb = sbase + (t & 1) * STAGE_BYTES;
        const uint32_t vb = sb + 2 * A_ARR;
#pragma unroll
        for (int kk = 0; kk < 4; kk++) {
            uint32_t ah[2][4], al[2][4], bh[2][4], bl[2][4];
            ldsm_x4(ah[0], faddr(sb,          mrow,      kk, lane));
            ldsm_x4(ah[1], faddr(sb,          mrow + 16, kk, lane));
            ldsm_x4(al[0], faddr(sb + A_ARR,  mrow,      kk, lane));
            ldsm_x4(al[1], faddr(sb + A_ARR,  mrow + 16, kk, lane));
            ldsm_x4(bh[0], faddr(vb,          nrow,      kk, lane));
            ldsm_x4(bh[1], faddr(vb,          nrow + 16, kk, lane));
            ldsm_x4(bl[0], faddr(vb + B_ARR,  nrow,      kk, lane));
            ldsm_x4(bl[1], faddr(vb + B_ARR,  nrow + 16, kk, lane));
#pragma unroll
            for (int mi = 0; mi < 2; mi++)
#pragma unroll
                for (int nb = 0; nb < 4; nb++) {
                    const int nf = nb >> 1, o = nb & 1;
                    mma16816(c[mi][nb], ah[mi], bh[nf][o], bh[nf][2 + o]);
                    mma16816(c[mi][nb], ah[mi], bl[nf][o], bl[nf][2 + o]);
                    mma16816(c[mi][nb], al[mi], bh[nf][o], bh[nf][2 + o]);
                }
        }
    }

    const int tq = lane >> 2, tr = lane & 3;
#pragma unroll
    for (int mi = 0; mi < 2; mi++)
#pragma unroll
        for (int nb = 0; nb < 4; nb++)
#pragma unroll
            for (int hh = 0; hh < 2; hh++) {
                int gr = m0 + mrow + mi * 16 + tq + hh * 8;
                int gc = n0 + nrow + nb * 8 + tr * 2;
                float v0 = c[mi][nb][hh * 2 + 0];
                float v1 = c[mi][nb][hh * 2 + 1];
                if (gc < D) {
                    size_t o = (size_t)gr * D + gc;
                    *(uint32_t*)&qw16[o] = h2pack(v0 + rwb[gc], v1 + rwb[gc + 1]);
                    *(uint32_t*)&qr16[o] = h2pack(v0 + rrb[gc], v1 + rrb[gc + 1]);
                } else if (gc < 2 * D) {
                    *(uint32_t*)&k16[(size_t)gr * D + gc - D] = h2pack(v0, v1);
                } else {
                    float2 o2; o2.x = v0; o2.y = v1;
                    *(float2*)&Cf[(size_t)gr * N + gc] = o2;
                }
            }
}

// ======================= fp16 1-term GEMM: 128x128 tile, 2 CTAs/SM ============
// EPI bits: 1=bias, 2=relu, 4=residual, 8=fp16-out
#define H_ARR (128 * MMSTRIDE * 2)
#define H_STAGE (2 * H_ARR)
#define MMH_SMEM (2 * H_STAGE)              // 73728

__device__ __forceinline__ void mmh_load_chunk(
    const __half* __restrict__ A, const __half* __restrict__ B,
    int m0, int n0, int K, int t, uint32_t stage_base, int tid) {
    const size_t k0 = (size_t)t * 64;
#pragma unroll
    for (int e = 0; e < 8; e++) {
        int idx = e * 256 + tid;
        int arr = idx >> 10;
        int row = (idx >> 3) & 127;
        int ck  = idx & 7;
        const __half* src = (arr == 0 ? A + (size_t)(m0 + row) * K
                                      : B + (size_t)(n0 + row) * K) + k0 + ck * 8;
        cpa16(stage_base + (uint32_t)arr * H_ARR + (uint32_t)(row * 144 + ck * 16), src);
    }
    asm volatile("cp.async.commit_group;" ::: "memory");
}

template <int EPI>
__global__ void __launch_bounds__(256, 2) mmh_kernel(
    const __half* __restrict__ A, const __half* __restrict__ B,
    const float* __restrict__ bias, const float* __restrict__ Rm,
    float* __restrict__ Cf, __half* __restrict__ C16,
    int M, int N, int K) {
    extern __shared__ char smem[];
    const uint32_t sbase = smem_u32(smem);
    const int tid = threadIdx.x;
    const int wid = tid >> 5, lane = tid & 31;
    const int m0 = blockIdx.y * 128, n0 = blockIdx.x * 128;
    const int mrow = (wid & 3) * 32;
    const int nrow = (wid >> 2) * 64;

    float c[2][8][4] = {};
    const int nch = K / 64;

    mmh_load_chunk(A, B, m0, n0, K, 0, sbase, tid);

    for (int t = 0; t < nch; t++) {
        asm volatile("cp.async.wait_group 0;" ::: "memory");
        __syncthreads();
        if (t + 1 < nch)
            mmh_load_chunk(A, B, m0, n0, K, t + 1, sbase + ((t + 1) & 1) * H_STAGE, tid);
        const uint32_t sb = sbase + (t & 1) * H_STAGE;
        const uint32_t vb = sb + H_ARR;
#pragma unroll
        for (int kk = 0; kk < 4; kk++) {
            uint32_t a[2][4], b[4][4];
            ldsm_x4(a[0], faddr(sb, mrow,      kk, lane));
            ldsm_x4(a[1], faddr(sb, mrow + 16, kk, lane));
#pragma unroll
            for (int nf = 0; nf < 4; nf++)
                ldsm_x4(b[nf], faddr(vb, nrow + nf * 16, kk, lane));
#pragma unroll
            for (int mi = 0; mi < 2; mi++)
#pragma unroll
                for (int nb = 0; nb < 8; nb++) {
                    const int nf = nb >> 1, o = nb & 1;
                    mma16816h(c[mi][nb], a[mi], b[nf][o], b[nf][2 + o]);
                }
        }
    }

    const int tq = lane >> 2, tr = lane & 3;
#pragma unroll
    for (int mi = 0; mi < 2; mi++)
#pragma unroll
        for (int nb = 0; nb < 8; nb++)
#pragma unroll
            for (int hh = 0; hh < 2; hh++) {
                int gr = m0 + mrow + mi * 16 + tq + hh * 8;
                int gc = n0 + nrow + nb * 8 + tr * 2;
                float v0 = c[mi][nb][hh * 2 + 0];
                float v1 = c[mi][nb][hh * 2 + 1];
                if (EPI & 1) { v0 += bias[gc]; v1 += bias[gc + 1]; }
                if (EPI & 2) { v0 = fmaxf(v0, 0.f); v1 = fmaxf(v1, 0.f); }
                if (EPI & 4) {
                    float2 r = *(const float2*)&Rm[(size_t)gr * N + gc];
                    v0 += r.x; v1 += r.y;
                }
                if (EPI & 8) {
                    *(uint32_t*)&C16[(size_t)gr * N + gc] = h2pack(v0, v1);
                } else {
                    float2 o; o.x = v0; o.y = v1;
                    *(float2*)&Cf[(size_t)gr * N + gc] = o;
                }
            }
}

// ======================= fp16 1-term attention scores =======================
// smem: [qw 18432][k 18432][qr 18432][band 36864] = 92160 -> 2 CTA/SM
// bdbuf f32 128x66 (33792 B) overlaps qw+k (dead after AC phase)
#define SAH 18432
#define SCH_BAND (3 * SAH)          // 55296
#define SCH_SMEM (3 * SAH + 36864)  // 92160

__global__ void __launch_bounds__(256, 2) scores16_kernel(
    const __half* __restrict__ qw, const __half* __restrict__ qr,
    const __half* __restrict__ k,  const __half* __restrict__ rk,
    float* __restrict__ sc) {
    const int h = blockIdx.z;
    const int n = blockIdx.x;
    float rf = (sqrtf(8.f * n + 1.f) - 1.f) * 0.5f;
    int iT = (int)rf;
    if ((iT + 1) * (iT + 2) / 2 <= n) iT++;
    if (iT * (iT + 1) / 2 > n) iT--;
    const int jT = n - iT * (iT + 1) / 2;
    const int i0 = iT * 128, j0 = jT * 128;
    extern __shared__ char smem[];
    const uint32_t sb = smem_u32(smem);
    const int tid = threadIdx.x;
    const int wid = tid >> 5, lane = tid & 31;
    const int mrow = (wid & 3) * 32;
    const int nrowAC = (wid >> 2) * 64;    // AC: 4x2 warps, 64-col groups
    const int nrowQ  = (wid >> 2) * 32;    // BD quarter: 4x2 warps, 32-col groups
    const int pbase = T - 1 - i0 + j0 - 127;
    float* bdbuf = (float*)(smem);          // 128 x 66 f32, overlaps qw/k

    // group 1: qw (i0), k (j0), qr (i0)
#pragma unroll
    for (int e = 0; e < 12; e++) {
        int idx = e * 256 + tid;            // 0..3071
        int arr = idx >> 10;                // 0: qw, 1: k, 2: qr
        int row = (idx >> 3) & 127;
        int ck  = idx & 7;
        const __half* src = (arr == 0) ? qw : (arr == 1) ? k : qr;
        int grow = ((arr == 1) ? j0 : i0) + row;
        cpa16(sb + (uint32_t)arr * SAH + (uint32_t)(row * 144 + ck * 16),
              src + (size_t)grow * D + h * DH + ck * 8);
    }
    asm volatile("cp.async.commit_group;" ::: "memory");
    // group 2: band (rk rows pbase..pbase+255)
#pragma unroll
    for (int e = 0; e < 8; e++) {
        int idx = e * 256 + tid;            // 0..2047
        int row = (idx >> 3) & 255;
        int ck  = idx & 7;
        int p = pbase + row;
        bool valid = (p >= 0 && p < T);
        size_t off = valid ? ((size_t)p * D + h * DH + ck * 8) : 0;
        cpa16z(sb + SCH_BAND + (uint32_t)(row * 144 + ck * 16), rk + off, valid ? 16 : 0);
    }
    asm volatile("cp.async.commit_group;" ::: "memory");
    asm volatile("cp.async.wait_group 1;" ::: "memory");   // qw/k/qr ready
    __syncthreads();

    float acc[2][8][4] = {};
    // ---- AC phase: qw @ k^T (band still streaming)
#pragma unroll
    for (int kk = 0; kk < 4; kk++) {
        uint32_t a[2][4], b[4][4];
        ldsm_x4(a[0], faddr(sb, mrow,      kk, lane));
        ldsm_x4(a[1], faddr(sb, mrow + 16, kk, lane));
#pragma unroll
        for (int nf = 0; nf < 4; nf++)
            ldsm_x4(b[nf], faddr(sb + SAH, nrowAC + nf * 16, kk, lane));
#pragma unroll
        for (int mi = 0; mi < 2; mi++)
#pragma unroll
            for (int nb = 0; nb < 8; nb++) {
                const int nf = nb >> 1, o = nb & 1;
                mma16816h(acc[mi][nb], a[mi], b[nf][o], b[nf][2 + o]);
            }
    }
    asm volatile("cp.async.wait_group 0;" ::: "memory");   // band ready
    __syncthreads();

    const int tq = lane >> 2, tr = lane & 3;
    // ---- BD: 4 quarter passes of 64 band-cols each
#pragma unroll 1
    for (int q = 0; q < 4; q++) {
        float c2[2][4][4] = {};
#pragma unroll
        for (int kk = 0; kk < 4; kk++) {
            uint32_t a[2][4], b[2][4];
            ldsm_x4(a[0], faddr(sb + 2 * SAH, mrow,      kk, lane));
            ldsm_x4(a[1], faddr(sb + 2 * SAH, mrow + 16, kk, lane));
            ldsm_x4(b[0], faddr(sb + SCH_BAND, q * 64 + nrowQ,      kk, lane));
            ldsm_x4(b[1], faddr(sb + SCH_BAND, q * 64 + nrowQ + 16, kk, lane));
#pragma unroll
            for (int mi = 0; mi < 2; mi++)
#pragma unroll
                for (int nb = 0; nb < 4; nb++) {
                    const int nf = nb >> 1, o = nb & 1;
                    mma16816h(c2[mi][nb], a[mi], b[nf][o], b[nf][2 + o]);
                }
        }
        __syncthreads();    // q=0: guards AC ldsm of qw/k; q>0: guards prior gather reads
#pragma unroll
        for (int mi = 0; mi < 2; mi++)
#pragma unroll
            for (int nb = 0; nb < 4; nb++)
#pragma unroll
                for (int hh = 0; hh < 2; hh++) {
                    int di = mrow + mi * 16 + tq + hh * 8;
                    int djq = nrowQ + nb * 8 + tr * 2;
                    bdbuf[di * 66 + djq]     = c2[mi][nb][hh * 2 + 0];
                    bdbuf[di * 66 + djq + 1] = c2[mi][nb][hh * 2 + 1];
                }
        __syncthreads();
#pragma unroll
        for (int mi = 0; mi < 2; mi++)
#pragma unroll
            for (int nb = 0; nb < 8; nb++)
#pragma unroll
                for (int hh = 0; hh < 2; hh++) {
                    int di = mrow + mi * 16 + tq + hh * 8;
                    int dj = nrowAC + nb * 8 + tr * 2;
#pragma unroll
                    for (int cc = 0; cc < 2; cc++) {
                        int pl = 127 + (dj + cc) - di;
                        if ((pl >> 6) == q)
                            acc[mi][nb][hh * 2 + cc] += bdbuf[di * 66 + (pl & 63)];
                    }
                }
        __syncthreads();
    }

    const float scale = 0.125f;
#pragma unroll
    for (int mi = 0; mi < 2; mi++)
#pragma unroll
        for (int nb = 0; nb < 8; nb++)
#pragma unroll
            for (int hh = 0; hh < 2; hh++) {
                int gi = i0 + mrow + mi * 16 + tq + hh * 8;
                int gj = j0 + nrowAC + nb * 8 + tr * 2;
                float2 o;
                o.x = acc[mi][nb][hh * 2 + 0] * scale;
                o.y = acc[mi][nb][hh * 2 + 1] * scale;
                *(float2*)&sc[((size_t)h * T + gi) * T + gj] = o;
            }
}

// ======================= causal softmax -> fp16 probs (pad to 128) ===========
__global__ void softmax_kernel(const float* __restrict__ sc, __half* __restrict__ p16) {
    const int i = blockIdx.x;
    const int h = blockIdx.y;
    const size_t roff = ((size_t)h * T + i) * T;
    const float* row = sc + roff;
    const int t = threadIdx.x;
    const int n = i + 1;
    const int nup = (i & ~127) + 128;
    float4 v[2];
    float mx = -3.4e38f;
#pragma unroll
    for (int p = 0; p < 2; p++) {
        int j = (p * 256 + t) * 4;
        if (j < nup) {
            float4 w = *(const float4*)(row + j);
            w.x = (j + 0 < n) ? w.x : -3.4e38f;
            w.y = (j + 1 < n) ? w.y : -3.4e38f;
            w.z = (j + 2 < n) ? w.z : -3.4e38f;
            w.w = (j + 3 < n) ? w.w : -3.4e38f;
            v[p] = w;
            mx = fmaxf(mx, fmaxf(fmaxf(w.x, w.y), fmaxf(w.z, w.w)));
        } else {
            v[p].x = v[p].y = v[p].z = v[p].w = -3.4e38f;
        }
    }
    __shared__ float red1[8], red2[8];
    mx = warpMax(mx);
    if ((t & 31) == 0) red1[t >> 5] = mx;
    __syncthreads();
    mx = fmaxf(fmaxf(fmaxf(red1[0], red1[1]), fmaxf(red1[2], red1[3])),
               fmaxf(fmaxf(red1[4], red1[5]), fmaxf(red1[6], red1[7])));
    float s = 0.f;
#pragma unroll
    for (int p = 0; p < 2; p++) {
        float e0 = (v[p].x > -3.0e38f) ? __expf(v[p].x - mx) : 0.f;
        float e1 = (v[p].y > -3.0e38f) ? __expf(v[p].y - mx) : 0.f;
        float e2 = (v[p].z > -3.0e38f) ? __expf(v[p].z - mx) : 0.f;
        float e3 = (v[p].w > -3.0e38f) ? __expf(v[p].w - mx) : 0.f;
        v[p].x = e0; v[p].y = e1; v[p].z = e2; v[p].w = e3;
        s += e0 + e1 + e2 + e3;
    }
    s = warpSum(s);
    if ((t & 31) == 0) red2[t >> 5] = s;
    __syncthreads();
    float tot = red2[0] + red2[1] + red2[2] + red2[3] + red2[4] + red2[5] + red2[6] + red2[7];
    float inv = 1.0f / tot;
#pragma unroll
    for (int p = 0; p < 2; p++) {
        int j = (p * 256 + t) * 4;
        if (j < nup) {
            uint2 pu;
            pu.x = h2pack(v[p].x * inv, v[p].y * inv);
            pu.y = h2pack(v[p].z * inv, v[p].w * inv);
            *(uint2*)&p16[roff + j] = pu;
        }
    }
}

// ======================= probs layout: fp16 [h][i][j] -> f32 [i][j][h] ========
__global__ void probs_out_kernel(const __half* __restrict__ p16,
                                 float* __restrict__ out) {
    const int i = blockIdx.y;
    const int t = threadIdx.x;
    const int nup = (i & ~63) + 64;
    __shared__ float sm[16][66];
#pragma unroll 1
    for (int s = 0; s < 4; s++) {
        const int j0 = (blockIdx.x * 4 + s) * 64;
        float* dst = out + ((size_t)i * T + j0) * H;
        if (j0 < nup) {
#pragma unroll
            for (int e = 0; e < 2; e++) {
                int idx = e * 256 + t;
                int hh = idx >> 5, jp = idx & 31;
                size_t o = ((size_t)hh * T + i) * T + j0 + jp * 2;
                __half2 a = *(const __half2*)&p16[o];
                sm[hh][jp * 2]     = __half2float(a.x);
                sm[hh][jp * 2 + 1] = __half2float(a.y);
            }
            __syncthreads();
            int base = t * 4;
            float4 o4;
            o4.x = sm[(base + 0) & 15][(base + 0) >> 4];
            o4.y = sm[(base + 1) & 15][(base + 1) >> 4];
            o4.z = sm[(base + 2) & 15][(base + 2) >> 4];
            o4.w = sm[(base + 3) & 15][(base + 3) >> 4];
            *(float4*)&dst[base] = o4;
            __syncthreads();
        } else {
            float4 z; z.x = z.y = z.z = z.w = 0.f;
            *(float4*)&dst[t * 4] = z;
        }
    }
}

// ======================= fp16 PV =======================
#define PVH_PARR 18432
#define PVH_VARR 9216
#define PVH_STAGE (PVH_PARR + PVH_VARR)
#define PVH_SMEM (2 * PVH_STAGE)

__device__ __forceinline__ void pvh_load_chunk(
    const __half* __restrict__ P, const __half* __restrict__ V,
    int h, int i0, int t, uint32_t stage_base, int tid) {
    const size_t j0 = (size_t)t * 64;
#pragma unroll
    for (int e = 0; e < 6; e++) {
        int idx = e * 256 + tid;
        const __half* src;
        uint32_t dst;
        if (idx < 1024) {
            int row = (idx >> 3) & 127;
            int ck  = idx & 7;
            src = P + ((size_t)h * T + i0 + row) * T + j0 + ck * 8;
            dst = stage_base + (uint32_t)(row * 144 + ck * 16);
        } else {
            int k = idx - 1024;
            int row = (k >> 3) & 63;
            int ck  = k & 7;
            src = V + (size_t)(h * DH + row) * T + j0 + ck * 8;
            dst = stage_base + PVH_PARR + (uint32_t)(row * 144 + ck * 16);
        }
        cpa16(dst, src);
    }
    asm volatile("cp.async.commit_group;" ::: "memory");
}

__global__ void __launch_bounds__(256, 2) pv16_kernel(
    const __half* __restrict__ P, const __half* __restrict__ V,
    __half* __restrict__ av16) {
    extern __shared__ char smem[];
    const uint32_t sbase = smem_u32(smem);
    const int h = blockIdx.y;
    const int i0 = (gridDim.x - 1 - blockIdx.x) * 128;
    const int tid = threadIdx.x;
    const int wid = tid >> 5, lane = tid & 31;
    const int mrow = (wid & 3) * 32;
    const int nrow = (wid >> 2) * 32;

    float c[2][4][4] = {};
    const int nch = i0 / 64 + 2;

    pvh_load_chunk(P, V, h, i0, 0, sbase, tid);

    for (int t = 0; t < nch; t++) {
        asm volatile("cp.async.wait_group 0;" ::: "memory");
        __syncthreads();
        if (t + 1 < nch)
            pvh_load_chunk(P, V, h, i0, t + 1, sbase + ((t + 1) & 1) * PVH_STAGE, tid);
        const uint32_t sb = sbase + (t & 1) * PVH_STAGE;
        const uint32_t vb = sb + PVH_PARR;
#pragma unroll
        for (int kk = 0; kk < 4; kk++) {
            uint32_t a[2][4], b[2][4];
            ldsm_x4(a[0], faddr(sb, mrow,      kk, lane));
            ldsm_x4(a[1], faddr(sb, mrow + 16, kk, lane));
            ldsm_x4(b[0], faddr(vb, nrow,      kk, lane));
            ldsm_x4(b[1], faddr(vb, nrow + 16, kk, lane));
#pragma unroll
            for (int mi = 0; mi < 2; mi++)
#pragma unroll
                for (int nb = 0; nb < 4; nb++) {
                    const int nf = nb >> 1, o = nb & 1;
                    mma16816h(c[mi][nb], a[mi], b[nf][o], b[nf][2 + o]);
                }
        }
    }

    const int tq = lane >> 2, tr = lane & 3;
#pragma unroll
    for (int mi = 0; mi < 2; mi++)
#pragma unroll
        for (int nb = 0; nb < 4; nb++)
#pragma unroll
            for (int hh = 0; hh < 2; hh++) {
                int gi = i0 + mrow + mi * 16 + tq + hh * 8;
                int gd = nrow + nb * 8 + tr * 2;
                size_t o = (size_t)gi * D + h * DH + gd;
                *(uint32_t*)&av16[o] = h2pack(c[mi][nb][hh * 2 + 0], c[mi][nb][hh * 2 + 1]);
            }
}

// ======================= host launch =======================
extern "C" void kernel_launch(void* const* d_in, const int* in_sizes, int n_in,
                              void* d_out, int out_size) {
    const float* input = (const float*)d_in[0];
    const float* pos   = (const float*)d_in[1];
    const float* rwb   = (const float*)d_in[2];
    const float* rrb   = (const float*)d_in[3];
    const float* ln1g  = (const float*)d_in[5];
    const float* ln1b  = (const float*)d_in[6];
    const float* qkvw  = (const float*)d_in[7];
    const float* rw    = (const float*)d_in[8];
    const float* ow    = (const float*)d_in[9];
    const float* ln2g  = (const float*)d_in[10];
    const float* ln2b  = (const float*)d_in[11];
    const float* ffw1  = (const float*)d_in[12];
    const float* ffb1  = (const float*)d_in[13];
    const float* ffw2  = (const float*)d_in[14];
    const float* ffb2  = (const float*)d_in[15];
    float* out = (float*)d_out;

    float *wheads, *scores, *x;
    cudaGetSymbolAddress((void**)&wheads, g_wheads);
    cudaGetSymbolAddress((void**)&scores, g_scores);
    cudaGetSymbolAddress((void**)&x,      g_x);
    __nv_bfloat16 *qin_h, *qin_l, *qkvwT_h, *qkvwT_l;
    cudaGetSymbolAddress((void**)&qin_h, g_qin_h); cudaGetSymbolAddress((void**)&qin_l, g_qin_l);
    cudaGetSymbolAddress((void**)&qkvwT_h, g_qkvwT_h); cudaGetSymbolAddress((void**)&qkvwT_l, g_qkvwT_l);
    __half *qw16, *qr16, *k16, *rk16, *pos16, *rwT16;
    cudaGetSymbolAddress((void**)&qw16, g_qw16);
    cudaGetSymbolAddress((void**)&qr16, g_qr16);
    cudaGetSymbolAddress((void**)&k16,  g_k16);
    cudaGetSymbolAddress((void**)&rk16, g_rk16);
    cudaGetSymbolAddress((void**)&pos16, g_pos16);
    cudaGetSymbolAddress((void**)&rwT16, g_rwT16);
    __half *p16, *vt16, *av16, *owT16, *y16, *ff16, *w1T16, *w2T16;
    cudaGetSymbolAddress((void**)&p16,   g_p16);
    cudaGetSymbolAddress((void**)&vt16,  g_vt16);
    cudaGetSymbolAddress((void**)&av16,  g_av16);
    cudaGetSymbolAddress((void**)&owT16, g_owT16);
    cudaGetSymbolAddress((void**)&y16,   g_y16);
    cudaGetSymbolAddress((void**)&ff16,  g_ff16);
    cudaGetSymbolAddress((void**)&w1T16, g_w1T16);
    cudaGetSymbolAddress((void**)&w2T16, g_w2T16);

    cudaFuncSetAttribute((const void*)mmqkv_kernel, cudaFuncAttributeMaxDynamicSharedMemorySize, MM_SMEM);
    cudaFuncSetAttribute((const void*)mmh_kernel<4>,  cudaFuncAttributeMaxDynamicSharedMemorySize, MMH_SMEM);
    cudaFuncSetAttribute((const void*)mmh_kernel<8>,  cudaFuncAttributeMaxDynamicSharedMemorySize, MMH_SMEM);
    cudaFuncSetAttribute((const void*)mmh_kernel<11>, cudaFuncAttributeMaxDynamicSharedMemorySize, MMH_SMEM);
    cudaFuncSetAttribute((const void*)mmh_kernel<5>,  cudaFuncAttributeMaxDynamicSharedMemorySize, MMH_SMEM);
    cudaFuncSetAttribute((const void*)scores16_kernel, cudaFuncAttributeMaxDynamicSharedMemorySize, SCH_SMEM);
    cudaFuncSetAttribute((const void*)pv16_kernel,  cudaFuncAttributeMaxDynamicSharedMemorySize, PVH_SMEM);

    const dim3 wthr(32, 8);
    const bool probs_fit =
        (long long)out_size >= (long long)T * D + (long long)H * T * T;

    ln_kernel<<<T, 256>>>(input, ln1g, ln1b, qin_h, qin_l);                          // 0
    wconvT_kernel<<<dim3(D3 / 32, D / 32), wthr>>>(qkvw, qkvwT_h, qkvwT_l, D, D3);   // 1
    splitcvt16_kernel<<<(T * D) / 1024, 256>>>(pos, pos16, T * D);                   // 2
    mmqkv_kernel<<<dim3(D3 / 64, T / 128), 256, MM_SMEM>>>(                           // 3 (profiled)
        qin_h, qin_l, qkvwT_h, qkvwT_l, wheads, rwb, rrb, qw16, qr16, k16, T, D3, D);
    wconvT16_kernel<<<dim3(D / 32,  D / 32), wthr>>>(rw, rwT16, D, D);               // 4
    vconvT16_kernel<<<dim3(T / 32, D / 32), wthr>>>(wheads, vt16);                   // 5
    mmh_kernel<8><<<dim3(D / 128, T / 128), 256, MMH_SMEM>>>(                         // 6: rk
        pos16, rwT16, nullptr, nullptr, nullptr, rk16, T, D, D);
    wconvT16_kernel<<<dim3(D / 32,  D / 32), wthr>>>(ow, owT16, D, D);               // 7
    scores16_kernel<<<dim3(136, 1, H), 256, SCH_SMEM>>>(qw16, qr16, k16, rk16, scores);
    softmax_kernel<<<dim3(T, H), 256>>>(scores, p16);
    if (probs_fit) {
        probs_out_kernel<<<dim3(T / 256, T), 256>>>(p16, out + (size_t)T * D);
    }
    pv16_kernel<<<dim3(T / 128, H), 256, PVH_SMEM>>>(p16, vt16, av16);
    mmh_kernel<4><<<dim3(D / 128, T / 128), 256, MMH_SMEM>>>(
        av16, owT16, nullptr, input, x, nullptr, T, D, D);
    ln16_kernel<<<T, 256>>>(x, ln2g, ln2b, y16);
    wconvT16_kernel<<<dim3(DFF / 32, D / 32), wthr>>>(ffw1, w1T16, D, DFF);
    wconvT16_kernel<<<dim3(D / 32, DFF / 32), wthr>>>(ffw2, w2T16, DFF, D);
    mmh_kernel<11><<<dim3(DFF / 128, T / 128), 256, MMH_SMEM>>>(
        y16, w1T16, ffb1, nullptr, nullptr, ff16, T, DFF, D);
    mmh_kernel<5><<<dim3(D / 128, T / 128), 256, MMH_SMEM>>>(
        ff16, w2T16, ffb2, x, out, nullptr, T, D, DFF);
}

// round 15
// speedup vs baseline: 1.9522x; 1.1461x over previous
#include <cuda_runtime.h>
#include <cuda_fp16.h>
#include <math.h>
#include <stdint.h>

#define T 2048
#define D 1024
#define H 16
#define DH 64
#define DFF 4096
#define D3 3072

// ======================= scratch (device globals) =======================
__device__ float g_scores[(size_t)H * T * T];
__device__ float g_x[(size_t)T * D];

// fp16 everything
__device__ __half g_qin16[(size_t)T * D];
__device__ __half g_qkvwT16[(size_t)D3 * D];
__device__ __half g_qw16[(size_t)T * D];     // Q + r_w_bias
__device__ __half g_qr16[(size_t)T * D];     // Q + r_r_bias
__device__ __half g_k16[(size_t)T * D];      // K
__device__ __half g_v16[(size_t)T * D];      // V (row-major)
__device__ __half g_rk16[(size_t)T * D];     // r_k
__device__ __half g_pos16[(size_t)T * D];
__device__ __half g_rwT16[(size_t)D * D];
__device__ __half g_p16[(size_t)H * T * T];
__device__ __half g_vt16[(size_t)D * T];     // V^T [h*64+d][t]
__device__ __half g_av16[(size_t)T * D];
__device__ __half g_owT16[(size_t)D * D];
__device__ __half g_y16[(size_t)T * D];
__device__ __half g_ff16[(size_t)T * DFF];
__device__ __half g_w1T16[(size_t)DFF * D];
__device__ __half g_w2T16[(size_t)D * DFF];

// ======================= small utils =======================
__device__ __forceinline__ float warpSum(float v) {
#pragma unroll
    for (int o = 16; o > 0; o >>= 1) v += __shfl_xor_sync(0xffffffffu, v, o);
    return v;
}
__device__ __forceinline__ float warpMax(float v) {
#pragma unroll
    for (int o = 16; o > 0; o >>= 1) v = fmaxf(v, __shfl_xor_sync(0xffffffffu, v, o));
    return v;
}
__device__ __forceinline__ uint32_t h2pack(float a, float b) {
    __half2 t = __floats2half2_rn(a, b);
    return *reinterpret_cast<uint32_t*>(&t);
}
__device__ __forceinline__ uint32_t smem_u32(const void* p) {
    uint32_t a;
    asm("{ .reg .u64 tmp; cvta.to.shared.u64 tmp, %1; cvt.u32.u64 %0, tmp; }" : "=r"(a) : "l"(p));
    return a;
}

// ======================= HMMA helpers =======================
__device__ __forceinline__ void ldsm_x4(uint32_t* r, uint32_t addr) {
    asm volatile("ldmatrix.sync.aligned.m8n8.x4.shared.b16 {%0,%1,%2,%3}, [%4];"
                 : "=r"(r[0]), "=r"(r[1]), "=r"(r[2]), "=r"(r[3]) : "r"(addr));
}
__device__ __forceinline__ void mma16816h(float* c, const uint32_t* a, uint32_t b0, uint32_t b1) {
    asm volatile(
        "mma.sync.aligned.m16n8k16.row.col.f32.f16.f16.f32 "
        "{%0,%1,%2,%3}, {%4,%5,%6,%7}, {%8,%9}, {%0,%1,%2,%3};"
        : "+f"(c[0]), "+f"(c[1]), "+f"(c[2]), "+f"(c[3])
        : "r"(a[0]), "r"(a[1]), "r"(a[2]), "r"(a[3]), "r"(b0), "r"(b1));
}
#define MMSTRIDE 72
__device__ __forceinline__ uint32_t faddr(uint32_t base, int row0, int kk, int lane) {
    return base + (uint32_t)(((row0 + (lane & 15)) * MMSTRIDE + kk * 16 + ((lane >> 4) << 3)) * 2);
}
__device__ __forceinline__ void cpa16(uint32_t dst, const void* src) {
    asm volatile("cp.async.cg.shared.global [%0], [%1], 16;"
                 :: "r"(dst), "l"(__cvta_generic_to_global(src)) : "memory");
}
__device__ __forceinline__ void cpa16z(uint32_t dst, const void* src, int bytes) {
    asm volatile("cp.async.cg.shared.global [%0], [%1], 16, %2;"
                 :: "r"(dst), "l"(__cvta_generic_to_global(src)), "r"(bytes) : "memory");
}

// ======================= convert kernels =======================
__global__ void splitcvt16_kernel(const float* __restrict__ x, __half* __restrict__ o16, int n) {
    int i = (blockIdx.x * 256 + threadIdx.x) * 4;
    if (i >= n) return;
    float4 v = *(const float4*)(x + i);
    uint2 o;
    o.x = h2pack(v.x, v.y);
    o.y = h2pack(v.z, v.w);
    *(uint2*)&o16[i] = o;
}

// transpose: W [K,N] f32 -> WT fp16 [N,K]
__global__ void wconvT16_kernel(const float* __restrict__ W, __half* __restrict__ th,
                                int K, int N) {
    __shared__ float sm[32][33];
    const int k0 = blockIdx.y * 32, n0 = blockIdx.x * 32;
    const int tx = threadIdx.x, ty = threadIdx.y;
    const int t = ty * 32 + tx;
#pragma unroll
    for (int i = 0; i < 4; i++)
        sm[ty + 8 * i][tx] = W[(size_t)(k0 + ty + 8 * i) * N + n0 + tx];
    __syncthreads();
#pragma unroll
    for (int e = 0; e < 2; e++) {
        int pid = e * 256 + t;
        int n = pid >> 4, kp = pid & 15;
        *(uint32_t*)&th[(size_t)(n0 + n) * K + k0 + 2 * kp] =
            h2pack(sm[2 * kp][n], sm[2 * kp + 1][n]);
    }
}

// V^T: v16 [t][c] fp16 -> vt16 [c][t] fp16
__global__ void vconvT16h_kernel(const __half* __restrict__ v16, __half* __restrict__ th) {
    __shared__ float sm[32][33];
    const int t0 = blockIdx.x * 32, c0 = blockIdx.y * 32;
    const int tx = threadIdx.x, ty = threadIdx.y;
    const int t = ty * 32 + tx;
#pragma unroll
    for (int i = 0; i < 4; i++)
        sm[ty + 8 * i][tx] = __half2float(v16[(size_t)(t0 + ty + 8 * i) * D + c0 + tx]);
    __syncthreads();
#pragma unroll
    for (int e = 0; e < 2; e++) {
        int pid = e * 256 + t;
        int c = pid >> 4, tp = pid & 15;
        *(uint32_t*)&th[(size_t)(c0 + c) * T + t0 + 2 * tp] =
            h2pack(sm[2 * tp][c], sm[2 * tp + 1][c]);
    }
}

// ======================= layernorm -> fp16 =======================
__global__ void ln16_kernel(const float* __restrict__ x, const float* __restrict__ g,
                            const float* __restrict__ b, __half* __restrict__ o16) {
    const int row = blockIdx.x;
    const int t = threadIdx.x;
    const float* xr = x + (size_t)row * D;
    float4 v = *(const float4*)&xr[t * 4];
    float s = v.x + v.y + v.z + v.w;
    __shared__ float red1[8], red2[8];
    s = warpSum(s);
    if ((t & 31) == 0) red1[t >> 5] = s;
    __syncthreads();
    float tot = red1[0] + red1[1] + red1[2] + red1[3] + red1[4] + red1[5] + red1[6] + red1[7];
    const float mean = tot * (1.0f / D);
    float dx = v.x - mean, dy = v.y - mean, dz = v.z - mean, dw = v.w - mean;
    float s2 = dx * dx + dy * dy + dz * dz + dw * dw;
    s2 = warpSum(s2);
    if ((t & 31) == 0) red2[t >> 5] = s2;
    __syncthreads();
    float var = (red2[0] + red2[1] + red2[2] + red2[3] + red2[4] + red2[5] + red2[6] + red2[7]) * (1.0f / D);
    const float inv = rsqrtf(var + 1e-5f);
    float4 gg = *(const float4*)&g[t * 4];
    float4 bb = *(const float4*)&b[t * 4];
    uint2 o;
    o.x = h2pack(dx * inv * gg.x + bb.x, dy * inv * gg.y + bb.y);
    o.y = h2pack(dz * inv * gg.z + bb.z, dw * inv * gg.w + bb.w);
    *(uint2*)&o16[(size_t)row * D + t * 4] = o;
}

// ======================= fp16 1-term GEMM: 128x128 tile, 2 CTAs/SM ============
// EPI bits: 1=bias, 2=relu, 4=residual, 8=fp16-out
#define H_ARR (128 * MMSTRIDE * 2)
#define H_STAGE (2 * H_ARR)
#define MMH_SMEM (2 * H_STAGE)              // 73728

__device__ __forceinline__ void mmh_load_chunk(
    const __half* __restrict__ A, const __half* __restrict__ B,
    int m0, int n0, int K, int t, uint32_t stage_base, int tid) {
    const size_t k0 = (size_t)t * 64;
#pragma unroll
    for (int e = 0; e < 8; e++) {
        int idx = e * 256 + tid;
        int arr = idx >> 10;
        int row = (idx >> 3) & 127;
        int ck  = idx & 7;
        const __half* src = (arr == 0 ? A + (size_t)(m0 + row) * K
                                      : B + (size_t)(n0 + row) * K) + k0 + ck * 8;
        cpa16(stage_base + (uint32_t)arr * H_ARR + (uint32_t)(row * 144 + ck * 16), src);
    }
    asm volatile("cp.async.commit_group;" ::: "memory");
}

template <int EPI>
__global__ void __launch_bounds__(256, 2) mmh_kernel(
    const __half* __restrict__ A, const __half* __restrict__ B,
    const float* __restrict__ bias, const float* __restrict__ Rm,
    float* __restrict__ Cf, __half* __restrict__ C16,
    int M, int N, int K) {
    extern __shared__ char smem[];
    const uint32_t sbase = smem_u32(smem);
    const int tid = threadIdx.x;
    const int wid = tid >> 5, lane = tid & 31;
    const int m0 = blockIdx.y * 128, n0 = blockIdx.x * 128;
    const int mrow = (wid & 3) * 32;
    const int nrow = (wid >> 2) * 64;

    float c[2][8][4] = {};
    const int nch = K / 64;

    mmh_load_chunk(A, B, m0, n0, K, 0, sbase, tid);

    for (int t = 0; t < nch; t++) {
        asm volatile("cp.async.wait_group 0;" ::: "memory");
        __syncthreads();
        if (t + 1 < nch)
            mmh_load_chunk(A, B, m0, n0, K, t + 1, sbase + ((t + 1) & 1) * H_STAGE, tid);
        const uint32_t sb = sbase + (t & 1) * H_STAGE;
        const uint32_t vb = sb + H_ARR;
#pragma unroll
        for (int kk = 0; kk < 4; kk++) {
            uint32_t a[2][4], b[4][4];
            ldsm_x4(a[0], faddr(sb, mrow,      kk, lane));
            ldsm_x4(a[1], faddr(sb, mrow + 16, kk, lane));
#pragma unroll
            for (int nf = 0; nf < 4; nf++)
                ldsm_x4(b[nf], faddr(vb, nrow + nf * 16, kk, lane));
#pragma unroll
            for (int mi = 0; mi < 2; mi++)
#pragma unroll
                for (int nb = 0; nb < 8; nb++) {
                    const int nf = nb >> 1, o = nb & 1;
                    mma16816h(c[mi][nb], a[mi], b[nf][o], b[nf][2 + o]);
                }
        }
    }

    const int tq = lane >> 2, tr = lane & 3;
#pragma unroll
    for (int mi = 0; mi < 2; mi++)
#pragma unroll
        for (int nb = 0; nb < 8; nb++)
#pragma unroll
            for (int hh = 0; hh < 2; hh++) {
                int gr = m0 + mrow + mi * 16 + tq + hh * 8;
                int gc = n0 + nrow + nb * 8 + tr * 2;
                float v0 = c[mi][nb][hh * 2 + 0];
                float v1 = c[mi][nb][hh * 2 + 1];
                if (EPI & 1) { v0 += bias[gc]; v1 += bias[gc + 1]; }
                if (EPI & 2) { v0 = fmaxf(v0, 0.f); v1 = fmaxf(v1, 0.f); }
                if (EPI & 4) {
                    float2 r = *(const float2*)&Rm[(size_t)gr * N + gc];
                    v0 += r.x; v1 += r.y;
                }
                if (EPI & 8) {
                    *(uint32_t*)&C16[(size_t)gr * N + gc] = h2pack(v0, v1);
                } else {
                    float2 o; o.x = v0; o.y = v1;
                    *(float2*)&Cf[(size_t)gr * N + gc] = o;
                }
            }
}

// ======================= fp16 QKV GEMM with attn-prep epilogue ================
__global__ void __launch_bounds__(256, 2) mmqkv16_kernel(
    const __half* __restrict__ A, const __half* __restrict__ B,
    const float* __restrict__ rwb, const float* __restrict__ rrb,
    __half* __restrict__ qw16, __half* __restrict__ qr16,
    __half* __restrict__ k16, __half* __restrict__ v16,
    int M, int N, int K) {
    extern __shared__ char smem[];
    const uint32_t sbase = smem_u32(smem);
    const int tid = threadIdx.x;
    const int wid = tid >> 5, lane = tid & 31;
    const int m0 = blockIdx.y * 128, n0 = blockIdx.x * 128;
    const int mrow = (wid & 3) * 32;
    const int nrow = (wid >> 2) * 64;

    float c[2][8][4] = {};
    const int nch = K / 64;

    mmh_load_chunk(A, B, m0, n0, K, 0, sbase, tid);

    for (int t = 0; t < nch; t++) {
        asm volatile("cp.async.wait_group 0;" ::: "memory");
        __syncthreads();
        if (t + 1 < nch)
            mmh_load_chunk(A, B, m0, n0, K, t + 1, sbase + ((t + 1) & 1) * H_STAGE, tid);
        const uint32_t sb = sbase + (t & 1) * H_STAGE;
        const uint32_t vb = sb + H_ARR;
#pragma unroll
        for (int kk = 0; kk < 4; kk++) {
            uint32_t a[2][4], b[4][4];
            ldsm_x4(a[0], faddr(sb, mrow,      kk, lane));
            ldsm_x4(a[1], faddr(sb, mrow + 16, kk, lane));
#pragma unroll
            for (int nf = 0; nf < 4; nf++)
                ldsm_x4(b[nf], faddr(vb, nrow + nf * 16, kk, lane));
#pragma unroll
            for (int mi = 0; mi < 2; mi++)
#pragma unroll
                for (int nb = 0; nb < 8; nb++) {
                    const int nf = nb >> 1, o = nb & 1;
                    mma16816h(c[mi][nb], a[mi], b[nf][o], b[nf][2 + o]);
                }
        }
    }

    const int tq = lane >> 2, tr = lane & 3;
#pragma unroll
    for (int mi = 0; mi < 2; mi++)
#pragma unroll
        for (int nb = 0; nb < 8; nb++)
#pragma unroll
            for (int hh = 0; hh < 2; hh++) {
                int gr = m0 + mrow + mi * 16 + tq + hh * 8;
                int gc = n0 + nrow + nb * 8 + tr * 2;
                float v0 = c[mi][nb][hh * 2 + 0];
                float v1 = c[mi][nb][hh * 2 + 1];
                if (gc < D) {
                    size_t o = (size_t)gr * D + gc;
                    *(uint32_t*)&qw16[o] = h2pack(v0 + rwb[gc], v1 + rwb[gc + 1]);
                    *(uint32_t*)&qr16[o] = h2pack(v0 + rrb[gc], v1 + rrb[gc + 1]);
                } else if (gc < 2 * D) {
                    *(uint32_t*)&k16[(size_t)gr * D + gc - D] = h2pack(v0, v1);
                } else {
                    *(uint32_t*)&v16[(size_t)gr * D + gc - 2 * D] = h2pack(v0, v1);
                }
            }
}

// ======================= fp16 1-term attention scores =======================
#define SAH 18432
#define SCH_BAND (3 * SAH)          // 55296
#define SCH_SMEM (3 * SAH + 36864)  // 92160

__global__ void __launch_bounds__(256, 2) scores16_kernel(
    const __half* __restrict__ qw, const __half* __restrict__ qr,
    const __half* __restrict__ k,  const __half* __restrict__ rk,
    float* __restrict__ sc) {
    const int h = blockIdx.z;
    const int n = blockIdx.x;
    float rf = (sqrtf(8.f * n + 1.f) - 1.f) * 0.5f;
    int iT = (int)rf;
    if ((iT + 1) * (iT + 2) / 2 <= n) iT++;
    if (iT * (iT + 1) / 2 > n) iT--;
    const int jT = n - iT * (iT + 1) / 2;
    const int i0 = iT * 128, j0 = jT * 128;
    extern __shared__ char smem[];
    const uint32_t sb = smem_u32(smem);
    const int tid = threadIdx.x;
    const int wid = tid >> 5, lane = tid & 31;
    const int mrow = (wid & 3) * 32;
    const int nrowAC = (wid >> 2) * 64;
    const int nrowQ  = (wid >> 2) * 32;
    const int pbase = T - 1 - i0 + j0 - 127;
    float* bdbuf = (float*)(smem);

#pragma unroll
    for (int e = 0; e < 12; e++) {
        int idx = e * 256 + tid;
        int arr = idx >> 10;                // 0: qw, 1: k, 2: qr
        int row = (idx >> 3) & 127;
        int ck  = idx & 7;
        const __half* src = (arr == 0) ? qw : (arr == 1) ? k : qr;
        int grow = ((arr == 1) ? j0 : i0) + row;
        cpa16(sb + (uint32_t)arr * SAH + (uint32_t)(row * 144 + ck * 16),
              src + (size_t)grow * D + h * DH + ck * 8);
    }
    asm volatile("cp.async.commit_group;" ::: "memory");
#pragma unroll
    for (int e = 0; e < 8; e++) {
        int idx = e * 256 + tid;
        int row = (idx >> 3) & 255;
        int ck  = idx & 7;
        int p = pbase + row;
        bool valid = (p >= 0 && p < T);
        size_t off = valid ? ((size_t)p * D + h * DH + ck * 8) : 0;
        cpa16z(sb + SCH_BAND + (uint32_t)(row * 144 + ck * 16), rk + off, valid ? 16 : 0);
    }
    asm volatile("cp.async.commit_group;" ::: "memory");
    asm volatile("cp.async.wait_group 1;" ::: "memory");
    __syncthreads();

    float acc[2][8][4] = {};
#pragma unroll
    for (int kk = 0; kk < 4; kk++) {
        uint32_t a[2][4], b[4][4];
        ldsm_x4(a[0], faddr(sb, mrow,      kk, lane));
        ldsm_x4(a[1], faddr(sb, mrow + 16, kk, lane));
#pragma unroll
        for (int nf = 0; nf < 4; nf++)
            ldsm_x4(b[nf], faddr(sb + SAH, nrowAC + nf * 16, kk, lane));
#pragma unroll
        for (int mi = 0; mi < 2; mi++)
#pragma unroll
            for (int nb = 0; nb < 8; nb++) {
                const int nf = nb >> 1, o = nb & 1;
                mma16816h(acc[mi][nb], a[mi], b[nf][o], b[nf][2 + o]);
            }
    }
    asm volatile("cp.async.wait_group 0;" ::: "memory");
    __syncthreads();

    const int tq = lane >> 2, tr = lane & 3;
#pragma unroll 1
    for (int q = 0; q < 4; q++) {
        float c2[2][4][4] = {};
#pragma unroll
        for (int kk = 0; kk < 4; kk++) {
            uint32_t a[2][4], b[2][4];
            ldsm_x4(a[0], faddr(sb + 2 * SAH, mrow,      kk, lane));
            ldsm_x4(a[1], faddr(sb + 2 * SAH, mrow + 16, kk, lane));
            ldsm_x4(b[0], faddr(sb + SCH_BAND, q * 64 + nrowQ,      kk, lane));
            ldsm_x4(b[1], faddr(sb + SCH_BAND, q * 64 + nrowQ + 16, kk, lane));
#pragma unroll
            for (int mi = 0; mi < 2; mi++)
#pragma unroll
                for (int nb = 0; nb < 4; nb++) {
                    const int nf = nb >> 1, o = nb & 1;
                    mma16816h(c2[mi][nb], a[mi], b[nf][o], b[nf][2 + o]);
                }
        }
        __syncthreads();
#pragma unroll
        for (int mi = 0; mi < 2; mi++)
#pragma unroll
            for (int nb = 0; nb < 4; nb++)
#pragma unroll
                for (int hh = 0; hh < 2; hh++) {
                    int di = mrow + mi * 16 + tq + hh * 8;
                    int djq = nrowQ + nb * 8 + tr * 2;
                    bdbuf[di * 66 + djq]     = c2[mi][nb][hh * 2 + 0];
                    bdbuf[di * 66 + djq + 1] = c2[mi][nb][hh * 2 + 1];
                }
        __syncthreads();
#pragma unroll
        for (int mi = 0; mi < 2; mi++)
#pragma unroll
            for (int nb = 0; nb < 8; nb++)
#pragma unroll
                for (int hh = 0; hh < 2; hh++) {
                    int di = mrow + mi * 16 + tq + hh * 8;
                    int dj = nrowAC + nb * 8 + tr * 2;
#pragma unroll
                    for (int cc = 0; cc < 2; cc++) {
                        int pl = 127 + (dj + cc) - di;
                        if ((pl >> 6) == q)
                            acc[mi][nb][hh * 2 + cc] += bdbuf[di * 66 + (pl & 63)];
                    }
                }
        __syncthreads();
    }

    const float scale = 0.125f;
#pragma unroll
    for (int mi = 0; mi < 2; mi++)
#pragma unroll
        for (int nb = 0; nb < 8; nb++)
#pragma unroll
            for (int hh = 0; hh < 2; hh++) {
                int gi = i0 + mrow + mi * 16 + tq + hh * 8;
                int gj = j0 + nrowAC + nb * 8 + tr * 2;
                float2 o;
                o.x = acc[mi][nb][hh * 2 + 0] * scale;
                o.y = acc[mi][nb][hh * 2 + 1] * scale;
                *(float2*)&sc[((size_t)h * T + gi) * T + gj] = o;
            }
}

// ======================= causal softmax -> fp16 probs (pad to 128) ===========
__global__ void softmax_kernel(const float* __restrict__ sc, __half* __restrict__ p16) {
    const int i = blockIdx.x;
    const int h = blockIdx.y;
    const size_t roff = ((size_t)h * T + i) * T;
    const float* row = sc + roff;
    const int t = threadIdx.x;
    const int n = i + 1;
    const int nup = (i & ~127) + 128;
    float4 v[2];
    float mx = -3.4e38f;
#pragma unroll
    for (int p = 0; p < 2; p++) {
        int j = (p * 256 + t) * 4;
        if (j < nup) {
            float4 w = *(const float4*)(row + j);
            w.x = (j + 0 < n) ? w.x : -3.4e38f;
            w.y = (j + 1 < n) ? w.y : -3.4e38f;
            w.z = (j + 2 < n) ? w.z : -3.4e38f;
            w.w = (j + 3 < n) ? w.w : -3.4e38f;
            v[p] = w;
            mx = fmaxf(mx, fmaxf(fmaxf(w.x, w.y), fmaxf(w.z, w.w)));
        } else {
            v[p].x = v[p].y = v[p].z = v[p].w = -3.4e38f;
        }
    }
    __shared__ float red1[8], red2[8];
    mx = warpMax(mx);
    if ((t & 31) == 0) red1[t >> 5] = mx;
    __syncthreads();
    mx = fmaxf(fmaxf(fmaxf(red1[0], red1[1]), fmaxf(red1[2], red1[3])),
               fmaxf(fmaxf(red1[4], red1[5]), fmaxf(red1[6], red1[7])));
    float s = 0.f;
#pragma unroll
    for (int p = 0; p < 2; p++) {
        float e0 = (v[p].x > -3.0e38f) ? __expf(v[p].x - mx) : 0.f;
        float e1 = (v[p].y > -3.0e38f) ? __expf(v[p].y - mx) : 0.f;
        float e2 = (v[p].z > -3.0e38f) ? __expf(v[p].z - mx) : 0.f;
        float e3 = (v[p].w > -3.0e38f) ? __expf(v[p].w - mx) : 0.f;
        v[p].x = e0; v[p].y = e1; v[p].z = e2; v[p].w = e3;
        s += e0 + e1 + e2 + e3;
    }
    s = warpSum(s);
    if ((t & 31) == 0) red2[t >> 5] = s;
    __syncthreads();
    float tot = red2[0] + red2[1] + red2[2] + red2[3] + red2[4] + red2[5] + red2[6] + red2[7];
    float inv = 1.0f / tot;
#pragma unroll
    for (int p = 0; p < 2; p++) {
        int j = (p * 256 + t) * 4;
        if (j < nup) {
            uint2 pu;
            pu.x = h2pack(v[p].x * inv, v[p].y * inv);
            pu.y = h2pack(v[p].z * inv, v[p].w * inv);
            *(uint2*)&p16[roff + j] = pu;
        }
    }
}

// ======================= probs layout: fp16 [h][i][j] -> f32 [i][j][h] ========
__global__ void probs_out_kernel(const __half* __restrict__ p16,
                                 float* __restrict__ out) {
    const int i = blockIdx.y;
    const int t = threadIdx.x;
    const int nup = (i & ~63) + 64;
    __shared__ float sm[16][66];
#pragma unroll 1
    for (int s = 0; s < 4; s++) {
        const int j0 = (blockIdx.x * 4 + s) * 64;
        float* dst = out + ((size_t)i * T + j0) * H;
        if (j0 < nup) {
#pragma unroll
            for (int e = 0; e < 2; e++) {
                int idx = e * 256 + t;
                int hh = idx >> 5, jp = idx & 31;
                size_t o = ((size_t)hh * T + i) * T + j0 + jp * 2;
                __half2 a = *(const __half2*)&p16[o];
                sm[hh][jp * 2]     = __half2float(a.x);
                sm[hh][jp * 2 + 1] = __half2float(a.y);
            }
            __syncthreads();
            int base = t * 4;
            float4 o4;
            o4.x = sm[(base + 0) & 15][(base + 0) >> 4];
            o4.y = sm[(base + 1) & 15][(base + 1) >> 4];
            o4.z = sm[(base + 2) & 15][(base + 2) >> 4];
            o4.w = sm[(base + 3) & 15][(base + 3) >> 4];
            *(float4*)&dst[base] = o4;
            __syncthreads();
        } else {
            float4 z; z.x = z.y = z.z = z.w = 0.f;
            *(float4*)&dst[t * 4] = z;
        }
    }
}

// ======================= fp16 PV =======================
#define PVH_PARR 18432
#define PVH_VARR 9216
#define PVH_STAGE (PVH_PARR + PVH_VARR)
#define PVH_SMEM (2 * PVH_STAGE)

__device__ __forceinline__ void pvh_load_chunk(
    const __half* __restrict__ P, const __half* __restrict__ V,
    int h, int i0, int t, uint32_t stage_base, int tid) {
    const size_t j0 = (size_t)t * 64;
#pragma unroll
    for (int e = 0; e < 6; e++) {
        int idx = e * 256 + tid;
        const __half* src;
        uint32_t dst;
        if (idx < 1024) {
            int row = (idx >> 3) & 127;
            int ck  = idx & 7;
            src = P + ((size_t)h * T + i0 + row) * T + j0 + ck * 8;
            dst = stage_base + (uint32_t)(row * 144 + ck * 16);
        } else {
            int k = idx - 1024;
            int row = (k >> 3) & 63;
            int ck  = k & 7;
            src = V + (size_t)(h * DH + row) * T + j0 + ck * 8;
            dst = stage_base + PVH_PARR + (uint32_t)(row * 144 + ck * 16);
        }
        cpa16(dst, src);
    }
    asm volatile("cp.async.commit_group;" ::: "memory");
}

__global__ void __launch_bounds__(256, 2) pv16_kernel(
    const __half* __restrict__ P, const __half* __restrict__ V,
    __half* __restrict__ av16) {
    extern __shared__ char smem[];
    const uint32_t sbase = smem_u32(smem);
    const int h = blockIdx.y;
    const int i0 = (gridDim.x - 1 - blockIdx.x) * 128;
    const int tid = threadIdx.x;
    const int wid = tid >> 5, lane = tid & 31;
    const int mrow = (wid & 3) * 32;
    const int nrow = (wid >> 2) * 32;

    float c[2][4][4] = {};
    const int nch = i0 / 64 + 2;

    pvh_load_chunk(P, V, h, i0, 0, sbase, tid);

    for (int t = 0; t < nch; t++) {
        asm volatile("cp.async.wait_group 0;" ::: "memory");
        __syncthreads();
        if (t + 1 < nch)
            pvh_load_chunk(P, V, h, i0, t + 1, sbase + ((t + 1) & 1) * PVH_STAGE, tid);
        const uint32_t sb = sbase + (t & 1) * PVH_STAGE;
        const uint32_t vb = sb + PVH_PARR;
#pragma unroll
        for (int kk = 0; kk < 4; kk++) {
            uint32_t a[2][4], b[2][4];
            ldsm_x4(a[0], faddr(sb, mrow,      kk, lane));
            ldsm_x4(a[1], faddr(sb, mrow + 16, kk, lane));
            ldsm_x4(b[0], faddr(vb, nrow,      kk, lane));
            ldsm_x4(b[1], faddr(vb, nrow + 16, kk, lane));
#pragma unroll
            for (int mi = 0; mi < 2; mi++)
#pragma unroll
                for (int nb = 0; nb < 4; nb++) {
                    const int nf = nb >> 1, o = nb & 1;
                    mma16816h(c[mi][nb], a[mi], b[nf][o], b[nf][2 + o]);
                }
        }
    }

    const int tq = lane >> 2, tr = lane & 3;
#pragma unroll
    for (int mi = 0; mi < 2; mi++)
#pragma unroll
        for (int nb = 0; nb < 4; nb++)
#pragma unroll
            for (int hh = 0; hh < 2; hh++) {
                int gi = i0 + mrow + mi * 16 + tq + hh * 8;
                int gd = nrow + nb * 8 + tr * 2;
                size_t o = (size_t)gi * D + h * DH + gd;
                *(uint32_t*)&av16[o] = h2pack(c[mi][nb][hh * 2 + 0], c[mi][nb][hh * 2 + 1]);
            }
}

// ======================= host launch =======================
extern "C" void kernel_launch(void* const* d_in, const int* in_sizes, int n_in,
                              void* d_out, int out_size) {
    const float* input = (const float*)d_in[0];
    const float* pos   = (const float*)d_in[1];
    const float* rwb   = (const float*)d_in[2];
    const float* rrb   = (const float*)d_in[3];
    const float* ln1g  = (const float*)d_in[5];
    const float* ln1b  = (const float*)d_in[6];
    const float* qkvw  = (const float*)d_in[7];
    const float* rw    = (const float*)d_in[8];
    const float* ow    = (const float*)d_in[9];
    const float* ln2g  = (const float*)d_in[10];
    const float* ln2b  = (const float*)d_in[11];
    const float* ffw1  = (const float*)d_in[12];
    const float* ffb1  = (const float*)d_in[13];
    const float* ffw2  = (const float*)d_in[14];
    const float* ffb2  = (const float*)d_in[15];
    float* out = (float*)d_out;

    float *scores, *x;
    cudaGetSymbolAddress((void**)&scores, g_scores);
    cudaGetSymbolAddress((void**)&x,      g_x);
    __half *qin16, *qkvwT16, *qw16, *qr16, *k16, *v16, *rk16, *pos16, *rwT16;
    cudaGetSymbolAddress((void**)&qin16,   g_qin16);
    cudaGetSymbolAddress((void**)&qkvwT16, g_qkvwT16);
    cudaGetSymbolAddress((void**)&qw16, g_qw16);
    cudaGetSymbolAddress((void**)&qr16, g_qr16);
    cudaGetSymbolAddress((void**)&k16,  g_k16);
    cudaGetSymbolAddress((void**)&v16,  g_v16);
    cudaGetSymbolAddress((void**)&rk16, g_rk16);
    cudaGetSymbolAddress((void**)&pos16, g_pos16);
    cudaGetSymbolAddress((void**)&rwT16, g_rwT16);
    __half *p16, *vt16, *av16, *owT16, *y16, *ff16, *w1T16, *w2T16;
    cudaGetSymbolAddress((void**)&p16,   g_p16);
    cudaGetSymbolAddress((void**)&vt16,  g_vt16);
    cudaGetSymbolAddress((void**)&av16,  g_av16);
    cudaGetSymbolAddress((void**)&owT16, g_owT16);
    cudaGetSymbolAddress((void**)&y16,   g_y16);
    cudaGetSymbolAddress((void**)&ff16,  g_ff16);
    cudaGetSymbolAddress((void**)&w1T16, g_w1T16);
    cudaGetSymbolAddress((void**)&w2T16, g_w2T16);

    cudaFuncSetAttribute((const void*)mmqkv16_kernel, cudaFuncAttributeMaxDynamicSharedMemorySize, MMH_SMEM);
    cudaFuncSetAttribute((const void*)mmh_kernel<4>,  cudaFuncAttributeMaxDynamicSharedMemorySize, MMH_SMEM);
    cudaFuncSetAttribute((const void*)mmh_kernel<8>,  cudaFuncAttributeMaxDynamicSharedMemorySize, MMH_SMEM);
    cudaFuncSetAttribute((const void*)mmh_kernel<11>, cudaFuncAttributeMaxDynamicSharedMemorySize, MMH_SMEM);
    cudaFuncSetAttribute((const void*)mmh_kernel<5>,  cudaFuncAttributeMaxDynamicSharedMemorySize, MMH_SMEM);
    cudaFuncSetAttribute((const void*)scores16_kernel, cudaFuncAttributeMaxDynamicSharedMemorySize, SCH_SMEM);
    cudaFuncSetAttribute((const void*)pv16_kernel,  cudaFuncAttributeMaxDynamicSharedMemorySize, PVH_SMEM);

    const dim3 wthr(32, 8);
    const bool probs_fit =
        (long long)out_size >= (long long)T * D + (long long)H * T * T;

    ln16_kernel<<<T, 256>>>(input, ln1g, ln1b, qin16);                               // 0
    wconvT16_kernel<<<dim3(D3 / 32, D / 32), wthr>>>(qkvw, qkvwT16, D, D3);          // 1
    splitcvt16_kernel<<<(T * D) / 1024, 256>>>(pos, pos16, T * D);                   // 2
    mmqkv16_kernel<<<dim3(D3 / 128, T / 128), 256, MMH_SMEM>>>(                       // 3 (profiled)
        qin16, qkvwT16, rwb, rrb, qw16, qr16, k16, v16, T, D3, D);
    wconvT16_kernel<<<dim3(D / 32,  D / 32), wthr>>>(rw, rwT16, D, D);               // 4
    vconvT16h_kernel<<<dim3(T / 32, D / 32), wthr>>>(v16, vt16);                     // 5
    mmh_kernel<8><<<dim3(D / 128, T / 128), 256, MMH_SMEM>>>(                         // 6: rk
        pos16, rwT16, nullptr, nullptr, nullptr, rk16, T, D, D);
    wconvT16_kernel<<<dim3(D / 32,  D / 32), wthr>>>(ow, owT16, D, D);               // 7
    scores16_kernel<<<dim3(136, 1, H), 256, SCH_SMEM>>>(qw16, qr16, k16, rk16, scores);
    softmax_kernel<<<dim3(T, H), 256>>>(scores, p16);
    if (probs_fit) {
        probs_out_kernel<<<dim3(T / 256, T), 256>>>(p16, out + (size_t)T * D);
    }
    pv16_kernel<<<dim3(T / 128, H), 256, PVH_SMEM>>>(p16, vt16, av16);
    mmh_kernel<4><<<dim3(D / 128, T / 128), 256, MMH_SMEM>>>(
        av16, owT16, nullptr, input, x, nullptr, T, D, D);
    ln16_kernel<<<T, 256>>>(x, ln2g, ln2b, y16);
    wconvT16_kernel<<<dim3(DFF / 32, D / 32), wthr>>>(ffw1, w1T16, D, DFF);
    wconvT16_kernel<<<dim3(D / 32, DFF / 32), wthr>>>(ffw2, w2T16, DFF, D);
    mmh_kernel<11><<<dim3(DFF / 128, T / 128), 256, MMH_SMEM>>>(
        y16, w1T16, ffb1, nullptr, nullptr, ff16, T, DFF, D);
    mmh_kernel<5><<<dim3(D / 128, T / 128), 256, MMH_SMEM>>>(
        ff16, w2T16, ffb2, x, out, nullptr, T, D, DFF);
}